// round 1
// baseline (speedup 1.0000x reference)
#include <cuda_runtime.h>
#include <math.h>

#define CT   4096
#define CHID 2560
#define CH   8
#define CKH  4
#define CD   256
#define CQD  2048   // H*D
#define CKD  1024   // KH*D
#define CWIN 1024

// Scratch (static device globals — allocation-free rule)
__device__ float g_Q[CT * CQD];      // 32 MB
__device__ float g_K[CT * CKD];      // 16 MB
__device__ float g_V[CT * CKD];      // 16 MB
__device__ float g_AO[CT * CQD];     // 32 MB
__device__ float g_invf[128];

__global__ void init_invf_kernel() {
    int d = threadIdx.x;
    if (d < 128) g_invf[d] = (float)pow(10000.0, -((double)d) / 128.0);
}

// ---------------------------------------------------------------------------
// SGEMM: C[M,N] = A[M,K] @ B[K,N], row-major, all dims multiples of 128/16.
// 128x128 block tile, BK=16, 256 threads, 8x8 per thread (split-64 fragments
// for conflict-free LDS.128).
// ---------------------------------------------------------------------------
__global__ __launch_bounds__(256) void sgemm_kernel(
    const float* __restrict__ A, const float* __restrict__ B,
    float* __restrict__ C, int M, int N, int K)
{
    __shared__ float As[16][132];  // transposed A tile, padded
    __shared__ float Bs[16][132];

    const int tid = threadIdx.x;
    const int tx = tid & 15;
    const int ty = tid >> 4;
    const int bx = blockIdx.x;
    const int by = blockIdx.y;

    float acc[8][8];
    #pragma unroll
    for (int i = 0; i < 8; i++)
        #pragma unroll
        for (int j = 0; j < 8; j++) acc[i][j] = 0.0f;

    const float* Ablk = A + (size_t)by * 128 * K;
    const float* Bblk = B + bx * 128;

    for (int k0 = 0; k0 < K; k0 += 16) {
        #pragma unroll
        for (int r = 0; r < 2; r++) {
            int id   = tid + r * 256;
            int arow = id >> 2;
            int acol = (id & 3) << 2;
            float4 v = *(const float4*)&Ablk[(size_t)arow * K + k0 + acol];
            As[acol + 0][arow] = v.x;
            As[acol + 1][arow] = v.y;
            As[acol + 2][arow] = v.z;
            As[acol + 3][arow] = v.w;
        }
        #pragma unroll
        for (int r = 0; r < 2; r++) {
            int id   = tid + r * 256;
            int brow = id >> 5;
            int bcol = (id & 31) << 2;
            *(float4*)&Bs[brow][bcol] =
                *(const float4*)&Bblk[(size_t)(k0 + brow) * N + bcol];
        }
        __syncthreads();

        #pragma unroll
        for (int k = 0; k < 16; k++) {
            float a[8], b[8];
            *(float4*)&a[0] = *(float4*)&As[k][ty * 4];
            *(float4*)&a[4] = *(float4*)&As[k][64 + ty * 4];
            *(float4*)&b[0] = *(float4*)&Bs[k][tx * 4];
            *(float4*)&b[4] = *(float4*)&Bs[k][64 + tx * 4];
            #pragma unroll
            for (int i = 0; i < 8; i++)
                #pragma unroll
                for (int j = 0; j < 8; j++)
                    acc[i][j] = fmaf(a[i], b[j], acc[i][j]);
        }
        __syncthreads();
    }

    #pragma unroll
    for (int i = 0; i < 8; i++) {
        int r = by * 128 + ((i < 4) ? (ty * 4 + i) : (64 + ty * 4 + i - 4));
        float* crow = C + (size_t)r * N + bx * 128;
        *(float4*)&crow[tx * 4] =
            make_float4(acc[i][0], acc[i][1], acc[i][2], acc[i][3]);
        *(float4*)&crow[64 + tx * 4] =
            make_float4(acc[i][4], acc[i][5], acc[i][6], acc[i][7]);
    }
}

// ---------------------------------------------------------------------------
// Fused RMSNorm (Gemma: scale by 1+w) + neox RoPE for Q and K.
// grid = (T, 12): y<8 -> Q head y ; y>=8 -> K head y-8. 128 threads: thread d
// handles dims d and d+128 (the rotate_half pair).
// ---------------------------------------------------------------------------
__global__ __launch_bounds__(128) void norm_rope_kernel(
    float* __restrict__ Qm, float* __restrict__ Km, const int* __restrict__ pos,
    const float* __restrict__ qw, const float* __restrict__ kw)
{
    int t  = blockIdx.x;
    int hh = blockIdx.y;
    float* base;
    const float* w;
    if (hh < CH) { base = Qm + (size_t)t * CQD + hh * CD;        w = qw; }
    else         { base = Km + (size_t)t * CKD + (hh - CH) * CD; w = kw; }

    int d = threadIdx.x;
    float x1 = base[d];
    float x2 = base[d + 128];
    float ss = x1 * x1 + x2 * x2;
    #pragma unroll
    for (int off = 16; off > 0; off >>= 1)
        ss += __shfl_xor_sync(0xffffffffu, ss, off);
    __shared__ float wsum[4];
    if ((d & 31) == 0) wsum[d >> 5] = ss;
    __syncthreads();
    float tot = wsum[0] + wsum[1] + wsum[2] + wsum[3];
    float inv = rsqrtf(tot * (1.0f / 256.0f) + 1e-6f);
    float n1 = x1 * inv * (1.0f + w[d]);
    float n2 = x2 * inv * (1.0f + w[d + 128]);

    float f = (float)pos[t] * g_invf[d];
    float c, s;
    sincosf(f, &s, &c);
    base[d]       = n1 * c - n2 * s;
    base[d + 128] = n2 * c + n1 * s;
}

// ---------------------------------------------------------------------------
// Flash attention with sliding window. One CTA per (q-block of 64, head).
// Tiles of 64 queries x 64 keys x D=256, fp32, online softmax.
// Smem tiles stored with XOR swizzle: phys col group = (4m) ^ 4*((row>>2)&7)
// -> conflict-free LDS.128 fragment reads in both QK^T and PV loops.
// K tile buffer is reused for V after S is computed.
// ---------------------------------------------------------------------------
#define FLASH_SMEM ((2 * 64 * 256 + 64 * 65 + 3 * 64) * 4)

__global__ __launch_bounds__(256, 1) void flash_kernel(
    const float* __restrict__ Q, const float* __restrict__ K,
    const float* __restrict__ V, float* __restrict__ O)
{
    extern __shared__ float sm[];
    float* Qs  = sm;                  // 64*256 (swizzled)
    float* KVs = sm + 64 * 256;       // 64*256 (swizzled), K then V
    float* Ps  = sm + 2 * 64 * 256;   // 64*65 scores/probs
    float* m_s = Ps + 64 * 65;        // running max per row
    float* l_s = m_s + 64;            // running denom per row
    float* a_s = l_s + 64;            // per-row rescale factor

    const int tid = threadIdx.x;
    const int tx  = tid & 15;
    const int ty  = tid >> 4;
    const int q0  = blockIdx.x * 64;
    const int h   = blockIdx.y;
    const int kvh = h >> 1;           // GQA: 2 q heads per kv head

    const int qkey = (ty & 7) * 4;    // swizzle key for this thread's Q rows
    const int kkey = (tx & 7) * 4;    // swizzle key for this thread's K rows

    // Load Q tile once
    #pragma unroll
    for (int it = 0; it < 16; it++) {
        int id  = tid + it * 256;
        int row = id >> 6;
        int m   = id & 63;
        float4 v = *(const float4*)&Q[(size_t)(q0 + row) * CQD + h * CD + m * 4];
        int key = ((row >> 2) & 7) * 4;
        *(float4*)&Qs[row * 256 + ((4 * m) ^ key)] = v;
    }
    if (tid < 64) { m_s[tid] = -1e30f; l_s[tid] = 0.0f; }

    float o[4][16];
    #pragma unroll
    for (int i = 0; i < 4; i++)
        #pragma unroll
        for (int c = 0; c < 16; c++) o[i][c] = 0.0f;

    int kb_lo = q0 - CWIN;
    if (kb_lo < 0) kb_lo = 0;

    for (int k0 = kb_lo; k0 <= q0; k0 += 64) {
        __syncthreads();  // prior PV reads of KVs/Ps complete
        // Load K tile
        #pragma unroll
        for (int it = 0; it < 16; it++) {
            int id  = tid + it * 256;
            int row = id >> 6;
            int m   = id & 63;
            float4 v = *(const float4*)&K[(size_t)(k0 + row) * CKD + kvh * CD + m * 4];
            int key = ((row >> 2) & 7) * 4;
            *(float4*)&KVs[row * 256 + ((4 * m) ^ key)] = v;
        }
        __syncthreads();

        // S = Q K^T  (each thread: 4x4 of the 64x64 score tile)
        float s[4][4];
        #pragma unroll
        for (int i = 0; i < 4; i++)
            #pragma unroll
            for (int j = 0; j < 4; j++) s[i][j] = 0.0f;

        #pragma unroll 8
        for (int m = 0; m < 64; m++) {
            float4 q4[4], k4[4];
            #pragma unroll
            for (int i = 0; i < 4; i++)
                q4[i] = *(const float4*)&Qs[(ty * 4 + i) * 256 + ((4 * m) ^ qkey)];
            #pragma unroll
            for (int j = 0; j < 4; j++)
                k4[j] = *(const float4*)&KVs[(tx * 4 + j) * 256 + ((4 * m) ^ kkey)];
            #pragma unroll
            for (int i = 0; i < 4; i++)
                #pragma unroll
                for (int j = 0; j < 4; j++) {
                    s[i][j] = fmaf(q4[i].x, k4[j].x, s[i][j]);
                    s[i][j] = fmaf(q4[i].y, k4[j].y, s[i][j]);
                    s[i][j] = fmaf(q4[i].z, k4[j].z, s[i][j]);
                    s[i][j] = fmaf(q4[i].w, k4[j].w, s[i][j]);
                }
        }
        #pragma unroll
        for (int i = 0; i < 4; i++)
            #pragma unroll
            for (int j = 0; j < 4; j++)
                Ps[(ty * 4 + i) * 65 + tx * 4 + j] = s[i][j] * 0.0625f;  // *SCALE
        __syncthreads();

        // Load V tile over the K buffer (not needed anymore)
        #pragma unroll
        for (int it = 0; it < 16; it++) {
            int id  = tid + it * 256;
            int row = id >> 6;
            int m   = id & 63;
            float4 v = *(const float4*)&V[(size_t)(k0 + row) * CKD + kvh * CD + m * 4];
            int key = ((row >> 2) & 7) * 4;
            *(float4*)&KVs[row * 256 + ((4 * m) ^ key)] = v;
        }
        // Online softmax: one thread per query row (mask applied here)
        if (tid < 64) {
            int r  = tid;
            int qg = q0 + r;
            float mb = m_s[r];
            float mx = mb;
            for (int c = 0; c < 64; c++) {
                int kg = k0 + c;
                if (kg <= qg && qg - kg < CWIN)
                    mx = fmaxf(mx, Ps[r * 65 + c]);
            }
            float alpha = expf(mb - mx);
            float sum = 0.0f;
            for (int c = 0; c < 64; c++) {
                int kg = k0 + c;
                float p = 0.0f;
                if (kg <= qg && qg - kg < CWIN)
                    p = expf(Ps[r * 65 + c] - mx);
                Ps[r * 65 + c] = p;
                sum += p;
            }
            m_s[r] = mx;
            l_s[r] = l_s[r] * alpha + sum;
            a_s[r] = alpha;
        }
        __syncthreads();

        // Rescale accumulator, then O += P @ V
        #pragma unroll
        for (int i = 0; i < 4; i++) {
            float al = a_s[ty * 4 + i];
            #pragma unroll
            for (int c = 0; c < 16; c++) o[i][c] *= al;
        }
        #pragma unroll 4
        for (int kv = 0; kv < 64; kv++) {
            float p[4];
            #pragma unroll
            for (int i = 0; i < 4; i++) p[i] = Ps[(ty * 4 + i) * 65 + kv];
            int key = ((kv >> 2) & 7) * 4;
            float4 v4[4];
            #pragma unroll
            for (int m4 = 0; m4 < 4; m4++)
                v4[m4] = *(const float4*)&KVs[kv * 256 + ((tx * 16 + 4 * m4) ^ key)];
            #pragma unroll
            for (int i = 0; i < 4; i++) {
                #pragma unroll
                for (int m4 = 0; m4 < 4; m4++) {
                    o[i][m4 * 4 + 0] = fmaf(p[i], v4[m4].x, o[i][m4 * 4 + 0]);
                    o[i][m4 * 4 + 1] = fmaf(p[i], v4[m4].y, o[i][m4 * 4 + 1]);
                    o[i][m4 * 4 + 2] = fmaf(p[i], v4[m4].z, o[i][m4 * 4 + 2]);
                    o[i][m4 * 4 + 3] = fmaf(p[i], v4[m4].w, o[i][m4 * 4 + 3]);
                }
            }
        }
    }

    // Epilogue: divide by softmax denom, write out
    #pragma unroll
    for (int i = 0; i < 4; i++) {
        int r = ty * 4 + i;
        float inv = 1.0f / l_s[r];
        float* orow = O + (size_t)(q0 + r) * CQD + h * CD;
        #pragma unroll
        for (int m4 = 0; m4 < 4; m4++) {
            *(float4*)&orow[tx * 16 + 4 * m4] =
                make_float4(o[i][4 * m4 + 0] * inv, o[i][4 * m4 + 1] * inv,
                            o[i][4 * m4 + 2] * inv, o[i][4 * m4 + 3] * inv);
        }
    }
}

// ---------------------------------------------------------------------------
extern "C" void kernel_launch(void* const* d_in, const int* in_sizes, int n_in,
                              void* d_out, int out_size) {
    const float* x  = (const float*)d_in[0];
    const int*   ps = (const int*)  d_in[1];
    const float* Wq = (const float*)d_in[2];
    const float* Wk = (const float*)d_in[3];
    const float* Wv = (const float*)d_in[4];
    const float* Wo = (const float*)d_in[5];
    const float* qw = (const float*)d_in[6];
    const float* kw = (const float*)d_in[7];
    float* out = (float*)d_out;
    (void)in_sizes; (void)n_in; (void)out_size;

    float *Qp, *Kp, *Vp, *AOp;
    cudaGetSymbolAddress((void**)&Qp,  g_Q);
    cudaGetSymbolAddress((void**)&Kp,  g_K);
    cudaGetSymbolAddress((void**)&Vp,  g_V);
    cudaGetSymbolAddress((void**)&AOp, g_AO);

    cudaFuncSetAttribute(flash_kernel,
                         cudaFuncAttributeMaxDynamicSharedMemorySize, FLASH_SMEM);

    init_invf_kernel<<<1, 128>>>();

    // Projections
    sgemm_kernel<<<dim3(CQD / 128, CT / 128), 256>>>(x, Wq, Qp, CT, CQD, CHID);
    sgemm_kernel<<<dim3(CKD / 128, CT / 128), 256>>>(x, Wk, Kp, CT, CKD, CHID);
    sgemm_kernel<<<dim3(CKD / 128, CT / 128), 256>>>(x, Wv, Vp, CT, CKD, CHID);

    // RMSNorm + RoPE on Q and K
    norm_rope_kernel<<<dim3(CT, CH + CKH), 128>>>(Qp, Kp, ps, qw, kw);

    // Sliding-window GQA flash attention
    flash_kernel<<<dim3(CT / 64, CH), 256, FLASH_SMEM>>>(Qp, Kp, Vp, AOp);

    // Output projection
    sgemm_kernel<<<dim3(CHID / 128, CT / 128), 256>>>(AOp, Wo, out, CT, CHID, CQD);
}

// round 2
// speedup vs baseline: 1.2195x; 1.2195x over previous
#include <cuda_runtime.h>
#include <math.h>

#define CT   4096
#define CHID 2560
#define CH   8
#define CKH  4
#define CD   256
#define CQD  2048   // H*D
#define CKD  1024   // KH*D
#define CWIN 1024
#define LOG2E 1.4426950408889634f

// Scratch (static device globals — allocation-free rule)
__device__ float g_Q[CT * CQD];      // 32 MB
__device__ float g_K[CT * CKD];      // 16 MB
__device__ float g_V[CT * CKD];      // 16 MB
__device__ float g_AO[CT * CQD];     // 32 MB
__device__ float g_invf[128];

__global__ void init_invf_kernel() {
    int d = threadIdx.x;
    if (d < 128) g_invf[d] = (float)pow(10000.0, -((double)d) / 128.0);
}

// ---------------------------------------------------------------------------
// SGEMM: C[M,N] = A[M,K] @ B[K,N], row-major. 128x128 tile, BK=16,
// 256 threads, 8x8 per thread. (unchanged from R1)
// ---------------------------------------------------------------------------
__global__ __launch_bounds__(256) void sgemm_kernel(
    const float* __restrict__ A, const float* __restrict__ B,
    float* __restrict__ C, int M, int N, int K)
{
    __shared__ float As[16][132];
    __shared__ float Bs[16][132];

    const int tid = threadIdx.x;
    const int tx = tid & 15;
    const int ty = tid >> 4;
    const int bx = blockIdx.x;
    const int by = blockIdx.y;

    float acc[8][8];
    #pragma unroll
    for (int i = 0; i < 8; i++)
        #pragma unroll
        for (int j = 0; j < 8; j++) acc[i][j] = 0.0f;

    const float* Ablk = A + (size_t)by * 128 * K;
    const float* Bblk = B + bx * 128;

    for (int k0 = 0; k0 < K; k0 += 16) {
        #pragma unroll
        for (int r = 0; r < 2; r++) {
            int id   = tid + r * 256;
            int arow = id >> 2;
            int acol = (id & 3) << 2;
            float4 v = *(const float4*)&Ablk[(size_t)arow * K + k0 + acol];
            As[acol + 0][arow] = v.x;
            As[acol + 1][arow] = v.y;
            As[acol + 2][arow] = v.z;
            As[acol + 3][arow] = v.w;
        }
        #pragma unroll
        for (int r = 0; r < 2; r++) {
            int id   = tid + r * 256;
            int brow = id >> 5;
            int bcol = (id & 31) << 2;
            *(float4*)&Bs[brow][bcol] =
                *(const float4*)&Bblk[(size_t)(k0 + brow) * N + bcol];
        }
        __syncthreads();

        #pragma unroll
        for (int k = 0; k < 16; k++) {
            float a[8], b[8];
            *(float4*)&a[0] = *(float4*)&As[k][ty * 4];
            *(float4*)&a[4] = *(float4*)&As[k][64 + ty * 4];
            *(float4*)&b[0] = *(float4*)&Bs[k][tx * 4];
            *(float4*)&b[4] = *(float4*)&Bs[k][64 + tx * 4];
            #pragma unroll
            for (int i = 0; i < 8; i++)
                #pragma unroll
                for (int j = 0; j < 8; j++)
                    acc[i][j] = fmaf(a[i], b[j], acc[i][j]);
        }
        __syncthreads();
    }

    #pragma unroll
    for (int i = 0; i < 8; i++) {
        int r = by * 128 + ((i < 4) ? (ty * 4 + i) : (64 + ty * 4 + i - 4));
        float* crow = C + (size_t)r * N + bx * 128;
        *(float4*)&crow[tx * 4] =
            make_float4(acc[i][0], acc[i][1], acc[i][2], acc[i][3]);
        *(float4*)&crow[64 + tx * 4] =
            make_float4(acc[i][4], acc[i][5], acc[i][6], acc[i][7]);
    }
}

// ---------------------------------------------------------------------------
// Fused RMSNorm + neox RoPE for Q and K. (unchanged from R1)
// ---------------------------------------------------------------------------
__global__ __launch_bounds__(128) void norm_rope_kernel(
    float* __restrict__ Qm, float* __restrict__ Km, const int* __restrict__ pos,
    const float* __restrict__ qw, const float* __restrict__ kw)
{
    int t  = blockIdx.x;
    int hh = blockIdx.y;
    float* base;
    const float* w;
    if (hh < CH) { base = Qm + (size_t)t * CQD + hh * CD;        w = qw; }
    else         { base = Km + (size_t)t * CKD + (hh - CH) * CD; w = kw; }

    int d = threadIdx.x;
    float x1 = base[d];
    float x2 = base[d + 128];
    float ss = x1 * x1 + x2 * x2;
    #pragma unroll
    for (int off = 16; off > 0; off >>= 1)
        ss += __shfl_xor_sync(0xffffffffu, ss, off);
    __shared__ float wsum[4];
    if ((d & 31) == 0) wsum[d >> 5] = ss;
    __syncthreads();
    float tot = wsum[0] + wsum[1] + wsum[2] + wsum[3];
    float inv = rsqrtf(tot * (1.0f / 256.0f) + 1e-6f);
    float n1 = x1 * inv * (1.0f + w[d]);
    float n2 = x2 * inv * (1.0f + w[d + 128]);

    float f = (float)pos[t] * g_invf[d];
    float c, s;
    sincosf(f, &s, &c);
    base[d]       = n1 * c - n2 * s;
    base[d + 128] = n2 * c + n1 * s;
}

// ---------------------------------------------------------------------------
// Flash attention v2 (R2): conflict-free swizzles + in-register online softmax.
//
// 64q x 64k tiles, D=256, 256 threads. tx=tid&15, ty=tid>>4.
// Thread owns rows ri = ty*4+i.
//   QK cols:   cj = tx*4+j           (4x4 score fragment)
//   PV/O cols: 4*tx + 64*m, m=0..3   (4x16 output fragment)
// Swizzle: element (row, 4m..4m+3) stored at row*256 + ((4m) ^ (4*(row>>2))).
//   -> K-fragment loads: 8 lanes/wavefront hit 8 distinct bank groups (CF).
//   -> V loads (cols 4tx+64m): consecutive 16B per wavefront (CF).
//   -> Q/P loads: broadcast within wavefront (free).
// Softmax: row max/sum via shfl_xor over the 16-lane row group; m/l/alpha in
// registers (each of the 16 lanes holds a replica). exp2f fast path.
// ---------------------------------------------------------------------------
#define FLASH_SMEM ((3 * 64 * 256 + 64 * 68) * 4)   // 214016 B

__global__ __launch_bounds__(256, 1) void flash_kernel(
    const float* __restrict__ Q, const float* __restrict__ K,
    const float* __restrict__ V, float* __restrict__ O)
{
    extern __shared__ float sm[];
    float* Qs = sm;                   // 64*256 swizzled, pre-scaled by SCALE
    float* Ks = sm + 64 * 256;        // 64*256 swizzled
    float* Vs = sm + 2 * 64 * 256;    // 64*256 swizzled
    float* Ps = sm + 3 * 64 * 256;    // 64 x 68 probs

    const int tid = threadIdx.x;
    const int tx  = tid & 15;
    const int ty  = tid >> 4;
    const int q0  = blockIdx.x * 64;
    const int h   = blockIdx.y;
    const int kvh = h >> 1;

    // ---- load Q tile (scaled) ----
    #pragma unroll
    for (int it = 0; it < 16; it++) {
        int id  = tid + it * 256;
        int row = id >> 6;
        int m   = id & 63;
        float4 v = *(const float4*)&Q[(size_t)(q0 + row) * CQD + h * CD + m * 4];
        int key = (row >> 2) * 4;
        v.x *= 0.0625f; v.y *= 0.0625f; v.z *= 0.0625f; v.w *= 0.0625f;
        *(float4*)&Qs[row * 256 + ((4 * m) ^ key)] = v;
    }

    float o[4][16];
    #pragma unroll
    for (int i = 0; i < 4; i++)
        #pragma unroll
        for (int c = 0; c < 16; c++) o[i][c] = 0.0f;
    float mrun[4] = {-1e30f, -1e30f, -1e30f, -1e30f};
    float lrun[4] = {0.0f, 0.0f, 0.0f, 0.0f};

    const int qkey = 4 * ty;   // swizzle key for this thread's Q rows (bcast)

    int kb_lo = q0 - CWIN;
    if (kb_lo < 0) kb_lo = 0;

    for (int k0 = kb_lo; k0 <= q0; k0 += 64) {
        __syncthreads();   // previous PV reads of Vs/Ps done
        // ---- load K and V tiles ----
        #pragma unroll
        for (int it = 0; it < 16; it++) {
            int id  = tid + it * 256;
            int row = id >> 6;
            int m   = id & 63;
            int key = (row >> 2) * 4;
            int off = row * 256 + ((4 * m) ^ key);
            *(float4*)&Ks[off] =
                *(const float4*)&K[(size_t)(k0 + row) * CKD + kvh * CD + m * 4];
            *(float4*)&Vs[off] =
                *(const float4*)&V[(size_t)(k0 + row) * CKD + kvh * CD + m * 4];
        }
        __syncthreads();

        // ---- S = Q K^T (4x4 fragment per thread) ----
        float s[4][4];
        #pragma unroll
        for (int i = 0; i < 4; i++)
            #pragma unroll
            for (int j = 0; j < 4; j++) s[i][j] = 0.0f;

        const int kkey = 4 * tx;
        #pragma unroll 4
        for (int m = 0; m < 64; m++) {
            float4 q4[4], k4[4];
            #pragma unroll
            for (int i = 0; i < 4; i++)
                q4[i] = *(const float4*)&Qs[(ty * 4 + i) * 256 + ((4 * m) ^ qkey)];
            #pragma unroll
            for (int j = 0; j < 4; j++)
                k4[j] = *(const float4*)&Ks[(tx * 4 + j) * 256 + ((4 * m) ^ kkey)];
            #pragma unroll
            for (int i = 0; i < 4; i++)
                #pragma unroll
                for (int j = 0; j < 4; j++) {
                    s[i][j] = fmaf(q4[i].x, k4[j].x, s[i][j]);
                    s[i][j] = fmaf(q4[i].y, k4[j].y, s[i][j]);
                    s[i][j] = fmaf(q4[i].z, k4[j].z, s[i][j]);
                    s[i][j] = fmaf(q4[i].w, k4[j].w, s[i][j]);
                }
        }

        // ---- in-register online softmax ----
        float alpha[4];
        const int dbase = (q0 - k0) + ty * 4 - tx * 4;   // + i - j later
        #pragma unroll
        for (int i = 0; i < 4; i++) {
            float mx = -1e30f;
            #pragma unroll
            for (int j = 0; j < 4; j++) {
                unsigned d = (unsigned)(dbase + i - j);
                if (d < (unsigned)CWIN) mx = fmaxf(mx, s[i][j]);
            }
            mx = fmaxf(mx, __shfl_xor_sync(0xffffffffu, mx, 1));
            mx = fmaxf(mx, __shfl_xor_sync(0xffffffffu, mx, 2));
            mx = fmaxf(mx, __shfl_xor_sync(0xffffffffu, mx, 4));
            mx = fmaxf(mx, __shfl_xor_sync(0xffffffffu, mx, 8));
            float newm = fmaxf(mrun[i], mx);
            alpha[i] = exp2f((mrun[i] - newm) * LOG2E);
            float rs = 0.0f;
            float4 p4;
            float* pp = (float*)&p4;
            #pragma unroll
            for (int j = 0; j < 4; j++) {
                unsigned d = (unsigned)(dbase + i - j);
                float e = (d < (unsigned)CWIN)
                              ? exp2f((s[i][j] - newm) * LOG2E) : 0.0f;
                pp[j] = e;
                rs += e;
            }
            rs += __shfl_xor_sync(0xffffffffu, rs, 1);
            rs += __shfl_xor_sync(0xffffffffu, rs, 2);
            rs += __shfl_xor_sync(0xffffffffu, rs, 4);
            rs += __shfl_xor_sync(0xffffffffu, rs, 8);
            lrun[i] = lrun[i] * alpha[i] + rs;
            mrun[i] = newm;
            *(float4*)&Ps[(ty * 4 + i) * 68 + tx * 4] = p4;
        }
        __syncthreads();   // Ps visible to all

        // ---- rescale accumulator, O += P @ V ----
        #pragma unroll
        for (int i = 0; i < 4; i++) {
            float al = alpha[i];
            #pragma unroll
            for (int c = 0; c < 16; c++) o[i][c] *= al;
        }
        #pragma unroll 2
        for (int kb = 0; kb < 16; kb++) {
            float4 pv[4];
            #pragma unroll
            for (int i = 0; i < 4; i++)
                pv[i] = *(const float4*)&Ps[(ty * 4 + i) * 68 + kb * 4];
            const float* pvf = (const float*)pv;
            const int vkey = 4 * kb;   // (kv>>2) == kb for j<4
            #pragma unroll
            for (int j = 0; j < 4; j++) {
                int kv = kb * 4 + j;
                float4 v4[4];
                #pragma unroll
                for (int m = 0; m < 4; m++)
                    v4[m] = *(const float4*)&Vs[kv * 256 + ((4 * tx + 64 * m) ^ vkey)];
                #pragma unroll
                for (int i = 0; i < 4; i++) {
                    float p = pvf[i * 4 + j];
                    #pragma unroll
                    for (int m = 0; m < 4; m++) {
                        o[i][m * 4 + 0] = fmaf(p, v4[m].x, o[i][m * 4 + 0]);
                        o[i][m * 4 + 1] = fmaf(p, v4[m].y, o[i][m * 4 + 1]);
                        o[i][m * 4 + 2] = fmaf(p, v4[m].z, o[i][m * 4 + 2]);
                        o[i][m * 4 + 3] = fmaf(p, v4[m].w, o[i][m * 4 + 3]);
                    }
                }
            }
        }
    }

    // ---- epilogue ----
    #pragma unroll
    for (int i = 0; i < 4; i++) {
        float inv = 1.0f / lrun[i];
        float* orow = O + (size_t)(q0 + ty * 4 + i) * CQD + h * CD;
        #pragma unroll
        for (int m = 0; m < 4; m++) {
            *(float4*)&orow[4 * tx + 64 * m] =
                make_float4(o[i][4 * m + 0] * inv, o[i][4 * m + 1] * inv,
                            o[i][4 * m + 2] * inv, o[i][4 * m + 3] * inv);
        }
    }
}

// ---------------------------------------------------------------------------
extern "C" void kernel_launch(void* const* d_in, const int* in_sizes, int n_in,
                              void* d_out, int out_size) {
    const float* x  = (const float*)d_in[0];
    const int*   ps = (const int*)  d_in[1];
    const float* Wq = (const float*)d_in[2];
    const float* Wk = (const float*)d_in[3];
    const float* Wv = (const float*)d_in[4];
    const float* Wo = (const float*)d_in[5];
    const float* qw = (const float*)d_in[6];
    const float* kw = (const float*)d_in[7];
    float* out = (float*)d_out;
    (void)in_sizes; (void)n_in; (void)out_size;

    float *Qp, *Kp, *Vp, *AOp;
    cudaGetSymbolAddress((void**)&Qp,  g_Q);
    cudaGetSymbolAddress((void**)&Kp,  g_K);
    cudaGetSymbolAddress((void**)&Vp,  g_V);
    cudaGetSymbolAddress((void**)&AOp, g_AO);

    cudaFuncSetAttribute(flash_kernel,
                         cudaFuncAttributeMaxDynamicSharedMemorySize, FLASH_SMEM);

    init_invf_kernel<<<1, 128>>>();

    sgemm_kernel<<<dim3(CQD / 128, CT / 128), 256>>>(x, Wq, Qp, CT, CQD, CHID);
    sgemm_kernel<<<dim3(CKD / 128, CT / 128), 256>>>(x, Wk, Kp, CT, CKD, CHID);
    sgemm_kernel<<<dim3(CKD / 128, CT / 128), 256>>>(x, Wv, Vp, CT, CKD, CHID);

    norm_rope_kernel<<<dim3(CT, CH + CKH), 128>>>(Qp, Kp, ps, qw, kw);

    flash_kernel<<<dim3(CT / 64, CH), 256, FLASH_SMEM>>>(Qp, Kp, Vp, AOp);

    sgemm_kernel<<<dim3(CHID / 128, CT / 128), 256>>>(AOp, Wo, out, CT, CHID, CQD);
}

// round 6
// speedup vs baseline: 2.1061x; 1.7270x over previous
#include <cuda_runtime.h>
#include <cuda_bf16.h>
#include <math.h>
#include <stdint.h>

#define CT   4096
#define CHID 2560
#define CH   8
#define CKH  4
#define CD   256
#define CQD  2048   // H*D
#define CKD  1024   // KH*D
#define CWIN 1024
#define LOG2E 1.4426950408889634f

// ---------------- scratch (static device globals) ----------------
__device__ float g_Q[CT * CQD];
__device__ float g_K[CT * CKD];
__device__ float g_V[CT * CKD];
__device__ float g_AO[CT * CQD];
__device__ float g_invf[128];

__device__ __nv_bfloat16 g_xh[CT * CHID],  g_xl[CT * CHID];
__device__ __nv_bfloat16 g_Wqh[CQD * CHID], g_Wql[CQD * CHID];   // [N,K]
__device__ __nv_bfloat16 g_Wkh[CKD * CHID], g_Wkl[CKD * CHID];
__device__ __nv_bfloat16 g_Wvh[CKD * CHID], g_Wvl[CKD * CHID];
__device__ __nv_bfloat16 g_Woh[CHID * CQD], g_Wol[CHID * CQD];
__device__ __nv_bfloat16 g_AOh[CT * CQD],  g_AOl[CT * CQD];

// single dynamic smem symbol shared by all kernels
extern __shared__ char dyn_smem[];

// ---------------- PTX helpers (compute_103-safe: no tcgen05) ----------------
__device__ __forceinline__ uint32_t smem_u32(const void* p) {
    uint32_t a;
    asm("{ .reg .u64 t; cvta.to.shared.u64 t, %1; cvt.u32.u64 %0, t; }"
        : "=r"(a) : "l"(p));
    return a;
}
__device__ __forceinline__ void cp_async16(uint32_t s, const void* g) {
    asm volatile("cp.async.cg.shared.global [%0], [%1], 16;" :: "r"(s), "l"(g));
}
#define CP_COMMIT()  asm volatile("cp.async.commit_group;" ::: "memory")
#define CP_WAIT(n)   asm volatile("cp.async.wait_group %0;" :: "n"(n) : "memory")

#define LDSM_X4(r0, r1, r2, r3, addr) \
    asm volatile("ldmatrix.sync.aligned.m8n8.x4.shared.b16 {%0,%1,%2,%3}, [%4];" \
                 : "=r"(r0), "=r"(r1), "=r"(r2), "=r"(r3) : "r"(addr))

__device__ __forceinline__ void mma16816(float* d, const uint32_t* a,
                                         const uint32_t* b) {
    asm volatile(
        "mma.sync.aligned.m16n8k16.row.col.f32.bf16.bf16.f32 "
        "{%0,%1,%2,%3}, {%4,%5,%6,%7}, {%8,%9}, {%0,%1,%2,%3};"
        : "+f"(d[0]), "+f"(d[1]), "+f"(d[2]), "+f"(d[3])
        : "r"(a[0]), "r"(a[1]), "r"(a[2]), "r"(a[3]), "r"(b[0]), "r"(b[1]));
}

// ---------------- small prep kernels ----------------
__global__ void init_invf_kernel() {
    int d = threadIdx.x;
    if (d < 128) g_invf[d] = (float)pow(10000.0, -((double)d) / 128.0);
}

__global__ __launch_bounds__(256) void convert_split_kernel(
    const float* __restrict__ x, __nv_bfloat16* __restrict__ hi,
    __nv_bfloat16* __restrict__ lo, int n)
{
    int i = blockIdx.x * 256 + threadIdx.x;
    int stride = gridDim.x * 256;
    for (; i < n; i += stride) {
        float v = x[i];
        __nv_bfloat16 h = __float2bfloat16_rn(v);
        hi[i] = h;
        lo[i] = __float2bfloat16_rn(v - __bfloat162float(h));
    }
}

// W[K,N] f32 -> T[N,K] bf16 hi/lo
__global__ __launch_bounds__(256) void transpose_split_kernel(
    const float* __restrict__ W, __nv_bfloat16* __restrict__ Th,
    __nv_bfloat16* __restrict__ Tl, int K, int N)
{
    __shared__ float t[32][33];
    int n0 = blockIdx.x * 32, k0 = blockIdx.y * 32;
    int tx = threadIdx.x & 31, ty = threadIdx.x >> 5;   // 32 x 8
    #pragma unroll
    for (int r = 0; r < 4; r++)
        t[ty + 8 * r][tx] = W[(size_t)(k0 + ty + 8 * r) * N + n0 + tx];
    __syncthreads();
    #pragma unroll
    for (int r = 0; r < 4; r++) {
        float v = t[tx][ty + 8 * r];
        __nv_bfloat16 h = __float2bfloat16_rn(v);
        size_t o = (size_t)(n0 + ty + 8 * r) * K + k0 + tx;
        Th[o] = h;
        Tl[o] = __float2bfloat16_rn(v - __bfloat162float(h));
    }
}

// ---------------------------------------------------------------------------
// HMMA bf16-split GEMM: C[M,N] = (Ah+Al)[M,K] @ (Bh+Bl)[N,K]^T  (3 products)
// 128x128 CTA tile, 8 warps (warp tile 64x32 = 4x4 m16n8k16), BK=64,
// 2-stage cp.async double buffer, swizzled smem for conflict-free ldmatrix.
// ---------------------------------------------------------------------------
#define GSTAGE 65536
#define GEMM_SMEM (2 * GSTAGE)

__device__ __forceinline__ void gemm_issue_loads(
    uint32_t st, int tid, size_t aBase, size_t bBase, int k0, int K,
    const __nv_bfloat16* __restrict__ Ah, const __nv_bfloat16* __restrict__ Al,
    const __nv_bfloat16* __restrict__ Bh, const __nv_bfloat16* __restrict__ Bl)
{
    #pragma unroll
    for (int it = 0; it < 4; it++) {
        int id  = tid + it * 256;
        int row = id >> 3;
        int c16 = id & 7;
        uint32_t sw = (uint32_t)(row * 128) + ((uint32_t)(c16 ^ (row & 7)) << 4);
        size_t go = (size_t)row * K + k0 + c16 * 8;
        cp_async16(st + sw,         Ah + aBase + go);
        cp_async16(st + 16384 + sw, Al + aBase + go);
        cp_async16(st + 32768 + sw, Bh + bBase + go);
        cp_async16(st + 49152 + sw, Bl + bBase + go);
    }
    CP_COMMIT();
}

__global__ __launch_bounds__(256, 1) void gemm_hmma_kernel(
    const __nv_bfloat16* __restrict__ Ah, const __nv_bfloat16* __restrict__ Al,
    const __nv_bfloat16* __restrict__ Bh, const __nv_bfloat16* __restrict__ Bl,
    float* __restrict__ C, int M, int N, int K)
{
    const uint32_t smb = smem_u32(dyn_smem);
    const int tid  = threadIdx.x;
    const int wid  = tid >> 5;
    const int lane = tid & 31;
    const int warp_m = wid >> 2;        // 0..1 -> 64 rows
    const int warp_n = wid & 3;         // 0..3 -> 32 cols
    const int m0 = blockIdx.y * 128, n0 = blockIdx.x * 128;
    const int NC = K >> 6;
    const size_t aBase = (size_t)m0 * K;
    const size_t bBase = (size_t)n0 * K;

    float acc[4][4][4];
    #pragma unroll
    for (int mt = 0; mt < 4; mt++)
        #pragma unroll
        for (int nt = 0; nt < 4; nt++)
            #pragma unroll
            for (int r = 0; r < 4; r++) acc[mt][nt][r] = 0.0f;

    gemm_issue_loads(smb, tid, aBase, bBase, 0, K, Ah, Al, Bh, Bl);
    if (NC > 1)
        gemm_issue_loads(smb + GSTAGE, tid, aBase, bBase, 64, K, Ah, Al, Bh, Bl);

    const int row_in = lane & 15;
    const int hi     = lane >> 4;
    const uint32_t swkey = (uint32_t)(row_in & 7);

    for (int c = 0; c < NC; c++) {
        if (c + 1 < NC) { CP_WAIT(1); } else { CP_WAIT(0); }
        __syncthreads();

        const uint32_t sA  = smb + (c & 1) * GSTAGE;
        const uint32_t sAl = sA + 16384;
        const uint32_t sBh = sA + 32768;
        const uint32_t sBl = sA + 49152;

        #pragma unroll
        for (int ks = 0; ks < 4; ks++) {
            const uint32_t chunk = (uint32_t)(ks * 2 + hi);
            const uint32_t csw   = (chunk ^ swkey) << 4;

            uint32_t ah[4][4], al_[4][4];
            #pragma unroll
            for (int mt = 0; mt < 4; mt++) {
                uint32_t off = (uint32_t)(warp_m * 64 + mt * 16 + row_in) * 128 + csw;
                LDSM_X4(ah[mt][0], ah[mt][1], ah[mt][2], ah[mt][3], sA + off);
                LDSM_X4(al_[mt][0], al_[mt][1], al_[mt][2], al_[mt][3], sAl + off);
            }
            uint32_t bh[4][2], bl[4][2];
            #pragma unroll
            for (int p = 0; p < 2; p++) {
                uint32_t off = (uint32_t)(warp_n * 32 + p * 16 + row_in) * 128 + csw;
                uint32_t r0, r1, r2, r3;
                LDSM_X4(r0, r1, r2, r3, sBh + off);
                bh[2 * p][0] = r0; bh[2 * p + 1][0] = r1;
                bh[2 * p][1] = r2; bh[2 * p + 1][1] = r3;
                LDSM_X4(r0, r1, r2, r3, sBl + off);
                bl[2 * p][0] = r0; bl[2 * p + 1][0] = r1;
                bl[2 * p][1] = r2; bl[2 * p + 1][1] = r3;
            }
            #pragma unroll
            for (int mt = 0; mt < 4; mt++)
                #pragma unroll
                for (int nt = 0; nt < 4; nt++) {
                    mma16816(acc[mt][nt], ah[mt],  bh[nt]);
                    mma16816(acc[mt][nt], ah[mt],  bl[nt]);
                    mma16816(acc[mt][nt], al_[mt], bh[nt]);
                }
        }
        __syncthreads();
        if (c + 2 < NC)
            gemm_issue_loads(smb + (c & 1) * GSTAGE, tid, aBase, bBase,
                             (c + 2) << 6, K, Ah, Al, Bh, Bl);
    }

    // epilogue: direct register -> gmem (float2 per fragment half)
    #pragma unroll
    for (int mt = 0; mt < 4; mt++) {
        int row = m0 + warp_m * 64 + mt * 16 + (lane >> 2);
        #pragma unroll
        for (int nt = 0; nt < 4; nt++) {
            int col = n0 + warp_n * 32 + nt * 8 + (lane & 3) * 2;
            *(float2*)&C[(size_t)row * N + col] =
                make_float2(acc[mt][nt][0], acc[mt][nt][1]);
            *(float2*)&C[(size_t)(row + 8) * N + col] =
                make_float2(acc[mt][nt][2], acc[mt][nt][3]);
        }
    }
}

// ---------------------------------------------------------------------------
// Fused RMSNorm + neox RoPE (unchanged)
// ---------------------------------------------------------------------------
__global__ __launch_bounds__(128) void norm_rope_kernel(
    float* __restrict__ Qm, float* __restrict__ Km, const int* __restrict__ pos,
    const float* __restrict__ qw, const float* __restrict__ kw)
{
    int t  = blockIdx.x;
    int hh = blockIdx.y;
    float* base;
    const float* w;
    if (hh < CH) { base = Qm + (size_t)t * CQD + hh * CD;        w = qw; }
    else         { base = Km + (size_t)t * CKD + (hh - CH) * CD; w = kw; }

    int d = threadIdx.x;
    float x1 = base[d];
    float x2 = base[d + 128];
    float ss = x1 * x1 + x2 * x2;
    #pragma unroll
    for (int off = 16; off > 0; off >>= 1)
        ss += __shfl_xor_sync(0xffffffffu, ss, off);
    __shared__ float wsum[4];
    if ((d & 31) == 0) wsum[d >> 5] = ss;
    __syncthreads();
    float tot = wsum[0] + wsum[1] + wsum[2] + wsum[3];
    float inv = rsqrtf(tot * (1.0f / 256.0f) + 1e-6f);
    float n1 = x1 * inv * (1.0f + w[d]);
    float n2 = x2 * inv * (1.0f + w[d + 128]);

    float f = (float)pos[t] * g_invf[d];
    float c, s;
    sincosf(f, &s, &c);
    base[d]       = n1 * c - n2 * s;
    base[d + 128] = n2 * c + n1 * s;
}

// ---------------------------------------------------------------------------
// Flash attention (unchanged from R2)
// ---------------------------------------------------------------------------
#define FLASH_SMEM ((3 * 64 * 256 + 64 * 68) * 4)

__global__ __launch_bounds__(256, 1) void flash_kernel(
    const float* __restrict__ Q, const float* __restrict__ K,
    const float* __restrict__ V, float* __restrict__ O)
{
    float* sm = (float*)dyn_smem;
    float* Qs = sm;
    float* Ks = sm + 64 * 256;
    float* Vs = sm + 2 * 64 * 256;
    float* Ps = sm + 3 * 64 * 256;

    const int tid = threadIdx.x;
    const int tx  = tid & 15;
    const int ty  = tid >> 4;
    const int q0  = blockIdx.x * 64;
    const int h   = blockIdx.y;
    const int kvh = h >> 1;

    #pragma unroll
    for (int it = 0; it < 16; it++) {
        int id  = tid + it * 256;
        int row = id >> 6;
        int m   = id & 63;
        float4 v = *(const float4*)&Q[(size_t)(q0 + row) * CQD + h * CD + m * 4];
        int key = (row >> 2) * 4;
        v.x *= 0.0625f; v.y *= 0.0625f; v.z *= 0.0625f; v.w *= 0.0625f;
        *(float4*)&Qs[row * 256 + ((4 * m) ^ key)] = v;
    }

    float o[4][16];
    #pragma unroll
    for (int i = 0; i < 4; i++)
        #pragma unroll
        for (int c = 0; c < 16; c++) o[i][c] = 0.0f;
    float mrun[4] = {-1e30f, -1e30f, -1e30f, -1e30f};
    float lrun[4] = {0.0f, 0.0f, 0.0f, 0.0f};

    const int qkey = 4 * ty;

    int kb_lo = q0 - CWIN;
    if (kb_lo < 0) kb_lo = 0;

    for (int k0 = kb_lo; k0 <= q0; k0 += 64) {
        __syncthreads();
        #pragma unroll
        for (int it = 0; it < 16; it++) {
            int id  = tid + it * 256;
            int row = id >> 6;
            int m   = id & 63;
            int key = (row >> 2) * 4;
            int off = row * 256 + ((4 * m) ^ key);
            *(float4*)&Ks[off] =
                *(const float4*)&K[(size_t)(k0 + row) * CKD + kvh * CD + m * 4];
            *(float4*)&Vs[off] =
                *(const float4*)&V[(size_t)(k0 + row) * CKD + kvh * CD + m * 4];
        }
        __syncthreads();

        float s[4][4];
        #pragma unroll
        for (int i = 0; i < 4; i++)
            #pragma unroll
            for (int j = 0; j < 4; j++) s[i][j] = 0.0f;

        const int kkey = 4 * tx;
        #pragma unroll 4
        for (int m = 0; m < 64; m++) {
            float4 q4[4], k4[4];
            #pragma unroll
            for (int i = 0; i < 4; i++)
                q4[i] = *(const float4*)&Qs[(ty * 4 + i) * 256 + ((4 * m) ^ qkey)];
            #pragma unroll
            for (int j = 0; j < 4; j++)
                k4[j] = *(const float4*)&Ks[(tx * 4 + j) * 256 + ((4 * m) ^ kkey)];
            #pragma unroll
            for (int i = 0; i < 4; i++)
                #pragma unroll
                for (int j = 0; j < 4; j++) {
                    s[i][j] = fmaf(q4[i].x, k4[j].x, s[i][j]);
                    s[i][j] = fmaf(q4[i].y, k4[j].y, s[i][j]);
                    s[i][j] = fmaf(q4[i].z, k4[j].z, s[i][j]);
                    s[i][j] = fmaf(q4[i].w, k4[j].w, s[i][j]);
                }
        }

        float alpha[4];
        const int dbase = (q0 - k0) + ty * 4 - tx * 4;
        #pragma unroll
        for (int i = 0; i < 4; i++) {
            float mx = -1e30f;
            #pragma unroll
            for (int j = 0; j < 4; j++) {
                unsigned d = (unsigned)(dbase + i - j);
                if (d < (unsigned)CWIN) mx = fmaxf(mx, s[i][j]);
            }
            mx = fmaxf(mx, __shfl_xor_sync(0xffffffffu, mx, 1));
            mx = fmaxf(mx, __shfl_xor_sync(0xffffffffu, mx, 2));
            mx = fmaxf(mx, __shfl_xor_sync(0xffffffffu, mx, 4));
            mx = fmaxf(mx, __shfl_xor_sync(0xffffffffu, mx, 8));
            float newm = fmaxf(mrun[i], mx);
            alpha[i] = exp2f((mrun[i] - newm) * LOG2E);
            float rs = 0.0f;
            float4 p4;
            float* pp = (float*)&p4;
            #pragma unroll
            for (int j = 0; j < 4; j++) {
                unsigned d = (unsigned)(dbase + i - j);
                float e = (d < (unsigned)CWIN)
                              ? exp2f((s[i][j] - newm) * LOG2E) : 0.0f;
                pp[j] = e;
                rs += e;
            }
            rs += __shfl_xor_sync(0xffffffffu, rs, 1);
            rs += __shfl_xor_sync(0xffffffffu, rs, 2);
            rs += __shfl_xor_sync(0xffffffffu, rs, 4);
            rs += __shfl_xor_sync(0xffffffffu, rs, 8);
            lrun[i] = lrun[i] * alpha[i] + rs;
            mrun[i] = newm;
            *(float4*)&Ps[(ty * 4 + i) * 68 + tx * 4] = p4;
        }
        __syncthreads();

        #pragma unroll
        for (int i = 0; i < 4; i++) {
            float al = alpha[i];
            #pragma unroll
            for (int c = 0; c < 16; c++) o[i][c] *= al;
        }
        #pragma unroll 2
        for (int kb = 0; kb < 16; kb++) {
            float4 pv[4];
            #pragma unroll
            for (int i = 0; i < 4; i++)
                pv[i] = *(const float4*)&Ps[(ty * 4 + i) * 68 + kb * 4];
            const float* pvf = (const float*)pv;
            const int vkey = 4 * kb;
            #pragma unroll
            for (int j = 0; j < 4; j++) {
                int kv = kb * 4 + j;
                float4 v4[4];
                #pragma unroll
                for (int m = 0; m < 4; m++)
                    v4[m] = *(const float4*)&Vs[kv * 256 + ((4 * tx + 64 * m) ^ vkey)];
                #pragma unroll
                for (int i = 0; i < 4; i++) {
                    float p = pvf[i * 4 + j];
                    #pragma unroll
                    for (int m = 0; m < 4; m++) {
                        o[i][m * 4 + 0] = fmaf(p, v4[m].x, o[i][m * 4 + 0]);
                        o[i][m * 4 + 1] = fmaf(p, v4[m].y, o[i][m * 4 + 1]);
                        o[i][m * 4 + 2] = fmaf(p, v4[m].z, o[i][m * 4 + 2]);
                        o[i][m * 4 + 3] = fmaf(p, v4[m].w, o[i][m * 4 + 3]);
                    }
                }
            }
        }
    }

    #pragma unroll
    for (int i = 0; i < 4; i++) {
        float inv = 1.0f / lrun[i];
        float* orow = O + (size_t)(q0 + ty * 4 + i) * CQD + h * CD;
        #pragma unroll
        for (int m = 0; m < 4; m++) {
            *(float4*)&orow[4 * tx + 64 * m] =
                make_float4(o[i][4 * m + 0] * inv, o[i][4 * m + 1] * inv,
                            o[i][4 * m + 2] * inv, o[i][4 * m + 3] * inv);
        }
    }
}

// ---------------------------------------------------------------------------
extern "C" void kernel_launch(void* const* d_in, const int* in_sizes, int n_in,
                              void* d_out, int out_size) {
    const float* x  = (const float*)d_in[0];
    const int*   ps = (const int*)  d_in[1];
    const float* Wq = (const float*)d_in[2];
    const float* Wk = (const float*)d_in[3];
    const float* Wv = (const float*)d_in[4];
    const float* Wo = (const float*)d_in[5];
    const float* qw = (const float*)d_in[6];
    const float* kw = (const float*)d_in[7];
    float* out = (float*)d_out;
    (void)in_sizes; (void)n_in; (void)out_size;

    float *Qp, *Kp, *Vp, *AOp;
    cudaGetSymbolAddress((void**)&Qp,  g_Q);
    cudaGetSymbolAddress((void**)&Kp,  g_K);
    cudaGetSymbolAddress((void**)&Vp,  g_V);
    cudaGetSymbolAddress((void**)&AOp, g_AO);
    __nv_bfloat16 *xh, *xl, *Wqh, *Wql, *Wkh, *Wkl, *Wvh, *Wvl, *Woh, *Wol, *AOh, *AOl;
    cudaGetSymbolAddress((void**)&xh,  g_xh);  cudaGetSymbolAddress((void**)&xl,  g_xl);
    cudaGetSymbolAddress((void**)&Wqh, g_Wqh); cudaGetSymbolAddress((void**)&Wql, g_Wql);
    cudaGetSymbolAddress((void**)&Wkh, g_Wkh); cudaGetSymbolAddress((void**)&Wkl, g_Wkl);
    cudaGetSymbolAddress((void**)&Wvh, g_Wvh); cudaGetSymbolAddress((void**)&Wvl, g_Wvl);
    cudaGetSymbolAddress((void**)&Woh, g_Woh); cudaGetSymbolAddress((void**)&Wol, g_Wol);
    cudaGetSymbolAddress((void**)&AOh, g_AOh); cudaGetSymbolAddress((void**)&AOl, g_AOl);

    cudaFuncSetAttribute(flash_kernel,
                         cudaFuncAttributeMaxDynamicSharedMemorySize, FLASH_SMEM);
    cudaFuncSetAttribute(gemm_hmma_kernel,
                         cudaFuncAttributeMaxDynamicSharedMemorySize, GEMM_SMEM);

    init_invf_kernel<<<1, 128>>>();

    // split inputs / transpose+split weights to bf16 [N,K]
    convert_split_kernel<<<512, 256>>>(x, xh, xl, CT * CHID);
    transpose_split_kernel<<<dim3(CQD / 32, CHID / 32), 256>>>(Wq, Wqh, Wql, CHID, CQD);
    transpose_split_kernel<<<dim3(CKD / 32, CHID / 32), 256>>>(Wk, Wkh, Wkl, CHID, CKD);
    transpose_split_kernel<<<dim3(CKD / 32, CHID / 32), 256>>>(Wv, Wvh, Wvl, CHID, CKD);
    transpose_split_kernel<<<dim3(CHID / 32, CQD / 32), 256>>>(Wo, Woh, Wol, CQD, CHID);

    // projections on tensor cores (HMMA)
    gemm_hmma_kernel<<<dim3(CQD / 128, CT / 128), 256, GEMM_SMEM>>>(
        xh, xl, Wqh, Wql, Qp, CT, CQD, CHID);
    gemm_hmma_kernel<<<dim3(CKD / 128, CT / 128), 256, GEMM_SMEM>>>(
        xh, xl, Wkh, Wkl, Kp, CT, CKD, CHID);
    gemm_hmma_kernel<<<dim3(CKD / 128, CT / 128), 256, GEMM_SMEM>>>(
        xh, xl, Wvh, Wvl, Vp, CT, CKD, CHID);

    norm_rope_kernel<<<dim3(CT, CH + CKH), 128>>>(Qp, Kp, ps, qw, kw);

    flash_kernel<<<dim3(CT / 64, CH), 256, FLASH_SMEM>>>(Qp, Kp, Vp, AOp);

    // output projection
    convert_split_kernel<<<512, 256>>>(AOp, AOh, AOl, CT * CQD);
    gemm_hmma_kernel<<<dim3(CHID / 128, CT / 128), 256, GEMM_SMEM>>>(
        AOh, AOl, Woh, Wol, out, CT, CHID, CQD);
}

// round 7
// speedup vs baseline: 2.9174x; 1.3852x over previous
#include <cuda_runtime.h>
#include <cuda_bf16.h>
#include <math.h>
#include <stdint.h>

#define CT   4096
#define CHID 2560
#define CH   8
#define CKH  4
#define CD   256
#define CQD  2048   // H*D
#define CKD  1024   // KH*D
#define CWIN 1024
#define LOG2E 1.4426950408889634f

// ---------------- scratch (static device globals) ----------------
__device__ float g_Q[CT * CQD];
__device__ float g_K[CT * CKD];
__device__ float g_V[CT * CKD];
__device__ float g_AO[CT * CQD];
__device__ float g_invf[128];

__device__ __nv_bfloat16 g_xh[CT * CHID],  g_xl[CT * CHID];
__device__ __nv_bfloat16 g_Wqh[CQD * CHID], g_Wql[CQD * CHID];   // [N,K]
__device__ __nv_bfloat16 g_Wkh[CKD * CHID], g_Wkl[CKD * CHID];
__device__ __nv_bfloat16 g_Wvh[CKD * CHID], g_Wvl[CKD * CHID];
__device__ __nv_bfloat16 g_Woh[CHID * CQD], g_Wol[CHID * CQD];
__device__ __nv_bfloat16 g_AOh[CT * CQD],  g_AOl[CT * CQD];

// flash operands, bf16 hi/lo
__device__ __nv_bfloat16 g_Qh[CT * CQD], g_Ql[CT * CQD];
__device__ __nv_bfloat16 g_Kh[CT * CKD], g_Kl[CT * CKD];
__device__ __nv_bfloat16 g_Vh[CT * CKD], g_Vl[CT * CKD];

extern __shared__ char dyn_smem[];

// ---------------- PTX helpers (compute_103-safe) ----------------
__device__ __forceinline__ uint32_t smem_u32(const void* p) {
    uint32_t a;
    asm("{ .reg .u64 t; cvta.to.shared.u64 t, %1; cvt.u32.u64 %0, t; }"
        : "=r"(a) : "l"(p));
    return a;
}
__device__ __forceinline__ void cp_async16(uint32_t s, const void* g) {
    asm volatile("cp.async.cg.shared.global [%0], [%1], 16;" :: "r"(s), "l"(g));
}
#define CP_COMMIT()  asm volatile("cp.async.commit_group;" ::: "memory")
#define CP_WAIT(n)   asm volatile("cp.async.wait_group %0;" :: "n"(n) : "memory")

#define LDSM_X4(r0, r1, r2, r3, addr) \
    asm volatile("ldmatrix.sync.aligned.m8n8.x4.shared.b16 {%0,%1,%2,%3}, [%4];" \
                 : "=r"(r0), "=r"(r1), "=r"(r2), "=r"(r3) : "r"(addr))
#define LDSM_X4_T(r0, r1, r2, r3, addr) \
    asm volatile("ldmatrix.sync.aligned.m8n8.x4.trans.shared.b16 {%0,%1,%2,%3}, [%4];" \
                 : "=r"(r0), "=r"(r1), "=r"(r2), "=r"(r3) : "r"(addr))

__device__ __forceinline__ void mma16816(float* d, const uint32_t* a,
                                         const uint32_t* b) {
    asm volatile(
        "mma.sync.aligned.m16n8k16.row.col.f32.bf16.bf16.f32 "
        "{%0,%1,%2,%3}, {%4,%5,%6,%7}, {%8,%9}, {%0,%1,%2,%3};"
        : "+f"(d[0]), "+f"(d[1]), "+f"(d[2]), "+f"(d[3])
        : "r"(a[0]), "r"(a[1]), "r"(a[2]), "r"(a[3]), "r"(b[0]), "r"(b[1]));
}
__device__ __forceinline__ float fast_exp2(float x) {
    float y;
    asm("ex2.approx.ftz.f32 %0, %1;" : "=f"(y) : "f"(x));
    return y;
}

// ---------------- small prep kernels ----------------
__global__ void init_invf_kernel() {
    int d = threadIdx.x;
    if (d < 128) g_invf[d] = (float)pow(10000.0, -((double)d) / 128.0);
}

__global__ __launch_bounds__(256) void convert_split_kernel(
    const float* __restrict__ x, __nv_bfloat16* __restrict__ hi,
    __nv_bfloat16* __restrict__ lo, int n)
{
    int i = blockIdx.x * 256 + threadIdx.x;
    int stride = gridDim.x * 256;
    for (; i < n; i += stride) {
        float v = x[i];
        __nv_bfloat16 h = __float2bfloat16_rn(v);
        hi[i] = h;
        lo[i] = __float2bfloat16_rn(v - __bfloat162float(h));
    }
}

// W[K,N] f32 -> T[N,K] bf16 hi/lo
__global__ __launch_bounds__(256) void transpose_split_kernel(
    const float* __restrict__ W, __nv_bfloat16* __restrict__ Th,
    __nv_bfloat16* __restrict__ Tl, int K, int N)
{
    __shared__ float t[32][33];
    int n0 = blockIdx.x * 32, k0 = blockIdx.y * 32;
    int tx = threadIdx.x & 31, ty = threadIdx.x >> 5;
    #pragma unroll
    for (int r = 0; r < 4; r++)
        t[ty + 8 * r][tx] = W[(size_t)(k0 + ty + 8 * r) * N + n0 + tx];
    __syncthreads();
    #pragma unroll
    for (int r = 0; r < 4; r++) {
        float v = t[tx][ty + 8 * r];
        __nv_bfloat16 h = __float2bfloat16_rn(v);
        size_t o = (size_t)(n0 + ty + 8 * r) * K + k0 + tx;
        Th[o] = h;
        Tl[o] = __float2bfloat16_rn(v - __bfloat162float(h));
    }
}

// ---------------------------------------------------------------------------
// HMMA bf16-split GEMM (unchanged from R6)
// ---------------------------------------------------------------------------
#define GSTAGE 65536
#define GEMM_SMEM (2 * GSTAGE)

__device__ __forceinline__ void gemm_issue_loads(
    uint32_t st, int tid, size_t aBase, size_t bBase, int k0, int K,
    const __nv_bfloat16* __restrict__ Ah, const __nv_bfloat16* __restrict__ Al,
    const __nv_bfloat16* __restrict__ Bh, const __nv_bfloat16* __restrict__ Bl)
{
    #pragma unroll
    for (int it = 0; it < 4; it++) {
        int id  = tid + it * 256;
        int row = id >> 3;
        int c16 = id & 7;
        uint32_t sw = (uint32_t)(row * 128) + ((uint32_t)(c16 ^ (row & 7)) << 4);
        size_t go = (size_t)row * K + k0 + c16 * 8;
        cp_async16(st + sw,         Ah + aBase + go);
        cp_async16(st + 16384 + sw, Al + aBase + go);
        cp_async16(st + 32768 + sw, Bh + bBase + go);
        cp_async16(st + 49152 + sw, Bl + bBase + go);
    }
    CP_COMMIT();
}

__global__ __launch_bounds__(256, 1) void gemm_hmma_kernel(
    const __nv_bfloat16* __restrict__ Ah, const __nv_bfloat16* __restrict__ Al,
    const __nv_bfloat16* __restrict__ Bh, const __nv_bfloat16* __restrict__ Bl,
    float* __restrict__ C, int M, int N, int K)
{
    const uint32_t smb = smem_u32(dyn_smem);
    const int tid  = threadIdx.x;
    const int wid  = tid >> 5;
    const int lane = tid & 31;
    const int warp_m = wid >> 2;
    const int warp_n = wid & 3;
    const int m0 = blockIdx.y * 128, n0 = blockIdx.x * 128;
    const int NC = K >> 6;
    const size_t aBase = (size_t)m0 * K;
    const size_t bBase = (size_t)n0 * K;

    float acc[4][4][4];
    #pragma unroll
    for (int mt = 0; mt < 4; mt++)
        #pragma unroll
        for (int nt = 0; nt < 4; nt++)
            #pragma unroll
            for (int r = 0; r < 4; r++) acc[mt][nt][r] = 0.0f;

    gemm_issue_loads(smb, tid, aBase, bBase, 0, K, Ah, Al, Bh, Bl);
    if (NC > 1)
        gemm_issue_loads(smb + GSTAGE, tid, aBase, bBase, 64, K, Ah, Al, Bh, Bl);

    const int row_in = lane & 15;
    const int hi     = lane >> 4;
    const uint32_t swkey = (uint32_t)(row_in & 7);

    for (int c = 0; c < NC; c++) {
        if (c + 1 < NC) { CP_WAIT(1); } else { CP_WAIT(0); }
        __syncthreads();

        const uint32_t sA  = smb + (c & 1) * GSTAGE;
        const uint32_t sAl = sA + 16384;
        const uint32_t sBh = sA + 32768;
        const uint32_t sBl = sA + 49152;

        #pragma unroll
        for (int ks = 0; ks < 4; ks++) {
            const uint32_t chunk = (uint32_t)(ks * 2 + hi);
            const uint32_t csw   = (chunk ^ swkey) << 4;

            uint32_t ah[4][4], al_[4][4];
            #pragma unroll
            for (int mt = 0; mt < 4; mt++) {
                uint32_t off = (uint32_t)(warp_m * 64 + mt * 16 + row_in) * 128 + csw;
                LDSM_X4(ah[mt][0], ah[mt][1], ah[mt][2], ah[mt][3], sA + off);
                LDSM_X4(al_[mt][0], al_[mt][1], al_[mt][2], al_[mt][3], sAl + off);
            }
            uint32_t bh[4][2], bl[4][2];
            #pragma unroll
            for (int p = 0; p < 2; p++) {
                uint32_t off = (uint32_t)(warp_n * 32 + p * 16 + row_in) * 128 + csw;
                uint32_t r0, r1, r2, r3;
                LDSM_X4(r0, r1, r2, r3, sBh + off);
                bh[2 * p][0] = r0; bh[2 * p + 1][0] = r1;
                bh[2 * p][1] = r2; bh[2 * p + 1][1] = r3;
                LDSM_X4(r0, r1, r2, r3, sBl + off);
                bl[2 * p][0] = r0; bl[2 * p + 1][0] = r1;
                bl[2 * p][1] = r2; bl[2 * p + 1][1] = r3;
            }
            #pragma unroll
            for (int mt = 0; mt < 4; mt++)
                #pragma unroll
                for (int nt = 0; nt < 4; nt++) {
                    mma16816(acc[mt][nt], ah[mt],  bh[nt]);
                    mma16816(acc[mt][nt], ah[mt],  bl[nt]);
                    mma16816(acc[mt][nt], al_[mt], bh[nt]);
                }
        }
        __syncthreads();
        if (c + 2 < NC)
            gemm_issue_loads(smb + (c & 1) * GSTAGE, tid, aBase, bBase,
                             (c + 2) << 6, K, Ah, Al, Bh, Bl);
    }

    #pragma unroll
    for (int mt = 0; mt < 4; mt++) {
        int row = m0 + warp_m * 64 + mt * 16 + (lane >> 2);
        #pragma unroll
        for (int nt = 0; nt < 4; nt++) {
            int col = n0 + warp_n * 32 + nt * 8 + (lane & 3) * 2;
            *(float2*)&C[(size_t)row * N + col] =
                make_float2(acc[mt][nt][0], acc[mt][nt][1]);
            *(float2*)&C[(size_t)(row + 8) * N + col] =
                make_float2(acc[mt][nt][2], acc[mt][nt][3]);
        }
    }
}

// ---------------------------------------------------------------------------
// Fused RMSNorm + neox RoPE -> bf16 hi/lo outputs for flash.
// Q is pre-scaled by SCALE*LOG2E (softmax runs in exp2 domain).
// ---------------------------------------------------------------------------
__global__ __launch_bounds__(128) void norm_rope_kernel(
    const float* __restrict__ Qm, const float* __restrict__ Km,
    const int* __restrict__ pos,
    const float* __restrict__ qw, const float* __restrict__ kw,
    __nv_bfloat16* __restrict__ Qh, __nv_bfloat16* __restrict__ Ql,
    __nv_bfloat16* __restrict__ Kh, __nv_bfloat16* __restrict__ Kl)
{
    int t  = blockIdx.x;
    int hh = blockIdx.y;
    const float* base;
    const float* w;
    bool isQ = hh < CH;
    if (isQ) { base = Qm + (size_t)t * CQD + hh * CD;        w = qw; }
    else     { base = Km + (size_t)t * CKD + (hh - CH) * CD; w = kw; }

    int d = threadIdx.x;
    float x1 = base[d];
    float x2 = base[d + 128];
    float ss = x1 * x1 + x2 * x2;
    #pragma unroll
    for (int off = 16; off > 0; off >>= 1)
        ss += __shfl_xor_sync(0xffffffffu, ss, off);
    __shared__ float wsum[4];
    if ((d & 31) == 0) wsum[d >> 5] = ss;
    __syncthreads();
    float tot = wsum[0] + wsum[1] + wsum[2] + wsum[3];
    float inv = rsqrtf(tot * (1.0f / 256.0f) + 1e-6f);
    float n1 = x1 * inv * (1.0f + w[d]);
    float n2 = x2 * inv * (1.0f + w[d + 128]);

    float f = (float)pos[t] * g_invf[d];
    float c, s;
    sincosf(f, &s, &c);
    float o1 = n1 * c - n2 * s;
    float o2 = n2 * c + n1 * s;

    if (isQ) {
        const float qs = 0.0625f * LOG2E;
        o1 *= qs; o2 *= qs;
        size_t o = (size_t)t * CQD + hh * CD + d;
        __nv_bfloat16 h1 = __float2bfloat16_rn(o1);
        __nv_bfloat16 h2 = __float2bfloat16_rn(o2);
        Qh[o] = h1;       Ql[o] = __float2bfloat16_rn(o1 - __bfloat162float(h1));
        Qh[o + 128] = h2; Ql[o + 128] = __float2bfloat16_rn(o2 - __bfloat162float(h2));
    } else {
        size_t o = (size_t)t * CKD + (hh - CH) * CD + d;
        __nv_bfloat16 h1 = __float2bfloat16_rn(o1);
        __nv_bfloat16 h2 = __float2bfloat16_rn(o2);
        Kh[o] = h1;       Kl[o] = __float2bfloat16_rn(o1 - __bfloat162float(h1));
        Kh[o + 128] = h2; Kl[o + 128] = __float2bfloat16_rn(o2 - __bfloat162float(h2));
    }
}

// ---------------------------------------------------------------------------
// HMMA flash attention with hi/lo bf16 split.
// CTA: 64 q rows x 64 kv tile, 256 threads = 8 warps.
// Warp (wq = wid>>1, wd = wid&1): 16 q rows; kv half (QK) / d half (PV).
// ---------------------------------------------------------------------------
#define FS_QH 0
#define FS_QL 32768
#define FS_KH 65536
#define FS_KL 98304
#define FS_VH 131072
#define FS_VL 163840
#define FS_PH 196608
#define FS_PL 204800
#define FS_SM 212992            // float sMax[2][64]
#define FS_SS 213504            // float sSum[2][64]
#define FLASH_SMEM 214016

__device__ __forceinline__ void flash_load_tile(
    uint32_t dstH, uint32_t dstL, const __nv_bfloat16* __restrict__ Sh,
    const __nv_bfloat16* __restrict__ Sl, int t0, int colbase, int ld, int tid)
{
    #pragma unroll
    for (int it = 0; it < 8; it++) {
        int id  = tid + it * 256;
        int row = id >> 5;
        int c16 = id & 31;
        uint32_t sw = (uint32_t)(row * 512) + ((uint32_t)(c16 ^ (row & 7)) << 4);
        size_t go = (size_t)(t0 + row) * ld + colbase + c16 * 8;
        cp_async16(dstH + sw, Sh + go);
        cp_async16(dstL + sw, Sl + go);
    }
    CP_COMMIT();
}

__global__ __launch_bounds__(256, 1) void flash_hmma_kernel(
    const __nv_bfloat16* __restrict__ Qh, const __nv_bfloat16* __restrict__ Ql,
    const __nv_bfloat16* __restrict__ Kh, const __nv_bfloat16* __restrict__ Kl,
    const __nv_bfloat16* __restrict__ Vh, const __nv_bfloat16* __restrict__ Vl,
    float* __restrict__ O)
{
    const uint32_t smb = smem_u32(dyn_smem);
    float* sMax = (float*)(dyn_smem + FS_SM);
    float* sSum = (float*)(dyn_smem + FS_SS);

    const int tid  = threadIdx.x;
    const int wid  = tid >> 5;
    const int lane = tid & 31;
    const int wq   = wid >> 1;
    const int wd   = wid & 1;
    const int q0   = blockIdx.x * 64;
    const int h    = blockIdx.y;
    const int kvh  = h >> 1;

    const int row_in = lane & 15;
    const int hi     = lane >> 4;
    const uint32_t swkey = (uint32_t)(row_in & 7);
    const int qr = lane >> 2;            // quad row 0..7
    const int qc = (lane & 3) * 2;       // quad col base

    // O accumulators: 16 q rows x 128 d (16 n8 tiles)
    float oacc[16][4];
    #pragma unroll
    for (int nt = 0; nt < 16; nt++)
        #pragma unroll
        for (int r = 0; r < 4; r++) oacc[nt][r] = 0.0f;
    float mrun0 = -1e30f, mrun1 = -1e30f, lrun0 = 0.0f, lrun1 = 0.0f;

    int kb_lo = q0 - CWIN;
    if (kb_lo < 0) kb_lo = 0;

    // Q tile load (group 0), first K tile (group 1)
    flash_load_tile(smb + FS_QH, smb + FS_QL, Qh, Ql, q0, h * CD, CQD, tid);
    flash_load_tile(smb + FS_KH, smb + FS_KL, Kh, Kl, kb_lo, kvh * CD, CKD, tid);

    for (int k0 = kb_lo; k0 <= q0; k0 += 64) {
        // V for this tile (overlaps QK)
        flash_load_tile(smb + FS_VH, smb + FS_VL, Vh, Vl, k0, kvh * CD, CKD, tid);
        CP_WAIT(1);           // Q + K(current) done
        __syncthreads();

        // ---- S = Q K^T : 4 n8-tiles over this warp's 32 kv cols ----
        float sacc[4][4];
        #pragma unroll
        for (int nt = 0; nt < 4; nt++)
            #pragma unroll
            for (int r = 0; r < 4; r++) sacc[nt][r] = 0.0f;

        #pragma unroll
        for (int ks = 0; ks < 16; ks++) {
            const uint32_t csw = ((uint32_t)(ks * 2 + hi) ^ swkey) << 4;
            uint32_t aH[4], aL[4];
            uint32_t offA = (uint32_t)(wq * 16 + row_in) * 512 + csw;
            LDSM_X4(aH[0], aH[1], aH[2], aH[3], smb + FS_QH + offA);
            LDSM_X4(aL[0], aL[1], aL[2], aL[3], smb + FS_QL + offA);
            uint32_t bH[4][2], bL[4][2];
            #pragma unroll
            for (int p = 0; p < 2; p++) {
                uint32_t offB = (uint32_t)(wd * 32 + p * 16 + row_in) * 512 + csw;
                uint32_t r0, r1, r2, r3;
                LDSM_X4(r0, r1, r2, r3, smb + FS_KH + offB);
                bH[2 * p][0] = r0; bH[2 * p + 1][0] = r1;
                bH[2 * p][1] = r2; bH[2 * p + 1][1] = r3;
                LDSM_X4(r0, r1, r2, r3, smb + FS_KL + offB);
                bL[2 * p][0] = r0; bL[2 * p + 1][0] = r1;
                bL[2 * p][1] = r2; bL[2 * p + 1][1] = r3;
            }
            #pragma unroll
            for (int nt = 0; nt < 4; nt++) {
                mma16816(sacc[nt], aH, bH[nt]);
                mma16816(sacc[nt], aH, bL[nt]);
                mma16816(sacc[nt], aL, bH[nt]);
            }
        }

        // ---- mask (only edge tiles need it) ----
        const bool needmask = (k0 + 64 > q0) || (k0 + 960 < q0);
        const int rbase = q0 + wq * 16 + qr;
        if (needmask) {
            #pragma unroll
            for (int nt = 0; nt < 4; nt++) {
                int kg = k0 + wd * 32 + nt * 8 + qc;
                #pragma unroll
                for (int e = 0; e < 4; e++) {
                    int qg = rbase + (e >> 1) * 8;
                    int kk = kg + (e & 1);
                    unsigned dd = (unsigned)(qg - kk);
                    if (dd >= (unsigned)CWIN) sacc[nt][e] = -1e30f;
                }
            }
        }

        // ---- online softmax (cross-warp-pair via smem stats) ----
        float mx0 = -1e30f, mx1 = -1e30f;
        #pragma unroll
        for (int nt = 0; nt < 4; nt++) {
            mx0 = fmaxf(mx0, fmaxf(sacc[nt][0], sacc[nt][1]));
            mx1 = fmaxf(mx1, fmaxf(sacc[nt][2], sacc[nt][3]));
        }
        mx0 = fmaxf(mx0, __shfl_xor_sync(0xffffffffu, mx0, 1));
        mx0 = fmaxf(mx0, __shfl_xor_sync(0xffffffffu, mx0, 2));
        mx1 = fmaxf(mx1, __shfl_xor_sync(0xffffffffu, mx1, 1));
        mx1 = fmaxf(mx1, __shfl_xor_sync(0xffffffffu, mx1, 2));
        if ((lane & 3) == 0) {
            sMax[wd * 64 + wq * 16 + qr]     = mx0;
            sMax[wd * 64 + wq * 16 + qr + 8] = mx1;
        }
        __syncthreads();
        mx0 = fmaxf(mx0, sMax[(1 - wd) * 64 + wq * 16 + qr]);
        mx1 = fmaxf(mx1, sMax[(1 - wd) * 64 + wq * 16 + qr + 8]);

        float newm0 = fmaxf(fmaxf(mrun0, mx0), -1e29f);
        float newm1 = fmaxf(fmaxf(mrun1, mx1), -1e29f);
        float alpha0 = fast_exp2(mrun0 - newm0);
        float alpha1 = fast_exp2(mrun1 - newm1);
        mrun0 = newm0; mrun1 = newm1;

        float rs0 = 0.0f, rs1 = 0.0f;
        float pv[4][4];
        #pragma unroll
        for (int nt = 0; nt < 4; nt++) {
            pv[nt][0] = fast_exp2(sacc[nt][0] - newm0);
            pv[nt][1] = fast_exp2(sacc[nt][1] - newm0);
            pv[nt][2] = fast_exp2(sacc[nt][2] - newm1);
            pv[nt][3] = fast_exp2(sacc[nt][3] - newm1);
            rs0 += pv[nt][0] + pv[nt][1];
            rs1 += pv[nt][2] + pv[nt][3];
        }
        rs0 += __shfl_xor_sync(0xffffffffu, rs0, 1);
        rs0 += __shfl_xor_sync(0xffffffffu, rs0, 2);
        rs1 += __shfl_xor_sync(0xffffffffu, rs1, 1);
        rs1 += __shfl_xor_sync(0xffffffffu, rs1, 2);
        if ((lane & 3) == 0) {
            sSum[wd * 64 + wq * 16 + qr]     = rs0;
            sSum[wd * 64 + wq * 16 + qr + 8] = rs1;
        }

        // ---- store P hi/lo fragments to smem ----
        #pragma unroll
        for (int nt = 0; nt < 4; nt++) {
            int kvc = wd * 32 + nt * 8 + qc;
            uint32_t c16 = (uint32_t)(kvc >> 3);
            #pragma unroll
            for (int hrow = 0; hrow < 2; hrow++) {
                int qrow = wq * 16 + qr + hrow * 8;
                uint32_t off = (uint32_t)qrow * 128 +
                               ((c16 ^ (uint32_t)(qrow & 7)) << 4) +
                               (uint32_t)(kvc & 7) * 2;
                float p0 = pv[nt][hrow * 2], p1 = pv[nt][hrow * 2 + 1];
                __nv_bfloat162 ph = __floats2bfloat162_rn(p0, p1);
                __nv_bfloat162 pl = __floats2bfloat162_rn(
                    p0 - __bfloat162float(ph.x), p1 - __bfloat162float(ph.y));
                *(uint32_t*)(dyn_smem + FS_PH + off) = *(uint32_t*)&ph;
                *(uint32_t*)(dyn_smem + FS_PL + off) = *(uint32_t*)&pl;
            }
        }

        // prefetch next K (overlaps PV)
        if (k0 + 64 <= q0)
            flash_load_tile(smb + FS_KH, smb + FS_KL, Kh, Kl, k0 + 64,
                            kvh * CD, CKD, tid);
        CP_WAIT(1);           // V(current) done; next-K may be pending
        __syncthreads();      // P + sums visible, V ready

        float os0 = sSum[(1 - wd) * 64 + wq * 16 + qr];
        float os1 = sSum[(1 - wd) * 64 + wq * 16 + qr + 8];
        lrun0 = lrun0 * alpha0 + rs0 + os0;
        lrun1 = lrun1 * alpha1 + rs1 + os1;

        // ---- rescale O, then O += P V ----
        #pragma unroll
        for (int nt = 0; nt < 16; nt++) {
            oacc[nt][0] *= alpha0; oacc[nt][1] *= alpha0;
            oacc[nt][2] *= alpha1; oacc[nt][3] *= alpha1;
        }
        #pragma unroll
        for (int ks = 0; ks < 4; ks++) {
            uint32_t pH[4], pL[4];
            uint32_t offP = (uint32_t)(wq * 16 + row_in) * 128 +
                            (((uint32_t)(ks * 2 + hi) ^ swkey) << 4);
            LDSM_X4(pH[0], pH[1], pH[2], pH[3], smb + FS_PH + offP);
            LDSM_X4(pL[0], pL[1], pL[2], pL[3], smb + FS_PL + offP);
            #pragma unroll
            for (int j = 0; j < 8; j++) {
                uint32_t c16v = (uint32_t)(wd * 16 + j * 2 + hi);
                uint32_t offV = (uint32_t)(ks * 16 + row_in) * 512 +
                                ((c16v ^ swkey) << 4);
                uint32_t h0, h1, h2, h3, l0, l1, l2, l3;
                LDSM_X4_T(h0, h1, h2, h3, smb + FS_VH + offV);
                LDSM_X4_T(l0, l1, l2, l3, smb + FS_VL + offV);
                uint32_t bh0[2] = {h0, h1}, bh1[2] = {h2, h3};
                uint32_t bl0[2] = {l0, l1}, bl1[2] = {l2, l3};
                mma16816(oacc[2 * j],     pH, bh0);
                mma16816(oacc[2 * j],     pH, bl0);
                mma16816(oacc[2 * j],     pL, bh0);
                mma16816(oacc[2 * j + 1], pH, bh1);
                mma16816(oacc[2 * j + 1], pH, bl1);
                mma16816(oacc[2 * j + 1], pL, bh1);
            }
        }
        __syncthreads();      // guard Vs/Ps reuse next tile
    }

    // ---- epilogue ----
    float inv0 = 1.0f / lrun0, inv1 = 1.0f / lrun1;
    int row0 = q0 + wq * 16 + qr;
    #pragma unroll
    for (int nt = 0; nt < 16; nt++) {
        int col = h * CD + wd * 128 + nt * 8 + qc;
        *(float2*)&O[(size_t)row0 * CQD + col] =
            make_float2(oacc[nt][0] * inv0, oacc[nt][1] * inv0);
        *(float2*)&O[(size_t)(row0 + 8) * CQD + col] =
            make_float2(oacc[nt][2] * inv1, oacc[nt][3] * inv1);
    }
}

// ---------------------------------------------------------------------------
extern "C" void kernel_launch(void* const* d_in, const int* in_sizes, int n_in,
                              void* d_out, int out_size) {
    const float* x  = (const float*)d_in[0];
    const int*   ps = (const int*)  d_in[1];
    const float* Wq = (const float*)d_in[2];
    const float* Wk = (const float*)d_in[3];
    const float* Wv = (const float*)d_in[4];
    const float* Wo = (const float*)d_in[5];
    const float* qw = (const float*)d_in[6];
    const float* kw = (const float*)d_in[7];
    float* out = (float*)d_out;
    (void)in_sizes; (void)n_in; (void)out_size;

    float *Qp, *Kp, *Vp, *AOp;
    cudaGetSymbolAddress((void**)&Qp,  g_Q);
    cudaGetSymbolAddress((void**)&Kp,  g_K);
    cudaGetSymbolAddress((void**)&Vp,  g_V);
    cudaGetSymbolAddress((void**)&AOp, g_AO);
    __nv_bfloat16 *xh, *xl, *Wqh, *Wql, *Wkh, *Wkl, *Wvh, *Wvl, *Woh, *Wol, *AOh, *AOl;
    __nv_bfloat16 *Qhh, *Qll, *Khh, *Kll, *Vhh, *Vll;
    cudaGetSymbolAddress((void**)&xh,  g_xh);  cudaGetSymbolAddress((void**)&xl,  g_xl);
    cudaGetSymbolAddress((void**)&Wqh, g_Wqh); cudaGetSymbolAddress((void**)&Wql, g_Wql);
    cudaGetSymbolAddress((void**)&Wkh, g_Wkh); cudaGetSymbolAddress((void**)&Wkl, g_Wkl);
    cudaGetSymbolAddress((void**)&Wvh, g_Wvh); cudaGetSymbolAddress((void**)&Wvl, g_Wvl);
    cudaGetSymbolAddress((void**)&Woh, g_Woh); cudaGetSymbolAddress((void**)&Wol, g_Wol);
    cudaGetSymbolAddress((void**)&AOh, g_AOh); cudaGetSymbolAddress((void**)&AOl, g_AOl);
    cudaGetSymbolAddress((void**)&Qhh, g_Qh);  cudaGetSymbolAddress((void**)&Qll, g_Ql);
    cudaGetSymbolAddress((void**)&Khh, g_Kh);  cudaGetSymbolAddress((void**)&Kll, g_Kl);
    cudaGetSymbolAddress((void**)&Vhh, g_Vh);  cudaGetSymbolAddress((void**)&Vll, g_Vl);

    cudaFuncSetAttribute(gemm_hmma_kernel,
                         cudaFuncAttributeMaxDynamicSharedMemorySize, GEMM_SMEM);
    cudaFuncSetAttribute(flash_hmma_kernel,
                         cudaFuncAttributeMaxDynamicSharedMemorySize, FLASH_SMEM);

    init_invf_kernel<<<1, 128>>>();

    convert_split_kernel<<<512, 256>>>(x, xh, xl, CT * CHID);
    transpose_split_kernel<<<dim3(CQD / 32, CHID / 32), 256>>>(Wq, Wqh, Wql, CHID, CQD);
    transpose_split_kernel<<<dim3(CKD / 32, CHID / 32), 256>>>(Wk, Wkh, Wkl, CHID, CKD);
    transpose_split_kernel<<<dim3(CKD / 32, CHID / 32), 256>>>(Wv, Wvh, Wvl, CHID, CKD);
    transpose_split_kernel<<<dim3(CHID / 32, CQD / 32), 256>>>(Wo, Woh, Wol, CQD, CHID);

    gemm_hmma_kernel<<<dim3(CQD / 128, CT / 128), 256, GEMM_SMEM>>>(
        xh, xl, Wqh, Wql, Qp, CT, CQD, CHID);
    gemm_hmma_kernel<<<dim3(CKD / 128, CT / 128), 256, GEMM_SMEM>>>(
        xh, xl, Wkh, Wkl, Kp, CT, CKD, CHID);
    gemm_hmma_kernel<<<dim3(CKD / 128, CT / 128), 256, GEMM_SMEM>>>(
        xh, xl, Wvh, Wvl, Vp, CT, CKD, CHID);

    norm_rope_kernel<<<dim3(CT, CH + CKH), 128>>>(Qp, Kp, ps, qw, kw,
                                                  Qhh, Qll, Khh, Kll);
    convert_split_kernel<<<512, 256>>>(Vp, Vhh, Vll, CT * CKD);

    flash_hmma_kernel<<<dim3(CT / 64, CH), 256, FLASH_SMEM>>>(
        Qhh, Qll, Khh, Kll, Vhh, Vll, AOp);

    convert_split_kernel<<<512, 256>>>(AOp, AOh, AOl, CT * CQD);
    gemm_hmma_kernel<<<dim3(CHID / 128, CT / 128), 256, GEMM_SMEM>>>(
        AOh, AOl, Woh, Wol, out, CT, CHID, CQD);
}

// round 8
// speedup vs baseline: 4.5616x; 1.5636x over previous
#include <cuda_runtime.h>
#include <cuda_fp16.h>
#include <math.h>
#include <stdint.h>

#define CT   4096
#define CHID 2560
#define CH   8
#define CKH  4
#define CD   256
#define CQD  2048   // H*D
#define CKD  1024   // KH*D
#define CWIN 1024
#define LOG2E 1.4426950408889634f
#define QSCALE (0.0625f * LOG2E)

// ---------------- scratch (static device globals) ----------------
__device__ float g_Q[CT * CQD];          // f32 Q proj (pre-norm)
__device__ float g_K[CT * CKD];          // f32 K proj (pre-norm)
__device__ float g_invf[128];

__device__ __half g_xs[CT * CHID];                       // x single fp16
__device__ __half g_Wqh[CQD * CHID], g_Wql[CQD * CHID];  // W [N,K] hi/lo
__device__ __half g_Wkh[CKD * CHID], g_Wkl[CKD * CHID];
__device__ __half g_Wvh[CKD * CHID], g_Wvl[CKD * CHID];
__device__ __half g_Woh[CHID * CQD], g_Wol[CHID * CQD];

__device__ __half g_Qs[CT * CQD];        // flash operands, single fp16
__device__ __half g_Ks[CT * CKD];
__device__ __half g_Vs[CT * CKD];
__device__ __half g_AOs[CT * CQD];       // attention output, single fp16

extern __shared__ char dyn_smem[];

// ---------------- PTX helpers (compute_103-safe) ----------------
__device__ __forceinline__ uint32_t smem_u32(const void* p) {
    uint32_t a;
    asm("{ .reg .u64 t; cvta.to.shared.u64 t, %1; cvt.u32.u64 %0, t; }"
        : "=r"(a) : "l"(p));
    return a;
}
__device__ __forceinline__ void cp_async16(uint32_t s, const void* g) {
    asm volatile("cp.async.cg.shared.global [%0], [%1], 16;" :: "r"(s), "l"(g));
}
#define CP_COMMIT()  asm volatile("cp.async.commit_group;" ::: "memory")
#define CP_WAIT(n)   asm volatile("cp.async.wait_group %0;" :: "n"(n) : "memory")

#define LDSM_X4(r0, r1, r2, r3, addr) \
    asm volatile("ldmatrix.sync.aligned.m8n8.x4.shared.b16 {%0,%1,%2,%3}, [%4];" \
                 : "=r"(r0), "=r"(r1), "=r"(r2), "=r"(r3) : "r"(addr))
#define LDSM_X4_T(r0, r1, r2, r3, addr) \
    asm volatile("ldmatrix.sync.aligned.m8n8.x4.trans.shared.b16 {%0,%1,%2,%3}, [%4];" \
                 : "=r"(r0), "=r"(r1), "=r"(r2), "=r"(r3) : "r"(addr))

__device__ __forceinline__ void mma16816(float* d, const uint32_t* a,
                                         const uint32_t* b) {
    asm volatile(
        "mma.sync.aligned.m16n8k16.row.col.f32.f16.f16.f32 "
        "{%0,%1,%2,%3}, {%4,%5,%6,%7}, {%8,%9}, {%0,%1,%2,%3};"
        : "+f"(d[0]), "+f"(d[1]), "+f"(d[2]), "+f"(d[3])
        : "r"(a[0]), "r"(a[1]), "r"(a[2]), "r"(a[3]), "r"(b[0]), "r"(b[1]));
}
__device__ __forceinline__ float fast_exp2(float x) {
    float y;
    asm("ex2.approx.ftz.f32 %0, %1;" : "=f"(y) : "f"(x));
    return y;
}

// ---------------- small prep kernels ----------------
__global__ void init_invf_kernel() {
    int d = threadIdx.x;
    if (d < 128) g_invf[d] = (float)pow(10000.0, -((double)d) / 128.0);
}

__global__ __launch_bounds__(256) void convert_f16_kernel(
    const float* __restrict__ x, __half* __restrict__ y, int n)
{
    int i = blockIdx.x * 256 + threadIdx.x;
    int stride = gridDim.x * 256;
    for (; i < n; i += stride) y[i] = __float2half_rn(x[i]);
}

// W[K,N] f32 -> T[N,K] fp16 hi/lo
__global__ __launch_bounds__(256) void transpose_split_kernel(
    const float* __restrict__ W, __half* __restrict__ Th,
    __half* __restrict__ Tl, int K, int N)
{
    __shared__ float t[32][33];
    int n0 = blockIdx.x * 32, k0 = blockIdx.y * 32;
    int tx = threadIdx.x & 31, ty = threadIdx.x >> 5;
    #pragma unroll
    for (int r = 0; r < 4; r++)
        t[ty + 8 * r][tx] = W[(size_t)(k0 + ty + 8 * r) * N + n0 + tx];
    __syncthreads();
    #pragma unroll
    for (int r = 0; r < 4; r++) {
        float v = t[tx][ty + 8 * r];
        __half h = __float2half_rn(v);
        size_t o = (size_t)(n0 + ty + 8 * r) * K + k0 + tx;
        Th[o] = h;
        Tl[o] = __float2half_rn(v - __half2float(h));
    }
}

// ---------------------------------------------------------------------------
// HMMA fp16 GEMM: C[M,N] = A[M,K] @ (Bh+Bl)[N,K]^T  (2 products, B split)
// 128x128 CTA tile, 8 warps (warp 64x32), BK=64, 2-stage cp.async.
// out_half: write __half C (for V proj), else float.
// ---------------------------------------------------------------------------
#define GSTAGE 49152
#define GEMM_SMEM (2 * GSTAGE)

__device__ __forceinline__ void gemm_issue_loads(
    uint32_t st, int tid, size_t aBase, size_t bBase, int k0, int K,
    const __half* __restrict__ A,
    const __half* __restrict__ Bh, const __half* __restrict__ Bl)
{
    #pragma unroll
    for (int it = 0; it < 4; it++) {
        int id  = tid + it * 256;
        int row = id >> 3;
        int c16 = id & 7;
        uint32_t sw = (uint32_t)(row * 128) + ((uint32_t)(c16 ^ (row & 7)) << 4);
        size_t go = (size_t)row * K + k0 + c16 * 8;
        cp_async16(st + sw,         A  + aBase + go);
        cp_async16(st + 16384 + sw, Bh + bBase + go);
        cp_async16(st + 32768 + sw, Bl + bBase + go);
    }
    CP_COMMIT();
}

__global__ __launch_bounds__(256, 2) void gemm_hmma_kernel(
    const __half* __restrict__ A,
    const __half* __restrict__ Bh, const __half* __restrict__ Bl,
    float* __restrict__ C, __half* __restrict__ Ch, int out_half,
    int M, int N, int K)
{
    const uint32_t smb = smem_u32(dyn_smem);
    const int tid  = threadIdx.x;
    const int wid  = tid >> 5;
    const int lane = tid & 31;
    const int warp_m = wid >> 2;
    const int warp_n = wid & 3;
    const int m0 = blockIdx.y * 128, n0 = blockIdx.x * 128;
    const int NC = K >> 6;
    const size_t aBase = (size_t)m0 * K;
    const size_t bBase = (size_t)n0 * K;

    float acc[4][4][4];
    #pragma unroll
    for (int mt = 0; mt < 4; mt++)
        #pragma unroll
        for (int nt = 0; nt < 4; nt++)
            #pragma unroll
            for (int r = 0; r < 4; r++) acc[mt][nt][r] = 0.0f;

    gemm_issue_loads(smb, tid, aBase, bBase, 0, K, A, Bh, Bl);
    if (NC > 1)
        gemm_issue_loads(smb + GSTAGE, tid, aBase, bBase, 64, K, A, Bh, Bl);

    const int row_in = lane & 15;
    const int hi     = lane >> 4;
    const uint32_t swkey = (uint32_t)(row_in & 7);

    for (int c = 0; c < NC; c++) {
        if (c + 1 < NC) { CP_WAIT(1); } else { CP_WAIT(0); }
        __syncthreads();

        const uint32_t sA  = smb + (c & 1) * GSTAGE;
        const uint32_t sBh = sA + 16384;
        const uint32_t sBl = sA + 32768;

        #pragma unroll
        for (int ks = 0; ks < 4; ks++) {
            const uint32_t csw = ((uint32_t)(ks * 2 + hi) ^ swkey) << 4;

            uint32_t ah[4][4];
            #pragma unroll
            for (int mt = 0; mt < 4; mt++) {
                uint32_t off = (uint32_t)(warp_m * 64 + mt * 16 + row_in) * 128 + csw;
                LDSM_X4(ah[mt][0], ah[mt][1], ah[mt][2], ah[mt][3], sA + off);
            }
            uint32_t bh[4][2], bl[4][2];
            #pragma unroll
            for (int p = 0; p < 2; p++) {
                uint32_t off = (uint32_t)(warp_n * 32 + p * 16 + row_in) * 128 + csw;
                uint32_t r0, r1, r2, r3;
                LDSM_X4(r0, r1, r2, r3, sBh + off);
                bh[2 * p][0] = r0; bh[2 * p + 1][0] = r1;
                bh[2 * p][1] = r2; bh[2 * p + 1][1] = r3;
                LDSM_X4(r0, r1, r2, r3, sBl + off);
                bl[2 * p][0] = r0; bl[2 * p + 1][0] = r1;
                bl[2 * p][1] = r2; bl[2 * p + 1][1] = r3;
            }
            #pragma unroll
            for (int mt = 0; mt < 4; mt++)
                #pragma unroll
                for (int nt = 0; nt < 4; nt++) {
                    mma16816(acc[mt][nt], ah[mt], bh[nt]);
                    mma16816(acc[mt][nt], ah[mt], bl[nt]);
                }
        }
        __syncthreads();
        if (c + 2 < NC)
            gemm_issue_loads(smb + (c & 1) * GSTAGE, tid, aBase, bBase,
                             (c + 2) << 6, K, A, Bh, Bl);
    }

    #pragma unroll
    for (int mt = 0; mt < 4; mt++) {
        int row = m0 + warp_m * 64 + mt * 16 + (lane >> 2);
        #pragma unroll
        for (int nt = 0; nt < 4; nt++) {
            int col = n0 + warp_n * 32 + nt * 8 + (lane & 3) * 2;
            if (out_half) {
                *(__half2*)&Ch[(size_t)row * N + col] =
                    __floats2half2_rn(acc[mt][nt][0], acc[mt][nt][1]);
                *(__half2*)&Ch[(size_t)(row + 8) * N + col] =
                    __floats2half2_rn(acc[mt][nt][2], acc[mt][nt][3]);
            } else {
                *(float2*)&C[(size_t)row * N + col] =
                    make_float2(acc[mt][nt][0], acc[mt][nt][1]);
                *(float2*)&C[(size_t)(row + 8) * N + col] =
                    make_float2(acc[mt][nt][2], acc[mt][nt][3]);
            }
        }
    }
}

// ---------------------------------------------------------------------------
// Fused RMSNorm + neox RoPE -> fp16 single outputs for flash (unscaled Q).
// ---------------------------------------------------------------------------
__global__ __launch_bounds__(128) void norm_rope_kernel(
    const float* __restrict__ Qm, const float* __restrict__ Km,
    const int* __restrict__ pos,
    const float* __restrict__ qw, const float* __restrict__ kw,
    __half* __restrict__ Qs, __half* __restrict__ Ks)
{
    int t  = blockIdx.x;
    int hh = blockIdx.y;
    const float* base;
    const float* w;
    bool isQ = hh < CH;
    if (isQ) { base = Qm + (size_t)t * CQD + hh * CD;        w = qw; }
    else     { base = Km + (size_t)t * CKD + (hh - CH) * CD; w = kw; }

    int d = threadIdx.x;
    float x1 = base[d];
    float x2 = base[d + 128];
    float ss = x1 * x1 + x2 * x2;
    #pragma unroll
    for (int off = 16; off > 0; off >>= 1)
        ss += __shfl_xor_sync(0xffffffffu, ss, off);
    __shared__ float wsum[4];
    if ((d & 31) == 0) wsum[d >> 5] = ss;
    __syncthreads();
    float tot = wsum[0] + wsum[1] + wsum[2] + wsum[3];
    float inv = rsqrtf(tot * (1.0f / 256.0f) + 1e-6f);
    float n1 = x1 * inv * (1.0f + w[d]);
    float n2 = x2 * inv * (1.0f + w[d + 128]);

    float f = (float)pos[t] * g_invf[d];
    float c, s;
    sincosf(f, &s, &c);
    float o1 = n1 * c - n2 * s;
    float o2 = n2 * c + n1 * s;

    if (isQ) {
        size_t o = (size_t)t * CQD + hh * CD + d;
        Qs[o]       = __float2half_rn(o1);
        Qs[o + 128] = __float2half_rn(o2);
    } else {
        size_t o = (size_t)t * CKD + (hh - CH) * CD + d;
        Ks[o]       = __float2half_rn(o1);
        Ks[o + 128] = __float2half_rn(o2);
    }
}

// ---------------------------------------------------------------------------
// HMMA flash attention, single fp16 operands.
// CTA: 64 q x 64 kv tile, 256 threads = 8 warps; warp (wq=wid>>1, wd=wid&1).
// Scores scaled by QSCALE post-MMA; softmax in exp2 domain.
// ---------------------------------------------------------------------------
#define FS_Q  0
#define FS_K  32768
#define FS_V  65536
#define FS_P  98304
#define FS_SM 106496            // float sMax[2][64]
#define FS_SS 107008            // float sSum[2][64]
#define FLASH_SMEM 107520

__device__ __forceinline__ void flash_load_tile(
    uint32_t dst, const __half* __restrict__ S, int t0, int colbase,
    int ld, int tid)
{
    #pragma unroll
    for (int it = 0; it < 8; it++) {
        int id  = tid + it * 256;
        int row = id >> 5;
        int c16 = id & 31;
        uint32_t sw = (uint32_t)(row * 512) + ((uint32_t)(c16 ^ (row & 7)) << 4);
        cp_async16(dst + sw, S + (size_t)(t0 + row) * ld + colbase + c16 * 8);
    }
    CP_COMMIT();
}

__global__ __launch_bounds__(256, 2) void flash_hmma_kernel(
    const __half* __restrict__ Qs, const __half* __restrict__ Ks,
    const __half* __restrict__ Vs, __half* __restrict__ AO)
{
    const uint32_t smb = smem_u32(dyn_smem);
    float* sMax = (float*)(dyn_smem + FS_SM);
    float* sSum = (float*)(dyn_smem + FS_SS);

    const int tid  = threadIdx.x;
    const int wid  = tid >> 5;
    const int lane = tid & 31;
    const int wq   = wid >> 1;
    const int wd   = wid & 1;
    const int q0   = blockIdx.x * 64;
    const int h    = blockIdx.y;
    const int kvh  = h >> 1;

    const int row_in = lane & 15;
    const int hi     = lane >> 4;
    const uint32_t swkey = (uint32_t)(row_in & 7);
    const int qr = lane >> 2;
    const int qc = (lane & 3) * 2;

    float oacc[16][4];
    #pragma unroll
    for (int nt = 0; nt < 16; nt++)
        #pragma unroll
        for (int r = 0; r < 4; r++) oacc[nt][r] = 0.0f;
    float mrun0 = -1e30f, mrun1 = -1e30f, lrun0 = 0.0f, lrun1 = 0.0f;

    int kb_lo = q0 - CWIN;
    if (kb_lo < 0) kb_lo = 0;

    flash_load_tile(smb + FS_Q, Qs, q0, h * CD, CQD, tid);
    flash_load_tile(smb + FS_K, Ks, kb_lo, kvh * CD, CKD, tid);

    for (int k0 = kb_lo; k0 <= q0; k0 += 64) {
        flash_load_tile(smb + FS_V, Vs, k0, kvh * CD, CKD, tid);
        CP_WAIT(1);           // Q + K(current) done
        __syncthreads();

        // ---- S = Q K^T ----
        float sacc[4][4];
        #pragma unroll
        for (int nt = 0; nt < 4; nt++)
            #pragma unroll
            for (int r = 0; r < 4; r++) sacc[nt][r] = 0.0f;

        #pragma unroll
        for (int ks = 0; ks < 16; ks++) {
            const uint32_t csw = ((uint32_t)(ks * 2 + hi) ^ swkey) << 4;
            uint32_t aQ[4];
            uint32_t offA = (uint32_t)(wq * 16 + row_in) * 512 + csw;
            LDSM_X4(aQ[0], aQ[1], aQ[2], aQ[3], smb + FS_Q + offA);
            uint32_t bK[4][2];
            #pragma unroll
            for (int p = 0; p < 2; p++) {
                uint32_t offB = (uint32_t)(wd * 32 + p * 16 + row_in) * 512 + csw;
                uint32_t r0, r1, r2, r3;
                LDSM_X4(r0, r1, r2, r3, smb + FS_K + offB);
                bK[2 * p][0] = r0; bK[2 * p + 1][0] = r1;
                bK[2 * p][1] = r2; bK[2 * p + 1][1] = r3;
            }
            #pragma unroll
            for (int nt = 0; nt < 4; nt++)
                mma16816(sacc[nt], aQ, bK[nt]);
        }
        #pragma unroll
        for (int nt = 0; nt < 4; nt++)
            #pragma unroll
            for (int r = 0; r < 4; r++) sacc[nt][r] *= QSCALE;

        // ---- mask (edge tiles) ----
        const bool needmask = (k0 + 64 > q0) || (k0 + 960 < q0);
        const int rbase = q0 + wq * 16 + qr;
        if (needmask) {
            #pragma unroll
            for (int nt = 0; nt < 4; nt++) {
                int kg = k0 + wd * 32 + nt * 8 + qc;
                #pragma unroll
                for (int e = 0; e < 4; e++) {
                    int qg = rbase + (e >> 1) * 8;
                    int kk = kg + (e & 1);
                    unsigned dd = (unsigned)(qg - kk);
                    if (dd >= (unsigned)CWIN) sacc[nt][e] = -1e30f;
                }
            }
        }

        // ---- online softmax ----
        float mx0 = -1e30f, mx1 = -1e30f;
        #pragma unroll
        for (int nt = 0; nt < 4; nt++) {
            mx0 = fmaxf(mx0, fmaxf(sacc[nt][0], sacc[nt][1]));
            mx1 = fmaxf(mx1, fmaxf(sacc[nt][2], sacc[nt][3]));
        }
        mx0 = fmaxf(mx0, __shfl_xor_sync(0xffffffffu, mx0, 1));
        mx0 = fmaxf(mx0, __shfl_xor_sync(0xffffffffu, mx0, 2));
        mx1 = fmaxf(mx1, __shfl_xor_sync(0xffffffffu, mx1, 1));
        mx1 = fmaxf(mx1, __shfl_xor_sync(0xffffffffu, mx1, 2));
        if ((lane & 3) == 0) {
            sMax[wd * 64 + wq * 16 + qr]     = mx0;
            sMax[wd * 64 + wq * 16 + qr + 8] = mx1;
        }
        __syncthreads();
        mx0 = fmaxf(mx0, sMax[(1 - wd) * 64 + wq * 16 + qr]);
        mx1 = fmaxf(mx1, sMax[(1 - wd) * 64 + wq * 16 + qr + 8]);

        float newm0 = fmaxf(fmaxf(mrun0, mx0), -1e29f);
        float newm1 = fmaxf(fmaxf(mrun1, mx1), -1e29f);
        float alpha0 = fast_exp2(mrun0 - newm0);
        float alpha1 = fast_exp2(mrun1 - newm1);
        mrun0 = newm0; mrun1 = newm1;

        float rs0 = 0.0f, rs1 = 0.0f;
        float pv[4][4];
        #pragma unroll
        for (int nt = 0; nt < 4; nt++) {
            pv[nt][0] = fast_exp2(sacc[nt][0] - newm0);
            pv[nt][1] = fast_exp2(sacc[nt][1] - newm0);
            pv[nt][2] = fast_exp2(sacc[nt][2] - newm1);
            pv[nt][3] = fast_exp2(sacc[nt][3] - newm1);
            rs0 += pv[nt][0] + pv[nt][1];
            rs1 += pv[nt][2] + pv[nt][3];
        }
        rs0 += __shfl_xor_sync(0xffffffffu, rs0, 1);
        rs0 += __shfl_xor_sync(0xffffffffu, rs0, 2);
        rs1 += __shfl_xor_sync(0xffffffffu, rs1, 1);
        rs1 += __shfl_xor_sync(0xffffffffu, rs1, 2);
        if ((lane & 3) == 0) {
            sSum[wd * 64 + wq * 16 + qr]     = rs0;
            sSum[wd * 64 + wq * 16 + qr + 8] = rs1;
        }

        // ---- store P fp16 fragments ----
        #pragma unroll
        for (int nt = 0; nt < 4; nt++) {
            int kvc = wd * 32 + nt * 8 + qc;
            uint32_t c16 = (uint32_t)(kvc >> 3);
            #pragma unroll
            for (int hrow = 0; hrow < 2; hrow++) {
                int qrow = wq * 16 + qr + hrow * 8;
                uint32_t off = (uint32_t)qrow * 128 +
                               ((c16 ^ (uint32_t)(qrow & 7)) << 4) +
                               (uint32_t)(kvc & 7) * 2;
                __half2 ph = __floats2half2_rn(pv[nt][hrow * 2],
                                               pv[nt][hrow * 2 + 1]);
                *(uint32_t*)(dyn_smem + FS_P + off) = *(uint32_t*)&ph;
            }
        }

        // prefetch next K (overlaps PV)
        if (k0 + 64 <= q0)
            flash_load_tile(smb + FS_K, Ks, k0 + 64, kvh * CD, CKD, tid);
        CP_WAIT(1);           // V(current) done
        __syncthreads();      // P + sums visible

        float os0 = sSum[(1 - wd) * 64 + wq * 16 + qr];
        float os1 = sSum[(1 - wd) * 64 + wq * 16 + qr + 8];
        lrun0 = lrun0 * alpha0 + rs0 + os0;
        lrun1 = lrun1 * alpha1 + rs1 + os1;

        // ---- rescale O, O += P V ----
        #pragma unroll
        for (int nt = 0; nt < 16; nt++) {
            oacc[nt][0] *= alpha0; oacc[nt][1] *= alpha0;
            oacc[nt][2] *= alpha1; oacc[nt][3] *= alpha1;
        }
        #pragma unroll
        for (int ks = 0; ks < 4; ks++) {
            uint32_t pH[4];
            uint32_t offP = (uint32_t)(wq * 16 + row_in) * 128 +
                            (((uint32_t)(ks * 2 + hi) ^ swkey) << 4);
            LDSM_X4(pH[0], pH[1], pH[2], pH[3], smb + FS_P + offP);
            #pragma unroll
            for (int j = 0; j < 8; j++) {
                uint32_t c16v = (uint32_t)(wd * 16 + j * 2 + hi);
                uint32_t offV = (uint32_t)(ks * 16 + row_in) * 512 +
                                ((c16v ^ swkey) << 4);
                uint32_t h0, h1, h2, h3;
                LDSM_X4_T(h0, h1, h2, h3, smb + FS_V + offV);
                uint32_t b0[2] = {h0, h1}, b1[2] = {h2, h3};
                mma16816(oacc[2 * j],     pH, b0);
                mma16816(oacc[2 * j + 1], pH, b1);
            }
        }
        __syncthreads();
    }

    // ---- epilogue: fp16 AO ----
    float inv0 = 1.0f / lrun0, inv1 = 1.0f / lrun1;
    int row0 = q0 + wq * 16 + qr;
    #pragma unroll
    for (int nt = 0; nt < 16; nt++) {
        int col = h * CD + wd * 128 + nt * 8 + qc;
        *(__half2*)&AO[(size_t)row0 * CQD + col] =
            __floats2half2_rn(oacc[nt][0] * inv0, oacc[nt][1] * inv0);
        *(__half2*)&AO[(size_t)(row0 + 8) * CQD + col] =
            __floats2half2_rn(oacc[nt][2] * inv1, oacc[nt][3] * inv1);
    }
}

// ---------------------------------------------------------------------------
extern "C" void kernel_launch(void* const* d_in, const int* in_sizes, int n_in,
                              void* d_out, int out_size) {
    const float* x  = (const float*)d_in[0];
    const int*   ps = (const int*)  d_in[1];
    const float* Wq = (const float*)d_in[2];
    const float* Wk = (const float*)d_in[3];
    const float* Wv = (const float*)d_in[4];
    const float* Wo = (const float*)d_in[5];
    const float* qw = (const float*)d_in[6];
    const float* kw = (const float*)d_in[7];
    float* out = (float*)d_out;
    (void)in_sizes; (void)n_in; (void)out_size;

    float *Qp, *Kp;
    cudaGetSymbolAddress((void**)&Qp, g_Q);
    cudaGetSymbolAddress((void**)&Kp, g_K);
    __half *xs, *Wqh, *Wql, *Wkh, *Wkl, *Wvh, *Wvl, *Woh, *Wol;
    __half *Qss, *Kss, *Vss, *AOs;
    cudaGetSymbolAddress((void**)&xs,  g_xs);
    cudaGetSymbolAddress((void**)&Wqh, g_Wqh); cudaGetSymbolAddress((void**)&Wql, g_Wql);
    cudaGetSymbolAddress((void**)&Wkh, g_Wkh); cudaGetSymbolAddress((void**)&Wkl, g_Wkl);
    cudaGetSymbolAddress((void**)&Wvh, g_Wvh); cudaGetSymbolAddress((void**)&Wvl, g_Wvl);
    cudaGetSymbolAddress((void**)&Woh, g_Woh); cudaGetSymbolAddress((void**)&Wol, g_Wol);
    cudaGetSymbolAddress((void**)&Qss, g_Qs);  cudaGetSymbolAddress((void**)&Kss, g_Ks);
    cudaGetSymbolAddress((void**)&Vss, g_Vs);  cudaGetSymbolAddress((void**)&AOs, g_AOs);

    cudaFuncSetAttribute(gemm_hmma_kernel,
                         cudaFuncAttributeMaxDynamicSharedMemorySize, GEMM_SMEM);
    cudaFuncSetAttribute(flash_hmma_kernel,
                         cudaFuncAttributeMaxDynamicSharedMemorySize, FLASH_SMEM);

    init_invf_kernel<<<1, 128>>>();

    convert_f16_kernel<<<512, 256>>>(x, xs, CT * CHID);
    transpose_split_kernel<<<dim3(CQD / 32, CHID / 32), 256>>>(Wq, Wqh, Wql, CHID, CQD);
    transpose_split_kernel<<<dim3(CKD / 32, CHID / 32), 256>>>(Wk, Wkh, Wkl, CHID, CKD);
    transpose_split_kernel<<<dim3(CKD / 32, CHID / 32), 256>>>(Wv, Wvh, Wvl, CHID, CKD);
    transpose_split_kernel<<<dim3(CHID / 32, CQD / 32), 256>>>(Wo, Woh, Wol, CQD, CHID);

    // projections (V straight to fp16)
    gemm_hmma_kernel<<<dim3(CQD / 128, CT / 128), 256, GEMM_SMEM>>>(
        xs, Wqh, Wql, Qp, (__half*)nullptr, 0, CT, CQD, CHID);
    gemm_hmma_kernel<<<dim3(CKD / 128, CT / 128), 256, GEMM_SMEM>>>(
        xs, Wkh, Wkl, Kp, (__half*)nullptr, 0, CT, CKD, CHID);
    gemm_hmma_kernel<<<dim3(CKD / 128, CT / 128), 256, GEMM_SMEM>>>(
        xs, Wvh, Wvl, (float*)nullptr, Vss, 1, CT, CKD, CHID);

    norm_rope_kernel<<<dim3(CT, CH + CKH), 128>>>(Qp, Kp, ps, qw, kw, Qss, Kss);

    flash_hmma_kernel<<<dim3(CT / 64, CH), 256, FLASH_SMEM>>>(Qss, Kss, Vss, AOs);

    gemm_hmma_kernel<<<dim3(CHID / 128, CT / 128), 256, GEMM_SMEM>>>(
        AOs, Woh, Wol, out, (__half*)nullptr, 0, CT, CHID, CQD);
}

// round 9
// speedup vs baseline: 5.9149x; 1.2967x over previous
#include <cuda_runtime.h>
#include <cuda_fp16.h>
#include <math.h>
#include <stdint.h>

#define CT   4096
#define CHID 2560
#define CH   8
#define CKH  4
#define CD   256
#define CQD  2048   // H*D
#define CKD  1024   // KH*D
#define CWIN 1024
#define LOG2E 1.4426950408889634f
#define QSCALE (0.0625f * LOG2E)

// ---------------- scratch (static device globals) ----------------
__device__ float g_Q[CT * CQD];          // f32 Q proj (pre-norm)
__device__ float g_K[CT * CKD];          // f32 K proj (pre-norm)
__device__ float g_invf[128];

__device__ __half g_xs[CT * CHID];                       // x single fp16
__device__ __half g_Wq[CQD * CHID];                      // W [N,K] single
__device__ __half g_Wk[CKD * CHID];
__device__ __half g_Wv[CKD * CHID];
__device__ __half g_Woh[CHID * CQD], g_Wol[CHID * CQD];  // Wo hi/lo

__device__ __half g_Qs[CT * CQD];        // flash operands, single fp16
__device__ __half g_Ks[CT * CKD];
__device__ __half g_Vs[CT * CKD];
__device__ __half g_AOs[CT * CQD];       // attention output, single fp16

extern __shared__ char dyn_smem[];

// ---------------- PTX helpers (compute_103-safe) ----------------
__device__ __forceinline__ uint32_t smem_u32(const void* p) {
    uint32_t a;
    asm("{ .reg .u64 t; cvta.to.shared.u64 t, %1; cvt.u32.u64 %0, t; }"
        : "=r"(a) : "l"(p));
    return a;
}
__device__ __forceinline__ void cp_async16(uint32_t s, const void* g) {
    asm volatile("cp.async.cg.shared.global [%0], [%1], 16;" :: "r"(s), "l"(g));
}
#define CP_COMMIT()  asm volatile("cp.async.commit_group;" ::: "memory")
#define CP_WAIT(n)   asm volatile("cp.async.wait_group %0;" :: "n"(n) : "memory")

#define LDSM_X4(r0, r1, r2, r3, addr) \
    asm volatile("ldmatrix.sync.aligned.m8n8.x4.shared.b16 {%0,%1,%2,%3}, [%4];" \
                 : "=r"(r0), "=r"(r1), "=r"(r2), "=r"(r3) : "r"(addr))
#define LDSM_X4_T(r0, r1, r2, r3, addr) \
    asm volatile("ldmatrix.sync.aligned.m8n8.x4.trans.shared.b16 {%0,%1,%2,%3}, [%4];" \
                 : "=r"(r0), "=r"(r1), "=r"(r2), "=r"(r3) : "r"(addr))

__device__ __forceinline__ void mma16816(float* d, const uint32_t* a,
                                         const uint32_t* b) {
    asm volatile(
        "mma.sync.aligned.m16n8k16.row.col.f32.f16.f16.f32 "
        "{%0,%1,%2,%3}, {%4,%5,%6,%7}, {%8,%9}, {%0,%1,%2,%3};"
        : "+f"(d[0]), "+f"(d[1]), "+f"(d[2]), "+f"(d[3])
        : "r"(a[0]), "r"(a[1]), "r"(a[2]), "r"(a[3]), "r"(b[0]), "r"(b[1]));
}
__device__ __forceinline__ float fast_exp2(float x) {
    float y;
    asm("ex2.approx.ftz.f32 %0, %1;" : "=f"(y) : "f"(x));
    return y;
}

// ---------------- small prep kernels ----------------
__global__ void init_invf_kernel() {
    int d = threadIdx.x;
    if (d < 128) g_invf[d] = (float)pow(10000.0, -((double)d) / 128.0);
}

__global__ __launch_bounds__(256) void convert_f16_kernel(
    const float* __restrict__ x, __half* __restrict__ y, int n)
{
    int i = blockIdx.x * 256 + threadIdx.x;
    int stride = gridDim.x * 256;
    for (; i < n; i += stride) y[i] = __float2half_rn(x[i]);
}

// All weight transposes in ONE launch (z selects matrix). W[K,N] -> T[N,K].
// Tl == nullptr -> single fp16 (no split).
__global__ __launch_bounds__(256) void transpose_all_kernel(
    const float* __restrict__ Wq, const float* __restrict__ Wk,
    const float* __restrict__ Wv, const float* __restrict__ Wo,
    __half* __restrict__ Tq, __half* __restrict__ Tk, __half* __restrict__ Tv,
    __half* __restrict__ Toh, __half* __restrict__ Tol)
{
    const float* W;
    __half *Th, *Tl = nullptr;
    int K, N;
    switch (blockIdx.z) {
        case 0: W = Wq; Th = Tq;  K = CHID; N = CQD;  break;
        case 1: W = Wk; Th = Tk;  K = CHID; N = CKD;  break;
        case 2: W = Wv; Th = Tv;  K = CHID; N = CKD;  break;
        default: W = Wo; Th = Toh; Tl = Tol; K = CQD; N = CHID; break;
    }
    int n0 = blockIdx.x * 32, k0 = blockIdx.y * 32;
    if (n0 >= N || k0 >= K) return;

    __shared__ float t[32][33];
    int tx = threadIdx.x & 31, ty = threadIdx.x >> 5;
    #pragma unroll
    for (int r = 0; r < 4; r++)
        t[ty + 8 * r][tx] = W[(size_t)(k0 + ty + 8 * r) * N + n0 + tx];
    __syncthreads();
    #pragma unroll
    for (int r = 0; r < 4; r++) {
        float v = t[tx][ty + 8 * r];
        __half h = __float2half_rn(v);
        size_t o = (size_t)(n0 + ty + 8 * r) * K + k0 + tx;
        Th[o] = h;
        if (Tl) Tl[o] = __float2half_rn(v - __half2float(h));
    }
}

// ---------------------------------------------------------------------------
// HMMA fp16 GEMM: C[M,N] = A[M,K] @ B[N,K]^T.
// SPLIT=1: B = Bh + Bl (2 products). SPLIT=0: single product.
// 128x128 CTA tile, 8 warps (64x32 warp tile), BK=64, 2-stage cp.async.
// ---------------------------------------------------------------------------
#define GSTAGE 49152
#define GEMM_SMEM (2 * GSTAGE)

template <int SPLIT>
__device__ __forceinline__ void gemm_issue_loads(
    uint32_t st, int tid, size_t aBase, size_t bBase, int k0, int K,
    const __half* __restrict__ A,
    const __half* __restrict__ Bh, const __half* __restrict__ Bl)
{
    #pragma unroll
    for (int it = 0; it < 4; it++) {
        int id  = tid + it * 256;
        int row = id >> 3;
        int c16 = id & 7;
        uint32_t sw = (uint32_t)(row * 128) + ((uint32_t)(c16 ^ (row & 7)) << 4);
        size_t go = (size_t)row * K + k0 + c16 * 8;
        cp_async16(st + sw,         A  + aBase + go);
        cp_async16(st + 16384 + sw, Bh + bBase + go);
        if (SPLIT) cp_async16(st + 32768 + sw, Bl + bBase + go);
    }
    CP_COMMIT();
}

template <int SPLIT>
__global__ __launch_bounds__(256, 2) void gemm_hmma_kernel(
    const __half* __restrict__ A,
    const __half* __restrict__ Bh, const __half* __restrict__ Bl,
    float* __restrict__ C, __half* __restrict__ Ch, int out_half,
    int M, int N, int K)
{
    const uint32_t smb = smem_u32(dyn_smem);
    const int tid  = threadIdx.x;
    const int wid  = tid >> 5;
    const int lane = tid & 31;
    const int warp_m = wid >> 2;
    const int warp_n = wid & 3;
    const int m0 = blockIdx.y * 128, n0 = blockIdx.x * 128;
    const int NC = K >> 6;
    const size_t aBase = (size_t)m0 * K;
    const size_t bBase = (size_t)n0 * K;

    float acc[4][4][4];
    #pragma unroll
    for (int mt = 0; mt < 4; mt++)
        #pragma unroll
        for (int nt = 0; nt < 4; nt++)
            #pragma unroll
            for (int r = 0; r < 4; r++) acc[mt][nt][r] = 0.0f;

    gemm_issue_loads<SPLIT>(smb, tid, aBase, bBase, 0, K, A, Bh, Bl);
    if (NC > 1)
        gemm_issue_loads<SPLIT>(smb + GSTAGE, tid, aBase, bBase, 64, K, A, Bh, Bl);

    const int row_in = lane & 15;
    const int hi     = lane >> 4;
    const uint32_t swkey = (uint32_t)(row_in & 7);

    for (int c = 0; c < NC; c++) {
        if (c + 1 < NC) { CP_WAIT(1); } else { CP_WAIT(0); }
        __syncthreads();

        const uint32_t sA  = smb + (c & 1) * GSTAGE;
        const uint32_t sBh = sA + 16384;
        const uint32_t sBl = sA + 32768;

        #pragma unroll
        for (int ks = 0; ks < 4; ks++) {
            const uint32_t csw = ((uint32_t)(ks * 2 + hi) ^ swkey) << 4;

            uint32_t ah[4][4];
            #pragma unroll
            for (int mt = 0; mt < 4; mt++) {
                uint32_t off = (uint32_t)(warp_m * 64 + mt * 16 + row_in) * 128 + csw;
                LDSM_X4(ah[mt][0], ah[mt][1], ah[mt][2], ah[mt][3], sA + off);
            }
            uint32_t bh[4][2], bl[4][2];
            #pragma unroll
            for (int p = 0; p < 2; p++) {
                uint32_t off = (uint32_t)(warp_n * 32 + p * 16 + row_in) * 128 + csw;
                uint32_t r0, r1, r2, r3;
                LDSM_X4(r0, r1, r2, r3, sBh + off);
                bh[2 * p][0] = r0; bh[2 * p + 1][0] = r1;
                bh[2 * p][1] = r2; bh[2 * p + 1][1] = r3;
                if (SPLIT) {
                    LDSM_X4(r0, r1, r2, r3, sBl + off);
                    bl[2 * p][0] = r0; bl[2 * p + 1][0] = r1;
                    bl[2 * p][1] = r2; bl[2 * p + 1][1] = r3;
                }
            }
            #pragma unroll
            for (int mt = 0; mt < 4; mt++)
                #pragma unroll
                for (int nt = 0; nt < 4; nt++) {
                    mma16816(acc[mt][nt], ah[mt], bh[nt]);
                    if (SPLIT) mma16816(acc[mt][nt], ah[mt], bl[nt]);
                }
        }
        __syncthreads();
        if (c + 2 < NC)
            gemm_issue_loads<SPLIT>(smb + (c & 1) * GSTAGE, tid, aBase, bBase,
                                    (c + 2) << 6, K, A, Bh, Bl);
    }

    #pragma unroll
    for (int mt = 0; mt < 4; mt++) {
        int row = m0 + warp_m * 64 + mt * 16 + (lane >> 2);
        #pragma unroll
        for (int nt = 0; nt < 4; nt++) {
            int col = n0 + warp_n * 32 + nt * 8 + (lane & 3) * 2;
            if (out_half) {
                *(__half2*)&Ch[(size_t)row * N + col] =
                    __floats2half2_rn(acc[mt][nt][0], acc[mt][nt][1]);
                *(__half2*)&Ch[(size_t)(row + 8) * N + col] =
                    __floats2half2_rn(acc[mt][nt][2], acc[mt][nt][3]);
            } else {
                *(float2*)&C[(size_t)row * N + col] =
                    make_float2(acc[mt][nt][0], acc[mt][nt][1]);
                *(float2*)&C[(size_t)(row + 8) * N + col] =
                    make_float2(acc[mt][nt][2], acc[mt][nt][3]);
            }
        }
    }
}

// ---------------------------------------------------------------------------
// Fused RMSNorm + neox RoPE -> fp16. Q pre-scaled by QSCALE (exp2 domain).
// ---------------------------------------------------------------------------
__global__ __launch_bounds__(128) void norm_rope_kernel(
    const float* __restrict__ Qm, const float* __restrict__ Km,
    const int* __restrict__ pos,
    const float* __restrict__ qw, const float* __restrict__ kw,
    __half* __restrict__ Qs, __half* __restrict__ Ks)
{
    int t  = blockIdx.x;
    int hh = blockIdx.y;
    const float* base;
    const float* w;
    bool isQ = hh < CH;
    if (isQ) { base = Qm + (size_t)t * CQD + hh * CD;        w = qw; }
    else     { base = Km + (size_t)t * CKD + (hh - CH) * CD; w = kw; }

    int d = threadIdx.x;
    float x1 = base[d];
    float x2 = base[d + 128];
    float ss = x1 * x1 + x2 * x2;
    #pragma unroll
    for (int off = 16; off > 0; off >>= 1)
        ss += __shfl_xor_sync(0xffffffffu, ss, off);
    __shared__ float wsum[4];
    if ((d & 31) == 0) wsum[d >> 5] = ss;
    __syncthreads();
    float tot = wsum[0] + wsum[1] + wsum[2] + wsum[3];
    float inv = rsqrtf(tot * (1.0f / 256.0f) + 1e-6f);
    float n1 = x1 * inv * (1.0f + w[d]);
    float n2 = x2 * inv * (1.0f + w[d + 128]);

    float f = (float)pos[t] * g_invf[d];
    float c, s;
    sincosf(f, &s, &c);
    float o1 = n1 * c - n2 * s;
    float o2 = n2 * c + n1 * s;

    if (isQ) {
        size_t o = (size_t)t * CQD + hh * CD + d;
        Qs[o]       = __float2half_rn(o1 * QSCALE);
        Qs[o + 128] = __float2half_rn(o2 * QSCALE);
    } else {
        size_t o = (size_t)t * CKD + (hh - CH) * CD + d;
        Ks[o]       = __float2half_rn(o1);
        Ks[o + 128] = __float2half_rn(o2);
    }
}

// ---------------------------------------------------------------------------
// HMMA flash attention, single fp16 operands. Q pre-scaled (exp2 domain).
// CTA: 64 q x 64 kv tile, 256 threads = 8 warps; warp (wq=wid>>1, wd=wid&1).
// ---------------------------------------------------------------------------
#define FS_Q  0
#define FS_K  32768
#define FS_V  65536
#define FS_P  98304
#define FS_SM 106496            // float sMax[2][64]
#define FS_SS 107008            // float sSum[2][64]
#define FLASH_SMEM 107520

__device__ __forceinline__ void flash_load_tile(
    uint32_t dst, const __half* __restrict__ S, int t0, int colbase,
    int ld, int tid)
{
    #pragma unroll
    for (int it = 0; it < 8; it++) {
        int id  = tid + it * 256;
        int row = id >> 5;
        int c16 = id & 31;
        uint32_t sw = (uint32_t)(row * 512) + ((uint32_t)(c16 ^ (row & 7)) << 4);
        cp_async16(dst + sw, S + (size_t)(t0 + row) * ld + colbase + c16 * 8);
    }
    CP_COMMIT();
}

__global__ __launch_bounds__(256, 2) void flash_hmma_kernel(
    const __half* __restrict__ Qs, const __half* __restrict__ Ks,
    const __half* __restrict__ Vs, __half* __restrict__ AO)
{
    const uint32_t smb = smem_u32(dyn_smem);
    float* sMax = (float*)(dyn_smem + FS_SM);
    float* sSum = (float*)(dyn_smem + FS_SS);

    const int tid  = threadIdx.x;
    const int wid  = tid >> 5;
    const int lane = tid & 31;
    const int wq   = wid >> 1;
    const int wd   = wid & 1;
    const int q0   = blockIdx.x * 64;
    const int h    = blockIdx.y;
    const int kvh  = h >> 1;

    const int row_in = lane & 15;
    const int hi     = lane >> 4;
    const uint32_t swkey = (uint32_t)(row_in & 7);
    const int qr = lane >> 2;
    const int qc = (lane & 3) * 2;

    float oacc[16][4];
    #pragma unroll
    for (int nt = 0; nt < 16; nt++)
        #pragma unroll
        for (int r = 0; r < 4; r++) oacc[nt][r] = 0.0f;
    float mrun0 = -1e30f, mrun1 = -1e30f, lrun0 = 0.0f, lrun1 = 0.0f;

    int kb_lo = q0 - CWIN;
    if (kb_lo < 0) kb_lo = 0;

    flash_load_tile(smb + FS_Q, Qs, q0, h * CD, CQD, tid);
    flash_load_tile(smb + FS_K, Ks, kb_lo, kvh * CD, CKD, tid);

    for (int k0 = kb_lo; k0 <= q0; k0 += 64) {
        flash_load_tile(smb + FS_V, Vs, k0, kvh * CD, CKD, tid);
        CP_WAIT(1);           // Q + K(current) done
        __syncthreads();

        // ---- S = Q K^T (exp2-domain logits) ----
        float sacc[4][4];
        #pragma unroll
        for (int nt = 0; nt < 4; nt++)
            #pragma unroll
            for (int r = 0; r < 4; r++) sacc[nt][r] = 0.0f;

        #pragma unroll
        for (int ks = 0; ks < 16; ks++) {
            const uint32_t csw = ((uint32_t)(ks * 2 + hi) ^ swkey) << 4;
            uint32_t aQ[4];
            uint32_t offA = (uint32_t)(wq * 16 + row_in) * 512 + csw;
            LDSM_X4(aQ[0], aQ[1], aQ[2], aQ[3], smb + FS_Q + offA);
            uint32_t bK[4][2];
            #pragma unroll
            for (int p = 0; p < 2; p++) {
                uint32_t offB = (uint32_t)(wd * 32 + p * 16 + row_in) * 512 + csw;
                uint32_t r0, r1, r2, r3;
                LDSM_X4(r0, r1, r2, r3, smb + FS_K + offB);
                bK[2 * p][0] = r0; bK[2 * p + 1][0] = r1;
                bK[2 * p][1] = r2; bK[2 * p + 1][1] = r3;
            }
            #pragma unroll
            for (int nt = 0; nt < 4; nt++)
                mma16816(sacc[nt], aQ, bK[nt]);
        }

        // ---- mask (edge tiles) ----
        const bool needmask = (k0 + 64 > q0) || (k0 + 960 < q0);
        const int rbase = q0 + wq * 16 + qr;
        if (needmask) {
            #pragma unroll
            for (int nt = 0; nt < 4; nt++) {
                int kg = k0 + wd * 32 + nt * 8 + qc;
                #pragma unroll
                for (int e = 0; e < 4; e++) {
                    int qg = rbase + (e >> 1) * 8;
                    int kk = kg + (e & 1);
                    unsigned dd = (unsigned)(qg - kk);
                    if (dd >= (unsigned)CWIN) sacc[nt][e] = -1e30f;
                }
            }
        }

        // ---- online softmax ----
        float mx0 = -1e30f, mx1 = -1e30f;
        #pragma unroll
        for (int nt = 0; nt < 4; nt++) {
            mx0 = fmaxf(mx0, fmaxf(sacc[nt][0], sacc[nt][1]));
            mx1 = fmaxf(mx1, fmaxf(sacc[nt][2], sacc[nt][3]));
        }
        mx0 = fmaxf(mx0, __shfl_xor_sync(0xffffffffu, mx0, 1));
        mx0 = fmaxf(mx0, __shfl_xor_sync(0xffffffffu, mx0, 2));
        mx1 = fmaxf(mx1, __shfl_xor_sync(0xffffffffu, mx1, 1));
        mx1 = fmaxf(mx1, __shfl_xor_sync(0xffffffffu, mx1, 2));
        if ((lane & 3) == 0) {
            sMax[wd * 64 + wq * 16 + qr]     = mx0;
            sMax[wd * 64 + wq * 16 + qr + 8] = mx1;
        }
        __syncthreads();
        mx0 = fmaxf(mx0, sMax[(1 - wd) * 64 + wq * 16 + qr]);
        mx1 = fmaxf(mx1, sMax[(1 - wd) * 64 + wq * 16 + qr + 8]);

        float newm0 = fmaxf(fmaxf(mrun0, mx0), -1e29f);
        float newm1 = fmaxf(fmaxf(mrun1, mx1), -1e29f);
        float alpha0 = fast_exp2(mrun0 - newm0);
        float alpha1 = fast_exp2(mrun1 - newm1);
        mrun0 = newm0; mrun1 = newm1;

        float rs0 = 0.0f, rs1 = 0.0f;
        float pv[4][4];
        #pragma unroll
        for (int nt = 0; nt < 4; nt++) {
            pv[nt][0] = fast_exp2(sacc[nt][0] - newm0);
            pv[nt][1] = fast_exp2(sacc[nt][1] - newm0);
            pv[nt][2] = fast_exp2(sacc[nt][2] - newm1);
            pv[nt][3] = fast_exp2(sacc[nt][3] - newm1);
            rs0 += pv[nt][0] + pv[nt][1];
            rs1 += pv[nt][2] + pv[nt][3];
        }
        rs0 += __shfl_xor_sync(0xffffffffu, rs0, 1);
        rs0 += __shfl_xor_sync(0xffffffffu, rs0, 2);
        rs1 += __shfl_xor_sync(0xffffffffu, rs1, 1);
        rs1 += __shfl_xor_sync(0xffffffffu, rs1, 2);
        if ((lane & 3) == 0) {
            sSum[wd * 64 + wq * 16 + qr]     = rs0;
            sSum[wd * 64 + wq * 16 + qr + 8] = rs1;
        }

        // ---- store P fp16 fragments ----
        #pragma unroll
        for (int nt = 0; nt < 4; nt++) {
            int kvc = wd * 32 + nt * 8 + qc;
            uint32_t c16 = (uint32_t)(kvc >> 3);
            #pragma unroll
            for (int hrow = 0; hrow < 2; hrow++) {
                int qrow = wq * 16 + qr + hrow * 8;
                uint32_t off = (uint32_t)qrow * 128 +
                               ((c16 ^ (uint32_t)(qrow & 7)) << 4) +
                               (uint32_t)(kvc & 7) * 2;
                __half2 ph = __floats2half2_rn(pv[nt][hrow * 2],
                                               pv[nt][hrow * 2 + 1]);
                *(uint32_t*)(dyn_smem + FS_P + off) = *(uint32_t*)&ph;
            }
        }

        // prefetch next K (overlaps PV)
        if (k0 + 64 <= q0)
            flash_load_tile(smb + FS_K, Ks, k0 + 64, kvh * CD, CKD, tid);
        CP_WAIT(1);           // V(current) done
        __syncthreads();      // P + sums visible

        float os0 = sSum[(1 - wd) * 64 + wq * 16 + qr];
        float os1 = sSum[(1 - wd) * 64 + wq * 16 + qr + 8];
        lrun0 = lrun0 * alpha0 + rs0 + os0;
        lrun1 = lrun1 * alpha1 + rs1 + os1;

        // ---- rescale O, O += P V ----
        #pragma unroll
        for (int nt = 0; nt < 16; nt++) {
            oacc[nt][0] *= alpha0; oacc[nt][1] *= alpha0;
            oacc[nt][2] *= alpha1; oacc[nt][3] *= alpha1;
        }
        #pragma unroll
        for (int ks = 0; ks < 4; ks++) {
            uint32_t pH[4];
            uint32_t offP = (uint32_t)(wq * 16 + row_in) * 128 +
                            (((uint32_t)(ks * 2 + hi) ^ swkey) << 4);
            LDSM_X4(pH[0], pH[1], pH[2], pH[3], smb + FS_P + offP);
            #pragma unroll
            for (int j = 0; j < 8; j++) {
                uint32_t c16v = (uint32_t)(wd * 16 + j * 2 + hi);
                uint32_t offV = (uint32_t)(ks * 16 + row_in) * 512 +
                                ((c16v ^ swkey) << 4);
                uint32_t h0, h1, h2, h3;
                LDSM_X4_T(h0, h1, h2, h3, smb + FS_V + offV);
                uint32_t b0[2] = {h0, h1}, b1[2] = {h2, h3};
                mma16816(oacc[2 * j],     pH, b0);
                mma16816(oacc[2 * j + 1], pH, b1);
            }
        }
        __syncthreads();
    }

    // ---- epilogue: fp16 AO ----
    float inv0 = 1.0f / lrun0, inv1 = 1.0f / lrun1;
    int row0 = q0 + wq * 16 + qr;
    #pragma unroll
    for (int nt = 0; nt < 16; nt++) {
        int col = h * CD + wd * 128 + nt * 8 + qc;
        *(__half2*)&AO[(size_t)row0 * CQD + col] =
            __floats2half2_rn(oacc[nt][0] * inv0, oacc[nt][1] * inv0);
        *(__half2*)&AO[(size_t)(row0 + 8) * CQD + col] =
            __floats2half2_rn(oacc[nt][2] * inv1, oacc[nt][3] * inv1);
    }
}

// ---------------------------------------------------------------------------
extern "C" void kernel_launch(void* const* d_in, const int* in_sizes, int n_in,
                              void* d_out, int out_size) {
    const float* x  = (const float*)d_in[0];
    const int*   ps = (const int*)  d_in[1];
    const float* Wq = (const float*)d_in[2];
    const float* Wk = (const float*)d_in[3];
    const float* Wv = (const float*)d_in[4];
    const float* Wo = (const float*)d_in[5];
    const float* qw = (const float*)d_in[6];
    const float* kw = (const float*)d_in[7];
    float* out = (float*)d_out;
    (void)in_sizes; (void)n_in; (void)out_size;

    float *Qp, *Kp;
    cudaGetSymbolAddress((void**)&Qp, g_Q);
    cudaGetSymbolAddress((void**)&Kp, g_K);
    __half *xs, *Wqs, *Wks, *Wvs, *Woh, *Wol, *Qss, *Kss, *Vss, *AOs;
    cudaGetSymbolAddress((void**)&xs,  g_xs);
    cudaGetSymbolAddress((void**)&Wqs, g_Wq);
    cudaGetSymbolAddress((void**)&Wks, g_Wk);
    cudaGetSymbolAddress((void**)&Wvs, g_Wv);
    cudaGetSymbolAddress((void**)&Woh, g_Woh); cudaGetSymbolAddress((void**)&Wol, g_Wol);
    cudaGetSymbolAddress((void**)&Qss, g_Qs);  cudaGetSymbolAddress((void**)&Kss, g_Ks);
    cudaGetSymbolAddress((void**)&Vss, g_Vs);  cudaGetSymbolAddress((void**)&AOs, g_AOs);

    cudaFuncSetAttribute(gemm_hmma_kernel<0>,
                         cudaFuncAttributeMaxDynamicSharedMemorySize, GEMM_SMEM);
    cudaFuncSetAttribute(gemm_hmma_kernel<1>,
                         cudaFuncAttributeMaxDynamicSharedMemorySize, GEMM_SMEM);
    cudaFuncSetAttribute(flash_hmma_kernel,
                         cudaFuncAttributeMaxDynamicSharedMemorySize, FLASH_SMEM);

    // launch order arranged so ncu (-s 5 -c 1) captures the Q GEMM (#6)
    init_invf_kernel<<<1, 128>>>();                                     // 1
    convert_f16_kernel<<<512, 256>>>(x, xs, CT * CHID);                 // 2
    transpose_all_kernel<<<dim3(80, 80, 4), 256>>>(                     // 3
        Wq, Wk, Wv, Wo, Wqs, Wks, Wvs, Woh, Wol);

    gemm_hmma_kernel<0><<<dim3(CKD / 128, CT / 128), 256, GEMM_SMEM>>>( // 4
        xs, Wks, nullptr, Kp, nullptr, 0, CT, CKD, CHID);
    gemm_hmma_kernel<0><<<dim3(CKD / 128, CT / 128), 256, GEMM_SMEM>>>( // 5
        xs, Wvs, nullptr, nullptr, Vss, 1, CT, CKD, CHID);
    gemm_hmma_kernel<0><<<dim3(CQD / 128, CT / 128), 256, GEMM_SMEM>>>( // 6 <- ncu
        xs, Wqs, nullptr, Qp, nullptr, 0, CT, CQD, CHID);

    norm_rope_kernel<<<dim3(CT, CH + CKH), 128>>>(Qp, Kp, ps, qw, kw,   // 7
                                                  Qss, Kss);

    flash_hmma_kernel<<<dim3(CT / 64, CH), 256, FLASH_SMEM>>>(          // 8
        Qss, Kss, Vss, AOs);

    gemm_hmma_kernel<1><<<dim3(CHID / 128, CT / 128), 256, GEMM_SMEM>>>( // 9
        AOs, Woh, Wol, out, nullptr, 0, CT, CHID, CQD);
}

// round 10
// speedup vs baseline: 7.3292x; 1.2391x over previous
#include <cuda_runtime.h>
#include <cuda_fp16.h>
#include <math.h>
#include <stdint.h>

#define CT   4096
#define CHID 2560
#define CH   8
#define CKH  4
#define CD   256
#define CQD  2048   // H*D
#define CKD  1024   // KH*D
#define CWIN 1024
#define LOG2E 1.4426950408889634f
#define QSCALE (0.0625f * LOG2E)

// ---------------- scratch (static device globals) ----------------
__device__ float g_Q[CT * CQD];          // f32 Q proj (pre-norm)
__device__ float g_K[CT * CKD];          // f32 K proj (pre-norm)
__device__ float g_invf[128];

__device__ __half g_xs[CT * CHID];                  // x fp16
__device__ __half g_Wqkv[(CQD + 2 * CKD) * CHID];   // [4096, 2560] concat [N,K]
__device__ __half g_Wot[CHID * CQD];                // Wo^T [2560, 2048]

__device__ __half g_Qs[CT * CQD];        // flash operands fp16
__device__ __half g_Ks[CT * CKD];
__device__ __half g_Vs[CT * CKD];
__device__ __half g_AOs[CT * CQD];       // attention output fp16

extern __shared__ char dyn_smem[];

// ---------------- PTX helpers (compute_103-safe) ----------------
__device__ __forceinline__ uint32_t smem_u32(const void* p) {
    uint32_t a;
    asm("{ .reg .u64 t; cvta.to.shared.u64 t, %1; cvt.u32.u64 %0, t; }"
        : "=r"(a) : "l"(p));
    return a;
}
__device__ __forceinline__ void cp_async16(uint32_t s, const void* g) {
    asm volatile("cp.async.cg.shared.global [%0], [%1], 16;" :: "r"(s), "l"(g));
}
#define CP_COMMIT()  asm volatile("cp.async.commit_group;" ::: "memory")
#define CP_WAIT(n)   asm volatile("cp.async.wait_group %0;" :: "n"(n) : "memory")

#define LDSM_X4(r0, r1, r2, r3, addr) \
    asm volatile("ldmatrix.sync.aligned.m8n8.x4.shared.b16 {%0,%1,%2,%3}, [%4];" \
                 : "=r"(r0), "=r"(r1), "=r"(r2), "=r"(r3) : "r"(addr))
#define LDSM_X4_T(r0, r1, r2, r3, addr) \
    asm volatile("ldmatrix.sync.aligned.m8n8.x4.trans.shared.b16 {%0,%1,%2,%3}, [%4];" \
                 : "=r"(r0), "=r"(r1), "=r"(r2), "=r"(r3) : "r"(addr))

__device__ __forceinline__ void mma16816(float* d, const uint32_t* a,
                                         const uint32_t* b) {
    asm volatile(
        "mma.sync.aligned.m16n8k16.row.col.f32.f16.f16.f32 "
        "{%0,%1,%2,%3}, {%4,%5,%6,%7}, {%8,%9}, {%0,%1,%2,%3};"
        : "+f"(d[0]), "+f"(d[1]), "+f"(d[2]), "+f"(d[3])
        : "r"(a[0]), "r"(a[1]), "r"(a[2]), "r"(a[3]), "r"(b[0]), "r"(b[1]));
}
__device__ __forceinline__ float fast_exp2(float x) {
    float y;
    asm("ex2.approx.ftz.f32 %0, %1;" : "=f"(y) : "f"(x));
    return y;
}
__device__ __forceinline__ uint32_t packh2(float a, float b) {
    __half2 t = __floats2half2_rn(a, b);
    return *(uint32_t*)&t;
}

// ---------------- small prep kernels ----------------
__global__ void init_invf_kernel() {
    int d = threadIdx.x;
    if (d < 128) g_invf[d] = (float)pow(10000.0, -((double)d) / 128.0);
}

__global__ __launch_bounds__(256) void convert_f16_kernel(
    const float* __restrict__ x, __half* __restrict__ y, int n)
{
    int i = blockIdx.x * 256 + threadIdx.x;
    int stride = gridDim.x * 256;
    for (; i < n; i += stride) y[i] = __float2half_rn(x[i]);
}

// All weight transposes in ONE launch (z selects matrix). W[K,N] -> T[N,K] fp16.
__global__ __launch_bounds__(256) void transpose_all_kernel(
    const float* __restrict__ Wq, const float* __restrict__ Wk,
    const float* __restrict__ Wv, const float* __restrict__ Wo,
    __half* __restrict__ Wqkv, __half* __restrict__ Wot)
{
    const float* W;
    __half* Th;
    int K, N;
    switch (blockIdx.z) {
        case 0: W = Wq; Th = Wqkv;                              K = CHID; N = CQD; break;
        case 1: W = Wk; Th = Wqkv + (size_t)CQD * CHID;         K = CHID; N = CKD; break;
        case 2: W = Wv; Th = Wqkv + (size_t)(CQD + CKD) * CHID; K = CHID; N = CKD; break;
        default: W = Wo; Th = Wot;                              K = CQD;  N = CHID; break;
    }
    int n0 = blockIdx.x * 32, k0 = blockIdx.y * 32;
    if (n0 >= N || k0 >= K) return;

    __shared__ float t[32][33];
    int tx = threadIdx.x & 31, ty = threadIdx.x >> 5;
    #pragma unroll
    for (int r = 0; r < 4; r++)
        t[ty + 8 * r][tx] = W[(size_t)(k0 + ty + 8 * r) * N + n0 + tx];
    __syncthreads();
    #pragma unroll
    for (int r = 0; r < 4; r++)
        Th[(size_t)(n0 + ty + 8 * r) * K + k0 + tx] =
            __float2half_rn(t[tx][ty + 8 * r]);
}

// ---------------------------------------------------------------------------
// HMMA fp16 GEMM core: 128x128 CTA tile, 8 warps (64x32 warp tile), BK=64,
// 3-stage cp.async pipeline, ONE syncthreads per K-chunk.
// ---------------------------------------------------------------------------
#define GSTG 32768
#define GEMM_SMEM (3 * GSTG)

__device__ __forceinline__ void gemm_issue(
    uint32_t st, int tid, size_t aBase, size_t bBase, int k0, int K,
    const __half* __restrict__ A, const __half* __restrict__ B)
{
    #pragma unroll
    for (int it = 0; it < 4; it++) {
        int id  = tid + it * 256;
        int row = id >> 3;
        int c16 = id & 7;
        uint32_t sw = (uint32_t)(row * 128) + ((uint32_t)(c16 ^ (row & 7)) << 4);
        size_t go = (size_t)row * K + k0 + c16 * 8;
        cp_async16(st + sw,         A + aBase + go);
        cp_async16(st + 16384 + sw, B + bBase + go);
    }
    CP_COMMIT();
}

__device__ __forceinline__ void gemm_core(
    uint32_t smb, int tid, int wid, int lane,
    size_t aBase, size_t bBase, int K,
    const __half* __restrict__ A, const __half* __restrict__ B,
    float acc[4][4][4])
{
    const int warp_m = wid >> 2;
    const int warp_n = wid & 3;
    const int NC = K >> 6;
    const int row_in = lane & 15;
    const int hi     = lane >> 4;
    const uint32_t swkey = (uint32_t)(row_in & 7);

    gemm_issue(smb, tid, aBase, bBase, 0, K, A, B);
    if (NC > 1) gemm_issue(smb + GSTG, tid, aBase, bBase, 64, K, A, B);

    for (int c = 0; c < NC; c++) {
        CP_WAIT(1);
        __syncthreads();
        if (c + 2 < NC)
            gemm_issue(smb + ((c + 2) % 3) * GSTG, tid, aBase, bBase,
                       (c + 2) << 6, K, A, B);
        const uint32_t sA = smb + (c % 3) * GSTG;
        const uint32_t sB = sA + 16384;

        #pragma unroll
        for (int ks = 0; ks < 4; ks++) {
            const uint32_t csw = ((uint32_t)(ks * 2 + hi) ^ swkey) << 4;
            uint32_t ah[4][4];
            #pragma unroll
            for (int mt = 0; mt < 4; mt++) {
                uint32_t off = (uint32_t)(warp_m * 64 + mt * 16 + row_in) * 128 + csw;
                LDSM_X4(ah[mt][0], ah[mt][1], ah[mt][2], ah[mt][3], sA + off);
            }
            uint32_t bf[4][2];
            #pragma unroll
            for (int p = 0; p < 2; p++) {
                uint32_t off = (uint32_t)(warp_n * 32 + p * 16 + row_in) * 128 + csw;
                uint32_t r0, r1, r2, r3;
                LDSM_X4(r0, r1, r2, r3, sB + off);
                bf[2 * p][0] = r0; bf[2 * p + 1][0] = r1;
                bf[2 * p][1] = r2; bf[2 * p + 1][1] = r3;
            }
            #pragma unroll
            for (int mt = 0; mt < 4; mt++)
                #pragma unroll
                for (int nt = 0; nt < 4; nt++)
                    mma16816(acc[mt][nt], ah[mt], bf[nt]);
        }
    }
}

// Fused QKV projection: N = 4096 concat (Q 2048 f32 | K 1024 f32 | V 1024 fp16)
__global__ __launch_bounds__(256, 2) void gemm_qkv_kernel(
    const __half* __restrict__ xs, const __half* __restrict__ Wqkv,
    float* __restrict__ Qf, float* __restrict__ Kf, __half* __restrict__ Vh)
{
    const uint32_t smb = smem_u32(dyn_smem);
    const int tid = threadIdx.x, wid = tid >> 5, lane = tid & 31;
    const int m0 = blockIdx.y * 128, n0 = blockIdx.x * 128;

    float acc[4][4][4];
    #pragma unroll
    for (int mt = 0; mt < 4; mt++)
        #pragma unroll
        for (int nt = 0; nt < 4; nt++)
            #pragma unroll
            for (int r = 0; r < 4; r++) acc[mt][nt][r] = 0.0f;

    gemm_core(smb, tid, wid, lane, (size_t)m0 * CHID, (size_t)n0 * CHID,
              CHID, xs, Wqkv, acc);

    float* Cf = nullptr; __half* Chh = nullptr;
    int ld, cb;
    if (n0 < CQD)            { Cf = Qf; ld = CQD; cb = n0; }
    else if (n0 < CQD + CKD) { Cf = Kf; ld = CKD; cb = n0 - CQD; }
    else                     { Chh = Vh; ld = CKD; cb = n0 - CQD - CKD; }

    const int warp_m = wid >> 2, warp_n = wid & 3;
    #pragma unroll
    for (int mt = 0; mt < 4; mt++) {
        int row = m0 + warp_m * 64 + mt * 16 + (lane >> 2);
        #pragma unroll
        for (int nt = 0; nt < 4; nt++) {
            int col = cb + warp_n * 32 + nt * 8 + (lane & 3) * 2;
            if (Chh) {
                *(__half2*)&Chh[(size_t)row * ld + col] =
                    __floats2half2_rn(acc[mt][nt][0], acc[mt][nt][1]);
                *(__half2*)&Chh[(size_t)(row + 8) * ld + col] =
                    __floats2half2_rn(acc[mt][nt][2], acc[mt][nt][3]);
            } else {
                *(float2*)&Cf[(size_t)row * ld + col] =
                    make_float2(acc[mt][nt][0], acc[mt][nt][1]);
                *(float2*)&Cf[(size_t)(row + 8) * ld + col] =
                    make_float2(acc[mt][nt][2], acc[mt][nt][3]);
            }
        }
    }
}

// Output projection: out[T, HID] = AO[T, QD] @ Wot[HID, QD]^T, f32 out
__global__ __launch_bounds__(256, 2) void gemm_o_kernel(
    const __half* __restrict__ AOs, const __half* __restrict__ Wot,
    float* __restrict__ out)
{
    const uint32_t smb = smem_u32(dyn_smem);
    const int tid = threadIdx.x, wid = tid >> 5, lane = tid & 31;
    const int m0 = blockIdx.y * 128, n0 = blockIdx.x * 128;

    float acc[4][4][4];
    #pragma unroll
    for (int mt = 0; mt < 4; mt++)
        #pragma unroll
        for (int nt = 0; nt < 4; nt++)
            #pragma unroll
            for (int r = 0; r < 4; r++) acc[mt][nt][r] = 0.0f;

    gemm_core(smb, tid, wid, lane, (size_t)m0 * CQD, (size_t)n0 * CQD,
              CQD, AOs, Wot, acc);

    const int warp_m = wid >> 2, warp_n = wid & 3;
    #pragma unroll
    for (int mt = 0; mt < 4; mt++) {
        int row = m0 + warp_m * 64 + mt * 16 + (lane >> 2);
        #pragma unroll
        for (int nt = 0; nt < 4; nt++) {
            int col = n0 + warp_n * 32 + nt * 8 + (lane & 3) * 2;
            *(float2*)&out[(size_t)row * CHID + col] =
                make_float2(acc[mt][nt][0], acc[mt][nt][1]);
            *(float2*)&out[(size_t)(row + 8) * CHID + col] =
                make_float2(acc[mt][nt][2], acc[mt][nt][3]);
        }
    }
}

// ---------------------------------------------------------------------------
// Fused RMSNorm + neox RoPE -> fp16. Q pre-scaled by QSCALE (exp2 domain).
// ---------------------------------------------------------------------------
__global__ __launch_bounds__(128) void norm_rope_kernel(
    const float* __restrict__ Qm, const float* __restrict__ Km,
    const int* __restrict__ pos,
    const float* __restrict__ qw, const float* __restrict__ kw,
    __half* __restrict__ Qs, __half* __restrict__ Ks)
{
    int t  = blockIdx.x;
    int hh = blockIdx.y;
    const float* base;
    const float* w;
    bool isQ = hh < CH;
    if (isQ) { base = Qm + (size_t)t * CQD + hh * CD;        w = qw; }
    else     { base = Km + (size_t)t * CKD + (hh - CH) * CD; w = kw; }

    int d = threadIdx.x;
    float x1 = base[d];
    float x2 = base[d + 128];
    float ss = x1 * x1 + x2 * x2;
    #pragma unroll
    for (int off = 16; off > 0; off >>= 1)
        ss += __shfl_xor_sync(0xffffffffu, ss, off);
    __shared__ float wsum[4];
    if ((d & 31) == 0) wsum[d >> 5] = ss;
    __syncthreads();
    float tot = wsum[0] + wsum[1] + wsum[2] + wsum[3];
    float inv = rsqrtf(tot * (1.0f / 256.0f) + 1e-6f);
    float n1 = x1 * inv * (1.0f + w[d]);
    float n2 = x2 * inv * (1.0f + w[d + 128]);

    float f = (float)pos[t] * g_invf[d];
    float c, s;
    sincosf(f, &s, &c);
    float o1 = n1 * c - n2 * s;
    float o2 = n2 * c + n1 * s;

    if (isQ) {
        size_t o = (size_t)t * CQD + hh * CD + d;
        Qs[o]       = __float2half_rn(o1 * QSCALE);
        Qs[o + 128] = __float2half_rn(o2 * QSCALE);
    } else {
        size_t o = (size_t)t * CKD + (hh - CH) * CD + d;
        Ks[o]       = __float2half_rn(o1);
        Ks[o + 128] = __float2half_rn(o2);
    }
}

// ---------------------------------------------------------------------------
// FA2-style HMMA flash attention, fp16, P in registers, warp-local softmax.
// CTA: 64 q x 64 kv tile, 256 thr = 8 warps; wq=wid>>1 (16 q rows, QK over
// ALL 64 kv — redundant across wd pair), wd=wid&1 (128-d half for PV).
// ---------------------------------------------------------------------------
#define FS_Q  0
#define FS_K  32768
#define FS_V  65536
#define FLASH_SMEM 98304

__device__ __forceinline__ void flash_load_tile(
    uint32_t dst, const __half* __restrict__ S, int t0, int colbase,
    int ld, int tid)
{
    #pragma unroll
    for (int it = 0; it < 8; it++) {
        int id  = tid + it * 256;
        int row = id >> 5;
        int c16 = id & 31;
        uint32_t sw = (uint32_t)(row * 512) + ((uint32_t)(c16 ^ (row & 7)) << 4);
        cp_async16(dst + sw, S + (size_t)(t0 + row) * ld + colbase + c16 * 8);
    }
    CP_COMMIT();
}

__global__ __launch_bounds__(256, 2) void flash_hmma_kernel(
    const __half* __restrict__ Qs, const __half* __restrict__ Ks,
    const __half* __restrict__ Vs, __half* __restrict__ AO)
{
    const uint32_t smb = smem_u32(dyn_smem);
    const int tid  = threadIdx.x;
    const int wid  = tid >> 5;
    const int lane = tid & 31;
    const int wq   = wid >> 1;
    const int wd   = wid & 1;
    const int q0   = blockIdx.x * 64;
    const int h    = blockIdx.y;
    const int kvh  = h >> 1;

    const int row_in = lane & 15;
    const int hi     = lane >> 4;
    const uint32_t swkey = (uint32_t)(row_in & 7);
    const int qr = lane >> 2;
    const int qc = (lane & 3) * 2;

    float oacc[16][4];
    #pragma unroll
    for (int nt = 0; nt < 16; nt++)
        #pragma unroll
        for (int r = 0; r < 4; r++) oacc[nt][r] = 0.0f;
    float mrun0 = -1e30f, mrun1 = -1e30f, lrun0 = 0.0f, lrun1 = 0.0f;

    int kb_lo = q0 - CWIN;
    if (kb_lo < 0) kb_lo = 0;

    flash_load_tile(smb + FS_Q, Qs, q0, h * CD, CQD, tid);      // grp 1
    flash_load_tile(smb + FS_K, Ks, kb_lo, kvh * CD, CKD, tid); // grp 2
    flash_load_tile(smb + FS_V, Vs, kb_lo, kvh * CD, CKD, tid); // grp 3

    for (int k0 = kb_lo; k0 <= q0; k0 += 64) {
        CP_WAIT(1);           // Q + K(cur) done; V(cur) may pend
        __syncthreads();

        // ---- S = Q K^T over all 64 kv (8 n8 tiles per warp) ----
        float sacc[8][4];
        #pragma unroll
        for (int nt = 0; nt < 8; nt++)
            #pragma unroll
            for (int r = 0; r < 4; r++) sacc[nt][r] = 0.0f;

        #pragma unroll
        for (int ks = 0; ks < 16; ks++) {
            const uint32_t csw = ((uint32_t)(ks * 2 + hi) ^ swkey) << 4;
            uint32_t aQ[4];
            LDSM_X4(aQ[0], aQ[1], aQ[2], aQ[3],
                    smb + FS_Q + (uint32_t)(wq * 16 + row_in) * 512 + csw);
            #pragma unroll
            for (int p = 0; p < 4; p++) {
                uint32_t r0, r1, r2, r3;
                LDSM_X4(r0, r1, r2, r3,
                        smb + FS_K + (uint32_t)(p * 16 + row_in) * 512 + csw);
                uint32_t b0[2] = {r0, r2}, b1[2] = {r1, r3};
                mma16816(sacc[2 * p],     aQ, b0);
                mma16816(sacc[2 * p + 1], aQ, b1);
            }
        }

        // ---- mask (edge tiles only) ----
        const bool needmask = (k0 + 64 > q0) || (k0 + (CWIN - 64) < q0);
        const int rbase = q0 + wq * 16 + qr;
        if (needmask) {
            #pragma unroll
            for (int nt = 0; nt < 8; nt++) {
                int kg = k0 + nt * 8 + qc;
                #pragma unroll
                for (int e = 0; e < 4; e++) {
                    int qg = rbase + (e >> 1) * 8;
                    int kk = kg + (e & 1);
                    unsigned dd = (unsigned)(qg - kk);
                    if (dd >= (unsigned)CWIN) sacc[nt][e] = -1e30f;
                }
            }
        }

        // ---- warp-local online softmax (quad shfl only) ----
        float mx0 = -1e30f, mx1 = -1e30f;
        #pragma unroll
        for (int nt = 0; nt < 8; nt++) {
            mx0 = fmaxf(mx0, fmaxf(sacc[nt][0], sacc[nt][1]));
            mx1 = fmaxf(mx1, fmaxf(sacc[nt][2], sacc[nt][3]));
        }
        mx0 = fmaxf(mx0, __shfl_xor_sync(0xffffffffu, mx0, 1));
        mx0 = fmaxf(mx0, __shfl_xor_sync(0xffffffffu, mx0, 2));
        mx1 = fmaxf(mx1, __shfl_xor_sync(0xffffffffu, mx1, 1));
        mx1 = fmaxf(mx1, __shfl_xor_sync(0xffffffffu, mx1, 2));

        float newm0 = fmaxf(fmaxf(mrun0, mx0), -1e29f);
        float newm1 = fmaxf(fmaxf(mrun1, mx1), -1e29f);
        float alpha0 = fast_exp2(mrun0 - newm0);
        float alpha1 = fast_exp2(mrun1 - newm1);
        mrun0 = newm0; mrun1 = newm1;

        float rs0 = 0.0f, rs1 = 0.0f;
        #pragma unroll
        for (int nt = 0; nt < 8; nt++) {
            sacc[nt][0] = fast_exp2(sacc[nt][0] - newm0);
            sacc[nt][1] = fast_exp2(sacc[nt][1] - newm0);
            sacc[nt][2] = fast_exp2(sacc[nt][2] - newm1);
            sacc[nt][3] = fast_exp2(sacc[nt][3] - newm1);
            rs0 += sacc[nt][0] + sacc[nt][1];
            rs1 += sacc[nt][2] + sacc[nt][3];
        }
        rs0 += __shfl_xor_sync(0xffffffffu, rs0, 1);
        rs0 += __shfl_xor_sync(0xffffffffu, rs0, 2);
        rs1 += __shfl_xor_sync(0xffffffffu, rs1, 1);
        rs1 += __shfl_xor_sync(0xffffffffu, rs1, 2);
        lrun0 = lrun0 * alpha0 + rs0;
        lrun1 = lrun1 * alpha1 + rs1;

        // ---- P acc fragments -> A fragments, in registers ----
        uint32_t pa[4][4];
        #pragma unroll
        for (int c = 0; c < 4; c++) {
            pa[c][0] = packh2(sacc[2 * c][0],     sacc[2 * c][1]);
            pa[c][1] = packh2(sacc[2 * c][2],     sacc[2 * c][3]);
            pa[c][2] = packh2(sacc[2 * c + 1][0], sacc[2 * c + 1][1]);
            pa[c][3] = packh2(sacc[2 * c + 1][2], sacc[2 * c + 1][3]);
        }

        CP_WAIT(0);           // V(cur) done
        __syncthreads();      // all warps done reading K
        if (k0 + 64 <= q0)    // K(next) load overlaps PV
            flash_load_tile(smb + FS_K, Ks, k0 + 64, kvh * CD, CKD, tid);

        // ---- rescale O, O += P V ----
        #pragma unroll
        for (int nt = 0; nt < 16; nt++) {
            oacc[nt][0] *= alpha0; oacc[nt][1] *= alpha0;
            oacc[nt][2] *= alpha1; oacc[nt][3] *= alpha1;
        }
        #pragma unroll
        for (int c = 0; c < 4; c++) {
            #pragma unroll
            for (int j = 0; j < 8; j++) {
                uint32_t c16v = (uint32_t)(wd * 16 + j * 2 + hi);
                uint32_t offV = (uint32_t)(c * 16 + row_in) * 512 +
                                ((c16v ^ swkey) << 4);
                uint32_t h0, h1, h2, h3;
                LDSM_X4_T(h0, h1, h2, h3, smb + FS_V + offV);
                uint32_t b0[2] = {h0, h1}, b1[2] = {h2, h3};
                mma16816(oacc[2 * j],     pa[c], b0);
                mma16816(oacc[2 * j + 1], pa[c], b1);
            }
        }
        __syncthreads();      // all warps done reading V
        if (k0 + 64 <= q0)    // V(next) load overlaps next QK
            flash_load_tile(smb + FS_V, Vs, k0 + 64, kvh * CD, CKD, tid);
    }

    // ---- epilogue: fp16 AO ----
    float inv0 = 1.0f / lrun0, inv1 = 1.0f / lrun1;
    int row0 = q0 + wq * 16 + qr;
    #pragma unroll
    for (int nt = 0; nt < 16; nt++) {
        int col = h * CD + wd * 128 + nt * 8 + qc;
        *(__half2*)&AO[(size_t)row0 * CQD + col] =
            __floats2half2_rn(oacc[nt][0] * inv0, oacc[nt][1] * inv0);
        *(__half2*)&AO[(size_t)(row0 + 8) * CQD + col] =
            __floats2half2_rn(oacc[nt][2] * inv1, oacc[nt][3] * inv1);
    }
}

// ---------------------------------------------------------------------------
extern "C" void kernel_launch(void* const* d_in, const int* in_sizes, int n_in,
                              void* d_out, int out_size) {
    const float* x  = (const float*)d_in[0];
    const int*   ps = (const int*)  d_in[1];
    const float* Wq = (const float*)d_in[2];
    const float* Wk = (const float*)d_in[3];
    const float* Wv = (const float*)d_in[4];
    const float* Wo = (const float*)d_in[5];
    const float* qw = (const float*)d_in[6];
    const float* kw = (const float*)d_in[7];
    float* out = (float*)d_out;
    (void)in_sizes; (void)n_in; (void)out_size;

    float *Qp, *Kp;
    cudaGetSymbolAddress((void**)&Qp, g_Q);
    cudaGetSymbolAddress((void**)&Kp, g_K);
    __half *xs, *Wqkv, *Wot, *Qss, *Kss, *Vss, *AOs;
    cudaGetSymbolAddress((void**)&xs,   g_xs);
    cudaGetSymbolAddress((void**)&Wqkv, g_Wqkv);
    cudaGetSymbolAddress((void**)&Wot,  g_Wot);
    cudaGetSymbolAddress((void**)&Qss,  g_Qs);
    cudaGetSymbolAddress((void**)&Kss,  g_Ks);
    cudaGetSymbolAddress((void**)&Vss,  g_Vs);
    cudaGetSymbolAddress((void**)&AOs,  g_AOs);

    cudaFuncSetAttribute(gemm_qkv_kernel,
                         cudaFuncAttributeMaxDynamicSharedMemorySize, GEMM_SMEM);
    cudaFuncSetAttribute(gemm_o_kernel,
                         cudaFuncAttributeMaxDynamicSharedMemorySize, GEMM_SMEM);
    cudaFuncSetAttribute(flash_hmma_kernel,
                         cudaFuncAttributeMaxDynamicSharedMemorySize, FLASH_SMEM);

    // launch order: ncu (-s 5 -c 1) captures launch #6 = flash
    init_invf_kernel<<<1, 128>>>();                                      // 1
    convert_f16_kernel<<<512, 256>>>(x, xs, CT * CHID);                  // 2
    transpose_all_kernel<<<dim3(80, 80, 4), 256>>>(                      // 3
        Wq, Wk, Wv, Wo, Wqkv, Wot);

    gemm_qkv_kernel<<<dim3((CQD + 2 * CKD) / 128, CT / 128), 256,        // 4
                      GEMM_SMEM>>>(xs, Wqkv, Qp, Kp, Vss);

    norm_rope_kernel<<<dim3(CT, CH + CKH), 128>>>(Qp, Kp, ps, qw, kw,    // 5
                                                  Qss, Kss);

    flash_hmma_kernel<<<dim3(CT / 64, CH), 256, FLASH_SMEM>>>(           // 6 <- ncu
        Qss, Kss, Vss, AOs);

    gemm_o_kernel<<<dim3(CHID / 128, CT / 128), 256, GEMM_SMEM>>>(       // 7
        AOs, Wot, out);
}

// round 11
// speedup vs baseline: 7.3797x; 1.0069x over previous
#include <cuda_runtime.h>
#include <cuda_fp16.h>
#include <math.h>
#include <stdint.h>

#define CT   4096
#define CHID 2560
#define CH   8
#define CKH  4
#define CD   256
#define CQD  2048   // H*D
#define CKD  1024   // KH*D
#define CWIN 1024
#define LOG2E 1.4426950408889634f
#define QSCALE (0.0625f * LOG2E)

// ---------------- scratch (static device globals) ----------------
__device__ float g_Q[CT * CQD];          // f32 Q proj (pre-norm)
__device__ float g_K[CT * CKD];          // f32 K proj (pre-norm)
__device__ float g_invf[128];

__device__ __half g_xs[CT * CHID];                  // x fp16
__device__ __half g_Wqkv[(CQD + 2 * CKD) * CHID];   // [4096, 2560] concat [N,K]
__device__ __half g_Wot[CHID * CQD];                // Wo^T [2560, 2048]

__device__ __half g_Qs[CT * CQD];        // flash operands fp16
__device__ __half g_Ks[CT * CKD];
__device__ __half g_Vs[CT * CKD];
__device__ __half g_AOs[CT * CQD];       // attention output fp16

extern __shared__ char dyn_smem[];

// ---------------- PTX helpers (compute_103-safe) ----------------
__device__ __forceinline__ uint32_t smem_u32(const void* p) {
    uint32_t a;
    asm("{ .reg .u64 t; cvta.to.shared.u64 t, %1; cvt.u32.u64 %0, t; }"
        : "=r"(a) : "l"(p));
    return a;
}
__device__ __forceinline__ void cp_async16(uint32_t s, const void* g) {
    asm volatile("cp.async.cg.shared.global [%0], [%1], 16;" :: "r"(s), "l"(g));
}
#define CP_COMMIT()  asm volatile("cp.async.commit_group;" ::: "memory")
#define CP_WAIT(n)   asm volatile("cp.async.wait_group %0;" :: "n"(n) : "memory")

#define LDSM_X4(r0, r1, r2, r3, addr) \
    asm volatile("ldmatrix.sync.aligned.m8n8.x4.shared.b16 {%0,%1,%2,%3}, [%4];" \
                 : "=r"(r0), "=r"(r1), "=r"(r2), "=r"(r3) : "r"(addr))
#define LDSM_X4_T(r0, r1, r2, r3, addr) \
    asm volatile("ldmatrix.sync.aligned.m8n8.x4.trans.shared.b16 {%0,%1,%2,%3}, [%4];" \
                 : "=r"(r0), "=r"(r1), "=r"(r2), "=r"(r3) : "r"(addr))

__device__ __forceinline__ void mma16816(float* d, const uint32_t* a,
                                         const uint32_t* b) {
    asm volatile(
        "mma.sync.aligned.m16n8k16.row.col.f32.f16.f16.f32 "
        "{%0,%1,%2,%3}, {%4,%5,%6,%7}, {%8,%9}, {%0,%1,%2,%3};"
        : "+f"(d[0]), "+f"(d[1]), "+f"(d[2]), "+f"(d[3])
        : "r"(a[0]), "r"(a[1]), "r"(a[2]), "r"(a[3]), "r"(b[0]), "r"(b[1]));
}
__device__ __forceinline__ float fast_exp2(float x) {
    float y;
    asm("ex2.approx.ftz.f32 %0, %1;" : "=f"(y) : "f"(x));
    return y;
}
__device__ __forceinline__ uint32_t packh2(float a, float b) {
    __half2 t = __floats2half2_rn(a, b);
    return *(uint32_t*)&t;
}

// ---------------- small prep kernels ----------------
__global__ void init_invf_kernel() {
    int d = threadIdx.x;
    if (d < 128) g_invf[d] = (float)pow(10000.0, -((double)d) / 128.0);
}

__global__ __launch_bounds__(256) void convert_f16_kernel(
    const float* __restrict__ x, __half* __restrict__ y, int n)
{
    int i = blockIdx.x * 256 + threadIdx.x;
    int stride = gridDim.x * 256;
    for (; i < n; i += stride) y[i] = __float2half_rn(x[i]);
}

// All weight transposes in ONE launch (z selects matrix). W[K,N] -> T[N,K] fp16.
__global__ __launch_bounds__(256) void transpose_all_kernel(
    const float* __restrict__ Wq, const float* __restrict__ Wk,
    const float* __restrict__ Wv, const float* __restrict__ Wo,
    __half* __restrict__ Wqkv, __half* __restrict__ Wot)
{
    const float* W;
    __half* Th;
    int K, N;
    switch (blockIdx.z) {
        case 0: W = Wq; Th = Wqkv;                              K = CHID; N = CQD; break;
        case 1: W = Wk; Th = Wqkv + (size_t)CQD * CHID;         K = CHID; N = CKD; break;
        case 2: W = Wv; Th = Wqkv + (size_t)(CQD + CKD) * CHID; K = CHID; N = CKD; break;
        default: W = Wo; Th = Wot;                              K = CQD;  N = CHID; break;
    }
    int n0 = blockIdx.x * 32, k0 = blockIdx.y * 32;
    if (n0 >= N || k0 >= K) return;

    __shared__ float t[32][33];
    int tx = threadIdx.x & 31, ty = threadIdx.x >> 5;
    #pragma unroll
    for (int r = 0; r < 4; r++)
        t[ty + 8 * r][tx] = W[(size_t)(k0 + ty + 8 * r) * N + n0 + tx];
    __syncthreads();
    #pragma unroll
    for (int r = 0; r < 4; r++)
        Th[(size_t)(n0 + ty + 8 * r) * K + k0 + tx] =
            __float2half_rn(t[tx][ty + 8 * r]);
}

// ---------------------------------------------------------------------------
// HMMA fp16 GEMM core: 128x128 CTA tile, 8 warps (64x32 warp tile), BK=64,
// 3-stage cp.async pipeline, ONE syncthreads per K-chunk. (unchanged R10)
// ---------------------------------------------------------------------------
#define GSTG 32768
#define GEMM_SMEM (3 * GSTG)

__device__ __forceinline__ void gemm_issue(
    uint32_t st, int tid, size_t aBase, size_t bBase, int k0, int K,
    const __half* __restrict__ A, const __half* __restrict__ B)
{
    #pragma unroll
    for (int it = 0; it < 4; it++) {
        int id  = tid + it * 256;
        int row = id >> 3;
        int c16 = id & 7;
        uint32_t sw = (uint32_t)(row * 128) + ((uint32_t)(c16 ^ (row & 7)) << 4);
        size_t go = (size_t)row * K + k0 + c16 * 8;
        cp_async16(st + sw,         A + aBase + go);
        cp_async16(st + 16384 + sw, B + bBase + go);
    }
    CP_COMMIT();
}

__device__ __forceinline__ void gemm_core(
    uint32_t smb, int tid, int wid, int lane,
    size_t aBase, size_t bBase, int K,
    const __half* __restrict__ A, const __half* __restrict__ B,
    float acc[4][4][4])
{
    const int warp_m = wid >> 2;
    const int warp_n = wid & 3;
    const int NC = K >> 6;
    const int row_in = lane & 15;
    const int hi     = lane >> 4;
    const uint32_t swkey = (uint32_t)(row_in & 7);

    gemm_issue(smb, tid, aBase, bBase, 0, K, A, B);
    if (NC > 1) gemm_issue(smb + GSTG, tid, aBase, bBase, 64, K, A, B);

    for (int c = 0; c < NC; c++) {
        CP_WAIT(1);
        __syncthreads();
        if (c + 2 < NC)
            gemm_issue(smb + ((c + 2) % 3) * GSTG, tid, aBase, bBase,
                       (c + 2) << 6, K, A, B);
        const uint32_t sA = smb + (c % 3) * GSTG;
        const uint32_t sB = sA + 16384;

        #pragma unroll
        for (int ks = 0; ks < 4; ks++) {
            const uint32_t csw = ((uint32_t)(ks * 2 + hi) ^ swkey) << 4;
            uint32_t ah[4][4];
            #pragma unroll
            for (int mt = 0; mt < 4; mt++) {
                uint32_t off = (uint32_t)(warp_m * 64 + mt * 16 + row_in) * 128 + csw;
                LDSM_X4(ah[mt][0], ah[mt][1], ah[mt][2], ah[mt][3], sA + off);
            }
            uint32_t bf[4][2];
            #pragma unroll
            for (int p = 0; p < 2; p++) {
                uint32_t off = (uint32_t)(warp_n * 32 + p * 16 + row_in) * 128 + csw;
                uint32_t r0, r1, r2, r3;
                LDSM_X4(r0, r1, r2, r3, sB + off);
                bf[2 * p][0] = r0; bf[2 * p + 1][0] = r1;
                bf[2 * p][1] = r2; bf[2 * p + 1][1] = r3;
            }
            #pragma unroll
            for (int mt = 0; mt < 4; mt++)
                #pragma unroll
                for (int nt = 0; nt < 4; nt++)
                    mma16816(acc[mt][nt], ah[mt], bf[nt]);
        }
    }
}

// Fused QKV projection: N = 4096 concat (Q 2048 f32 | K 1024 f32 | V 1024 fp16)
__global__ __launch_bounds__(256, 2) void gemm_qkv_kernel(
    const __half* __restrict__ xs, const __half* __restrict__ Wqkv,
    float* __restrict__ Qf, float* __restrict__ Kf, __half* __restrict__ Vh)
{
    const uint32_t smb = smem_u32(dyn_smem);
    const int tid = threadIdx.x, wid = tid >> 5, lane = tid & 31;
    const int m0 = blockIdx.y * 128, n0 = blockIdx.x * 128;

    float acc[4][4][4];
    #pragma unroll
    for (int mt = 0; mt < 4; mt++)
        #pragma unroll
        for (int nt = 0; nt < 4; nt++)
            #pragma unroll
            for (int r = 0; r < 4; r++) acc[mt][nt][r] = 0.0f;

    gemm_core(smb, tid, wid, lane, (size_t)m0 * CHID, (size_t)n0 * CHID,
              CHID, xs, Wqkv, acc);

    float* Cf = nullptr; __half* Chh = nullptr;
    int ld, cb;
    if (n0 < CQD)            { Cf = Qf; ld = CQD; cb = n0; }
    else if (n0 < CQD + CKD) { Cf = Kf; ld = CKD; cb = n0 - CQD; }
    else                     { Chh = Vh; ld = CKD; cb = n0 - CQD - CKD; }

    const int warp_m = wid >> 2, warp_n = wid & 3;
    #pragma unroll
    for (int mt = 0; mt < 4; mt++) {
        int row = m0 + warp_m * 64 + mt * 16 + (lane >> 2);
        #pragma unroll
        for (int nt = 0; nt < 4; nt++) {
            int col = cb + warp_n * 32 + nt * 8 + (lane & 3) * 2;
            if (Chh) {
                *(__half2*)&Chh[(size_t)row * ld + col] =
                    __floats2half2_rn(acc[mt][nt][0], acc[mt][nt][1]);
                *(__half2*)&Chh[(size_t)(row + 8) * ld + col] =
                    __floats2half2_rn(acc[mt][nt][2], acc[mt][nt][3]);
            } else {
                *(float2*)&Cf[(size_t)row * ld + col] =
                    make_float2(acc[mt][nt][0], acc[mt][nt][1]);
                *(float2*)&Cf[(size_t)(row + 8) * ld + col] =
                    make_float2(acc[mt][nt][2], acc[mt][nt][3]);
            }
        }
    }
}

// Output projection: out[T, HID] = AO[T, QD] @ Wot[HID, QD]^T, f32 out
__global__ __launch_bounds__(256, 2) void gemm_o_kernel(
    const __half* __restrict__ AOs, const __half* __restrict__ Wot,
    float* __restrict__ out)
{
    const uint32_t smb = smem_u32(dyn_smem);
    const int tid = threadIdx.x, wid = tid >> 5, lane = tid & 31;
    const int m0 = blockIdx.y * 128, n0 = blockIdx.x * 128;

    float acc[4][4][4];
    #pragma unroll
    for (int mt = 0; mt < 4; mt++)
        #pragma unroll
        for (int nt = 0; nt < 4; nt++)
            #pragma unroll
            for (int r = 0; r < 4; r++) acc[mt][nt][r] = 0.0f;

    gemm_core(smb, tid, wid, lane, (size_t)m0 * CQD, (size_t)n0 * CQD,
              CQD, AOs, Wot, acc);

    const int warp_m = wid >> 2, warp_n = wid & 3;
    #pragma unroll
    for (int mt = 0; mt < 4; mt++) {
        int row = m0 + warp_m * 64 + mt * 16 + (lane >> 2);
        #pragma unroll
        for (int nt = 0; nt < 4; nt++) {
            int col = n0 + warp_n * 32 + nt * 8 + (lane & 3) * 2;
            *(float2*)&out[(size_t)row * CHID + col] =
                make_float2(acc[mt][nt][0], acc[mt][nt][1]);
            *(float2*)&out[(size_t)(row + 8) * CHID + col] =
                make_float2(acc[mt][nt][2], acc[mt][nt][3]);
        }
    }
}

// ---------------------------------------------------------------------------
// Fused RMSNorm + neox RoPE -> fp16. Q pre-scaled by QSCALE (exp2 domain).
// ---------------------------------------------------------------------------
__global__ __launch_bounds__(128) void norm_rope_kernel(
    const float* __restrict__ Qm, const float* __restrict__ Km,
    const int* __restrict__ pos,
    const float* __restrict__ qw, const float* __restrict__ kw,
    __half* __restrict__ Qs, __half* __restrict__ Ks)
{
    int t  = blockIdx.x;
    int hh = blockIdx.y;
    const float* base;
    const float* w;
    bool isQ = hh < CH;
    if (isQ) { base = Qm + (size_t)t * CQD + hh * CD;        w = qw; }
    else     { base = Km + (size_t)t * CKD + (hh - CH) * CD; w = kw; }

    int d = threadIdx.x;
    float x1 = base[d];
    float x2 = base[d + 128];
    float ss = x1 * x1 + x2 * x2;
    #pragma unroll
    for (int off = 16; off > 0; off >>= 1)
        ss += __shfl_xor_sync(0xffffffffu, ss, off);
    __shared__ float wsum[4];
    if ((d & 31) == 0) wsum[d >> 5] = ss;
    __syncthreads();
    float tot = wsum[0] + wsum[1] + wsum[2] + wsum[3];
    float inv = rsqrtf(tot * (1.0f / 256.0f) + 1e-6f);
    float n1 = x1 * inv * (1.0f + w[d]);
    float n2 = x2 * inv * (1.0f + w[d + 128]);

    float f = (float)pos[t] * g_invf[d];
    float c, s;
    sincosf(f, &s, &c);
    float o1 = n1 * c - n2 * s;
    float o2 = n2 * c + n1 * s;

    if (isQ) {
        size_t o = (size_t)t * CQD + hh * CD + d;
        Qs[o]       = __float2half_rn(o1 * QSCALE);
        Qs[o + 128] = __float2half_rn(o2 * QSCALE);
    } else {
        size_t o = (size_t)t * CKD + (hh - CH) * CD + d;
        Ks[o]       = __float2half_rn(o1);
        Ks[o + 128] = __float2half_rn(o2);
    }
}

// ---------------------------------------------------------------------------
// FA2-style HMMA flash attention with GQA head pairing.
// CTA: 64 q rows x 2 query heads (sharing one kv head) x 64 kv tile.
// 512 thr = 16 warps: hh = wid>>3 (head), wq = (wid>>1)&3 (16 q rows),
// wd = wid&1 (128-d half for PV). K/V loaded ONCE per head pair.
// ---------------------------------------------------------------------------
#define FS_Q  0                 // 128 rows (2 heads x 64) x 256 cols fp16 = 64KB
#define FS_K  65536             // 64 x 256 fp16 = 32KB
#define FS_V  98304             // 64 x 256 fp16 = 32KB
#define FLASH_SMEM 131072

__device__ __forceinline__ void flash_load_q(
    uint32_t dst, const __half* __restrict__ Qs, int q0, int kvh, int tid)
{
    #pragma unroll
    for (int it = 0; it < 8; it++) {
        int id  = tid + it * 512;
        int row = id >> 5;          // 0..127
        int c16 = id & 31;
        uint32_t sw = (uint32_t)(row * 512) + ((uint32_t)(c16 ^ (row & 7)) << 4);
        int head = row >> 6;
        int r    = row & 63;
        cp_async16(dst + sw, Qs + (size_t)(q0 + r) * CQD +
                                 (kvh * 2 + head) * CD + c16 * 8);
    }
    CP_COMMIT();
}

__device__ __forceinline__ void flash_load_kv(
    uint32_t dst, const __half* __restrict__ S, int t0, int colbase, int tid)
{
    #pragma unroll
    for (int it = 0; it < 4; it++) {
        int id  = tid + it * 512;
        int row = id >> 5;          // 0..63
        int c16 = id & 31;
        uint32_t sw = (uint32_t)(row * 512) + ((uint32_t)(c16 ^ (row & 7)) << 4);
        cp_async16(dst + sw, S + (size_t)(t0 + row) * CKD + colbase + c16 * 8);
    }
    CP_COMMIT();
}

__global__ __launch_bounds__(512, 1) void flash_hmma_kernel(
    const __half* __restrict__ Qs, const __half* __restrict__ Ks,
    const __half* __restrict__ Vs, __half* __restrict__ AO)
{
    const uint32_t smb = smem_u32(dyn_smem);
    const int tid  = threadIdx.x;
    const int wid  = tid >> 5;
    const int lane = tid & 31;
    const int hh   = wid >> 3;          // head within pair
    const int wq   = (wid >> 1) & 3;    // q-row group
    const int wd   = wid & 1;           // d half
    const int q0   = blockIdx.x * 64;
    const int kvh  = blockIdx.y;
    const int h    = kvh * 2 + hh;

    const int row_in = lane & 15;
    const int hi     = lane >> 4;
    const uint32_t swkey = (uint32_t)(row_in & 7);
    const int qr = lane >> 2;
    const int qc = (lane & 3) * 2;

    float oacc[16][4];
    #pragma unroll
    for (int nt = 0; nt < 16; nt++)
        #pragma unroll
        for (int r = 0; r < 4; r++) oacc[nt][r] = 0.0f;
    float mrun0 = -1e30f, mrun1 = -1e30f, lrun0 = 0.0f, lrun1 = 0.0f;

    int kb_lo = q0 - CWIN;
    if (kb_lo < 0) kb_lo = 0;

    flash_load_q(smb + FS_Q, Qs, q0, kvh, tid);                 // grp 1
    flash_load_kv(smb + FS_K, Ks, kb_lo, kvh * CD, tid);        // grp 2
    flash_load_kv(smb + FS_V, Vs, kb_lo, kvh * CD, tid);        // grp 3

    const uint32_t qbase = smb + FS_Q +
        (uint32_t)(hh * 64 + wq * 16 + row_in) * 512;

    for (int k0 = kb_lo; k0 <= q0; k0 += 64) {
        CP_WAIT(1);           // Q + K(cur) done; V(cur) may pend
        __syncthreads();

        // ---- S = Q K^T over all 64 kv (8 n8 tiles per warp) ----
        float sacc[8][4];
        #pragma unroll
        for (int nt = 0; nt < 8; nt++)
            #pragma unroll
            for (int r = 0; r < 4; r++) sacc[nt][r] = 0.0f;

        #pragma unroll
        for (int ks = 0; ks < 16; ks++) {
            const uint32_t csw = ((uint32_t)(ks * 2 + hi) ^ swkey) << 4;
            uint32_t aQ[4];
            LDSM_X4(aQ[0], aQ[1], aQ[2], aQ[3], qbase + csw);
            #pragma unroll
            for (int p = 0; p < 4; p++) {
                uint32_t r0, r1, r2, r3;
                LDSM_X4(r0, r1, r2, r3,
                        smb + FS_K + (uint32_t)(p * 16 + row_in) * 512 + csw);
                uint32_t b0[2] = {r0, r2}, b1[2] = {r1, r3};
                mma16816(sacc[2 * p],     aQ, b0);
                mma16816(sacc[2 * p + 1], aQ, b1);
            }
        }

        // ---- mask (edge tiles only) ----
        const bool needmask = (k0 + 64 > q0) || (k0 + (CWIN - 64) < q0);
        const int rbase = q0 + wq * 16 + qr;
        if (needmask) {
            #pragma unroll
            for (int nt = 0; nt < 8; nt++) {
                int kg = k0 + nt * 8 + qc;
                #pragma unroll
                for (int e = 0; e < 4; e++) {
                    int qg = rbase + (e >> 1) * 8;
                    int kk = kg + (e & 1);
                    unsigned dd = (unsigned)(qg - kk);
                    if (dd >= (unsigned)CWIN) sacc[nt][e] = -1e30f;
                }
            }
        }

        // ---- warp-local online softmax (quad shfl only) ----
        float mx0 = -1e30f, mx1 = -1e30f;
        #pragma unroll
        for (int nt = 0; nt < 8; nt++) {
            mx0 = fmaxf(mx0, fmaxf(sacc[nt][0], sacc[nt][1]));
            mx1 = fmaxf(mx1, fmaxf(sacc[nt][2], sacc[nt][3]));
        }
        mx0 = fmaxf(mx0, __shfl_xor_sync(0xffffffffu, mx0, 1));
        mx0 = fmaxf(mx0, __shfl_xor_sync(0xffffffffu, mx0, 2));
        mx1 = fmaxf(mx1, __shfl_xor_sync(0xffffffffu, mx1, 1));
        mx1 = fmaxf(mx1, __shfl_xor_sync(0xffffffffu, mx1, 2));

        float newm0 = fmaxf(fmaxf(mrun0, mx0), -1e29f);
        float newm1 = fmaxf(fmaxf(mrun1, mx1), -1e29f);
        float alpha0 = fast_exp2(mrun0 - newm0);
        float alpha1 = fast_exp2(mrun1 - newm1);
        mrun0 = newm0; mrun1 = newm1;

        float rs0 = 0.0f, rs1 = 0.0f;
        #pragma unroll
        for (int nt = 0; nt < 8; nt++) {
            sacc[nt][0] = fast_exp2(sacc[nt][0] - newm0);
            sacc[nt][1] = fast_exp2(sacc[nt][1] - newm0);
            sacc[nt][2] = fast_exp2(sacc[nt][2] - newm1);
            sacc[nt][3] = fast_exp2(sacc[nt][3] - newm1);
            rs0 += sacc[nt][0] + sacc[nt][1];
            rs1 += sacc[nt][2] + sacc[nt][3];
        }
        rs0 += __shfl_xor_sync(0xffffffffu, rs0, 1);
        rs0 += __shfl_xor_sync(0xffffffffu, rs0, 2);
        rs1 += __shfl_xor_sync(0xffffffffu, rs1, 1);
        rs1 += __shfl_xor_sync(0xffffffffu, rs1, 2);
        lrun0 = lrun0 * alpha0 + rs0;
        lrun1 = lrun1 * alpha1 + rs1;

        // ---- P acc fragments -> A fragments, in registers ----
        uint32_t pa[4][4];
        #pragma unroll
        for (int c = 0; c < 4; c++) {
            pa[c][0] = packh2(sacc[2 * c][0],     sacc[2 * c][1]);
            pa[c][1] = packh2(sacc[2 * c][2],     sacc[2 * c][3]);
            pa[c][2] = packh2(sacc[2 * c + 1][0], sacc[2 * c + 1][1]);
            pa[c][3] = packh2(sacc[2 * c + 1][2], sacc[2 * c + 1][3]);
        }

        CP_WAIT(0);           // V(cur) done
        __syncthreads();      // all warps done reading K
        if (k0 + 64 <= q0)    // K(next) load overlaps PV
            flash_load_kv(smb + FS_K, Ks, k0 + 64, kvh * CD, tid);

        // ---- rescale O, O += P V ----
        #pragma unroll
        for (int nt = 0; nt < 16; nt++) {
            oacc[nt][0] *= alpha0; oacc[nt][1] *= alpha0;
            oacc[nt][2] *= alpha1; oacc[nt][3] *= alpha1;
        }
        #pragma unroll
        for (int c = 0; c < 4; c++) {
            #pragma unroll
            for (int j = 0; j < 8; j++) {
                uint32_t c16v = (uint32_t)(wd * 16 + j * 2 + hi);
                uint32_t offV = (uint32_t)(c * 16 + row_in) * 512 +
                                ((c16v ^ swkey) << 4);
                uint32_t h0, h1, h2, h3;
                LDSM_X4_T(h0, h1, h2, h3, smb + FS_V + offV);
                uint32_t b0[2] = {h0, h1}, b1[2] = {h2, h3};
                mma16816(oacc[2 * j],     pa[c], b0);
                mma16816(oacc[2 * j + 1], pa[c], b1);
            }
        }
        __syncthreads();      // all warps done reading V
        if (k0 + 64 <= q0)    // V(next) load overlaps next QK
            flash_load_kv(smb + FS_V, Vs, k0 + 64, kvh * CD, tid);
    }

    // ---- epilogue: fp16 AO ----
    float inv0 = 1.0f / lrun0, inv1 = 1.0f / lrun1;
    int row0 = q0 + wq * 16 + qr;
    #pragma unroll
    for (int nt = 0; nt < 16; nt++) {
        int col = h * CD + wd * 128 + nt * 8 + qc;
        *(__half2*)&AO[(size_t)row0 * CQD + col] =
            __floats2half2_rn(oacc[nt][0] * inv0, oacc[nt][1] * inv0);
        *(__half2*)&AO[(size_t)(row0 + 8) * CQD + col] =
            __floats2half2_rn(oacc[nt][2] * inv1, oacc[nt][3] * inv1);
    }
}

// ---------------------------------------------------------------------------
extern "C" void kernel_launch(void* const* d_in, const int* in_sizes, int n_in,
                              void* d_out, int out_size) {
    const float* x  = (const float*)d_in[0];
    const int*   ps = (const int*)  d_in[1];
    const float* Wq = (const float*)d_in[2];
    const float* Wk = (const float*)d_in[3];
    const float* Wv = (const float*)d_in[4];
    const float* Wo = (const float*)d_in[5];
    const float* qw = (const float*)d_in[6];
    const float* kw = (const float*)d_in[7];
    float* out = (float*)d_out;
    (void)in_sizes; (void)n_in; (void)out_size;

    float *Qp, *Kp;
    cudaGetSymbolAddress((void**)&Qp, g_Q);
    cudaGetSymbolAddress((void**)&Kp, g_K);
    __half *xs, *Wqkv, *Wot, *Qss, *Kss, *Vss, *AOs;
    cudaGetSymbolAddress((void**)&xs,   g_xs);
    cudaGetSymbolAddress((void**)&Wqkv, g_Wqkv);
    cudaGetSymbolAddress((void**)&Wot,  g_Wot);
    cudaGetSymbolAddress((void**)&Qss,  g_Qs);
    cudaGetSymbolAddress((void**)&Kss,  g_Ks);
    cudaGetSymbolAddress((void**)&Vss,  g_Vs);
    cudaGetSymbolAddress((void**)&AOs,  g_AOs);

    cudaFuncSetAttribute(gemm_qkv_kernel,
                         cudaFuncAttributeMaxDynamicSharedMemorySize, GEMM_SMEM);
    cudaFuncSetAttribute(gemm_o_kernel,
                         cudaFuncAttributeMaxDynamicSharedMemorySize, GEMM_SMEM);
    cudaFuncSetAttribute(flash_hmma_kernel,
                         cudaFuncAttributeMaxDynamicSharedMemorySize, FLASH_SMEM);

    // launch order: ncu (-s 5 -c 1) captures launch #6 = flash
    init_invf_kernel<<<1, 128>>>();                                      // 1
    convert_f16_kernel<<<512, 256>>>(x, xs, CT * CHID);                  // 2
    transpose_all_kernel<<<dim3(80, 80, 4), 256>>>(                      // 3
        Wq, Wk, Wv, Wo, Wqkv, Wot);

    gemm_qkv_kernel<<<dim3((CQD + 2 * CKD) / 128, CT / 128), 256,        // 4
                      GEMM_SMEM>>>(xs, Wqkv, Qp, Kp, Vss);

    norm_rope_kernel<<<dim3(CT, CH + CKH), 128>>>(Qp, Kp, ps, qw, kw,    // 5
                                                  Qss, Kss);

    flash_hmma_kernel<<<dim3(CT / 64, CKH), 512, FLASH_SMEM>>>(          // 6 <- ncu
        Qss, Kss, Vss, AOs);

    gemm_o_kernel<<<dim3(CHID / 128, CT / 128), 256, GEMM_SMEM>>>(       // 7
        AOs, Wot, out);
}

// round 13
// speedup vs baseline: 7.5707x; 1.0259x over previous
#include <cuda_runtime.h>
#include <cuda_fp16.h>
#include <math.h>
#include <stdint.h>

#define CT   4096
#define CHID 2560
#define CH   8
#define CKH  4
#define CD   256
#define CQD  2048   // H*D
#define CKD  1024   // KH*D
#define CWIN 1024
#define LOG2E 1.4426950408889634f
#define QSCALE (0.0625f * LOG2E)

// ---------------- scratch (static device globals) ----------------
__device__ float g_Q[CT * CQD];          // f32 Q proj (pre-norm)
__device__ float g_K[CT * CKD];          // f32 K proj (pre-norm)
__device__ float g_invf[128];

__device__ __half g_xs[CT * CHID];                  // x fp16
__device__ __half g_Wqkv[(CQD + 2 * CKD) * CHID];   // [4096, 2560] concat [N,K]
__device__ __half g_Wot[CHID * CQD];                // Wo^T [2560, 2048]

__device__ __half g_Qs[CT * CQD];        // flash operands fp16
__device__ __half g_Ks[CT * CKD];
__device__ __half g_Vs[CT * CKD];
__device__ __half g_AOs[CT * CQD];       // attention output fp16

extern __shared__ char dyn_smem[];

// ---------------- PTX helpers (compute_103-safe) ----------------
__device__ __forceinline__ uint32_t smem_u32(const void* p) {
    uint32_t a;
    asm("{ .reg .u64 t; cvta.to.shared.u64 t, %1; cvt.u32.u64 %0, t; }"
        : "=r"(a) : "l"(p));
    return a;
}
__device__ __forceinline__ void cp_async16(uint32_t s, const void* g) {
    asm volatile("cp.async.cg.shared.global [%0], [%1], 16;" :: "r"(s), "l"(g));
}
#define CP_COMMIT()  asm volatile("cp.async.commit_group;" ::: "memory")
#define CP_WAIT(n)   asm volatile("cp.async.wait_group %0;" :: "n"(n) : "memory")

#define LDSM_X4(r0, r1, r2, r3, addr) \
    asm volatile("ldmatrix.sync.aligned.m8n8.x4.shared.b16 {%0,%1,%2,%3}, [%4];" \
                 : "=r"(r0), "=r"(r1), "=r"(r2), "=r"(r3) : "r"(addr))
#define LDSM_X4_T(r0, r1, r2, r3, addr) \
    asm volatile("ldmatrix.sync.aligned.m8n8.x4.trans.shared.b16 {%0,%1,%2,%3}, [%4];" \
                 : "=r"(r0), "=r"(r1), "=r"(r2), "=r"(r3) : "r"(addr))

__device__ __forceinline__ void mma16816(float* d, const uint32_t* a,
                                         const uint32_t* b) {
    asm volatile(
        "mma.sync.aligned.m16n8k16.row.col.f32.f16.f16.f32 "
        "{%0,%1,%2,%3}, {%4,%5,%6,%7}, {%8,%9}, {%0,%1,%2,%3};"
        : "+f"(d[0]), "+f"(d[1]), "+f"(d[2]), "+f"(d[3])
        : "r"(a[0]), "r"(a[1]), "r"(a[2]), "r"(a[3]), "r"(b[0]), "r"(b[1]));
}
__device__ __forceinline__ float fast_exp2(float x) {
    float y;
    asm("ex2.approx.ftz.f32 %0, %1;" : "=f"(y) : "f"(x));
    return y;
}
__device__ __forceinline__ uint32_t packh2(float a, float b) {
    __half2 t = __floats2half2_rn(a, b);
    return *(uint32_t*)&t;
}

// ---------------- small prep kernels ----------------
__global__ void init_invf_kernel() {
    int d = threadIdx.x;
    if (d < 128) g_invf[d] = (float)pow(10000.0, -((double)d) / 128.0);
}

__global__ __launch_bounds__(256) void convert_f16_kernel(
    const float* __restrict__ x, __half* __restrict__ y, int n)
{
    int i = blockIdx.x * 256 + threadIdx.x;
    int stride = gridDim.x * 256;
    for (; i < n; i += stride) y[i] = __float2half_rn(x[i]);
}

// All weight transposes in ONE launch (z selects matrix). W[K,N] -> T[N,K] fp16.
__global__ __launch_bounds__(256) void transpose_all_kernel(
    const float* __restrict__ Wq, const float* __restrict__ Wk,
    const float* __restrict__ Wv, const float* __restrict__ Wo,
    __half* __restrict__ Wqkv, __half* __restrict__ Wot)
{
    const float* W;
    __half* Th;
    int K, N;
    switch (blockIdx.z) {
        case 0: W = Wq; Th = Wqkv;                              K = CHID; N = CQD; break;
        case 1: W = Wk; Th = Wqkv + (size_t)CQD * CHID;         K = CHID; N = CKD; break;
        case 2: W = Wv; Th = Wqkv + (size_t)(CQD + CKD) * CHID; K = CHID; N = CKD; break;
        default: W = Wo; Th = Wot;                              K = CQD;  N = CHID; break;
    }
    int n0 = blockIdx.x * 32, k0 = blockIdx.y * 32;
    if (n0 >= N || k0 >= K) return;

    __shared__ float t[32][33];
    int tx = threadIdx.x & 31, ty = threadIdx.x >> 5;
    #pragma unroll
    for (int r = 0; r < 4; r++)
        t[ty + 8 * r][tx] = W[(size_t)(k0 + ty + 8 * r) * N + n0 + tx];
    __syncthreads();
    #pragma unroll
    for (int r = 0; r < 4; r++)
        Th[(size_t)(n0 + ty + 8 * r) * K + k0 + tx] =
            __float2half_rn(t[tx][ty + 8 * r]);
}

// ---------------------------------------------------------------------------
// HMMA fp16 GEMM core: 128x128 CTA tile, 8 warps (64x32 warp tile), BK=64,
// 3-stage cp.async pipeline, ONE syncthreads per K-chunk. (unchanged)
// ---------------------------------------------------------------------------
#define GSTG 32768
#define GEMM_SMEM (3 * GSTG)

__device__ __forceinline__ void gemm_issue(
    uint32_t st, int tid, size_t aBase, size_t bBase, int k0, int K,
    const __half* __restrict__ A, const __half* __restrict__ B)
{
    #pragma unroll
    for (int it = 0; it < 4; it++) {
        int id  = tid + it * 256;
        int row = id >> 3;
        int c16 = id & 7;
        uint32_t sw = (uint32_t)(row * 128) + ((uint32_t)(c16 ^ (row & 7)) << 4);
        size_t go = (size_t)row * K + k0 + c16 * 8;
        cp_async16(st + sw,         A + aBase + go);
        cp_async16(st + 16384 + sw, B + bBase + go);
    }
    CP_COMMIT();
}

__device__ __forceinline__ void gemm_core(
    uint32_t smb, int tid, int wid, int lane,
    size_t aBase, size_t bBase, int K,
    const __half* __restrict__ A, const __half* __restrict__ B,
    float acc[4][4][4])
{
    const int warp_m = wid >> 2;
    const int warp_n = wid & 3;
    const int NC = K >> 6;
    const int row_in = lane & 15;
    const int hi     = lane >> 4;
    const uint32_t swkey = (uint32_t)(row_in & 7);

    gemm_issue(smb, tid, aBase, bBase, 0, K, A, B);
    if (NC > 1) gemm_issue(smb + GSTG, tid, aBase, bBase, 64, K, A, B);

    for (int c = 0; c < NC; c++) {
        CP_WAIT(1);
        __syncthreads();
        if (c + 2 < NC)
            gemm_issue(smb + ((c + 2) % 3) * GSTG, tid, aBase, bBase,
                       (c + 2) << 6, K, A, B);
        const uint32_t sA = smb + (c % 3) * GSTG;
        const uint32_t sB = sA + 16384;

        #pragma unroll
        for (int ks = 0; ks < 4; ks++) {
            const uint32_t csw = ((uint32_t)(ks * 2 + hi) ^ swkey) << 4;
            uint32_t ah[4][4];
            #pragma unroll
            for (int mt = 0; mt < 4; mt++) {
                uint32_t off = (uint32_t)(warp_m * 64 + mt * 16 + row_in) * 128 + csw;
                LDSM_X4(ah[mt][0], ah[mt][1], ah[mt][2], ah[mt][3], sA + off);
            }
            uint32_t bf[4][2];
            #pragma unroll
            for (int p = 0; p < 2; p++) {
                uint32_t off = (uint32_t)(warp_n * 32 + p * 16 + row_in) * 128 + csw;
                uint32_t r0, r1, r2, r3;
                LDSM_X4(r0, r1, r2, r3, sB + off);
                bf[2 * p][0] = r0; bf[2 * p + 1][0] = r1;
                bf[2 * p][1] = r2; bf[2 * p + 1][1] = r3;
            }
            #pragma unroll
            for (int mt = 0; mt < 4; mt++)
                #pragma unroll
                for (int nt = 0; nt < 4; nt++)
                    mma16816(acc[mt][nt], ah[mt], bf[nt]);
        }
    }
}

// Fused QKV projection: N = 4096 concat (Q 2048 f32 | K 1024 f32 | V 1024 fp16)
__global__ __launch_bounds__(256, 2) void gemm_qkv_kernel(
    const __half* __restrict__ xs, const __half* __restrict__ Wqkv,
    float* __restrict__ Qf, float* __restrict__ Kf, __half* __restrict__ Vh)
{
    const uint32_t smb = smem_u32(dyn_smem);
    const int tid = threadIdx.x, wid = tid >> 5, lane = tid & 31;
    const int m0 = blockIdx.y * 128, n0 = blockIdx.x * 128;

    float acc[4][4][4];
    #pragma unroll
    for (int mt = 0; mt < 4; mt++)
        #pragma unroll
        for (int nt = 0; nt < 4; nt++)
            #pragma unroll
            for (int r = 0; r < 4; r++) acc[mt][nt][r] = 0.0f;

    gemm_core(smb, tid, wid, lane, (size_t)m0 * CHID, (size_t)n0 * CHID,
              CHID, xs, Wqkv, acc);

    float* Cf = nullptr; __half* Chh = nullptr;
    int ld, cb;
    if (n0 < CQD)            { Cf = Qf; ld = CQD; cb = n0; }
    else if (n0 < CQD + CKD) { Cf = Kf; ld = CKD; cb = n0 - CQD; }
    else                     { Chh = Vh; ld = CKD; cb = n0 - CQD - CKD; }

    const int warp_m = wid >> 2, warp_n = wid & 3;
    #pragma unroll
    for (int mt = 0; mt < 4; mt++) {
        int row = m0 + warp_m * 64 + mt * 16 + (lane >> 2);
        #pragma unroll
        for (int nt = 0; nt < 4; nt++) {
            int col = cb + warp_n * 32 + nt * 8 + (lane & 3) * 2;
            if (Chh) {
                *(__half2*)&Chh[(size_t)row * ld + col] =
                    __floats2half2_rn(acc[mt][nt][0], acc[mt][nt][1]);
                *(__half2*)&Chh[(size_t)(row + 8) * ld + col] =
                    __floats2half2_rn(acc[mt][nt][2], acc[mt][nt][3]);
            } else {
                *(float2*)&Cf[(size_t)row * ld + col] =
                    make_float2(acc[mt][nt][0], acc[mt][nt][1]);
                *(float2*)&Cf[(size_t)(row + 8) * ld + col] =
                    make_float2(acc[mt][nt][2], acc[mt][nt][3]);
            }
        }
    }
}

// Output projection: out[T, HID] = AO[T, QD] @ Wot[HID, QD]^T, f32 out
__global__ __launch_bounds__(256, 2) void gemm_o_kernel(
    const __half* __restrict__ AOs, const __half* __restrict__ Wot,
    float* __restrict__ out)
{
    const uint32_t smb = smem_u32(dyn_smem);
    const int tid = threadIdx.x, wid = tid >> 5, lane = tid & 31;
    const int m0 = blockIdx.y * 128, n0 = blockIdx.x * 128;

    float acc[4][4][4];
    #pragma unroll
    for (int mt = 0; mt < 4; mt++)
        #pragma unroll
        for (int nt = 0; nt < 4; nt++)
            #pragma unroll
            for (int r = 0; r < 4; r++) acc[mt][nt][r] = 0.0f;

    gemm_core(smb, tid, wid, lane, (size_t)m0 * CQD, (size_t)n0 * CQD,
              CQD, AOs, Wot, acc);

    const int warp_m = wid >> 2, warp_n = wid & 3;
    #pragma unroll
    for (int mt = 0; mt < 4; mt++) {
        int row = m0 + warp_m * 64 + mt * 16 + (lane >> 2);
        #pragma unroll
        for (int nt = 0; nt < 4; nt++) {
            int col = n0 + warp_n * 32 + nt * 8 + (lane & 3) * 2;
            *(float2*)&out[(size_t)row * CHID + col] =
                make_float2(acc[mt][nt][0], acc[mt][nt][1]);
            *(float2*)&out[(size_t)(row + 8) * CHID + col] =
                make_float2(acc[mt][nt][2], acc[mt][nt][3]);
        }
    }
}

// ---------------------------------------------------------------------------
// Fused RMSNorm + neox RoPE -> fp16. Q pre-scaled by QSCALE (exp2 domain).
// ---------------------------------------------------------------------------
__global__ __launch_bounds__(128) void norm_rope_kernel(
    const float* __restrict__ Qm, const float* __restrict__ Km,
    const int* __restrict__ pos,
    const float* __restrict__ qw, const float* __restrict__ kw,
    __half* __restrict__ Qs, __half* __restrict__ Ks)
{
    int t  = blockIdx.x;
    int hh = blockIdx.y;
    const float* base;
    const float* w;
    bool isQ = hh < CH;
    if (isQ) { base = Qm + (size_t)t * CQD + hh * CD;        w = qw; }
    else     { base = Km + (size_t)t * CKD + (hh - CH) * CD; w = kw; }

    int d = threadIdx.x;
    float x1 = base[d];
    float x2 = base[d + 128];
    float ss = x1 * x1 + x2 * x2;
    #pragma unroll
    for (int off = 16; off > 0; off >>= 1)
        ss += __shfl_xor_sync(0xffffffffu, ss, off);
    __shared__ float wsum[4];
    if ((d & 31) == 0) wsum[d >> 5] = ss;
    __syncthreads();
    float tot = wsum[0] + wsum[1] + wsum[2] + wsum[3];
    float inv = rsqrtf(tot * (1.0f / 256.0f) + 1e-6f);
    float n1 = x1 * inv * (1.0f + w[d]);
    float n2 = x2 * inv * (1.0f + w[d + 128]);

    float f = (float)pos[t] * g_invf[d];
    float c, s;
    sincosf(f, &s, &c);
    float o1 = n1 * c - n2 * s;
    float o2 = n2 * c + n1 * s;

    if (isQ) {
        size_t o = (size_t)t * CQD + hh * CD + d;
        Qs[o]       = __float2half_rn(o1 * QSCALE);
        Qs[o + 128] = __float2half_rn(o2 * QSCALE);
    } else {
        size_t o = (size_t)t * CKD + (hh - CH) * CD + d;
        Ks[o]       = __float2half_rn(o1);
        Ks[o + 128] = __float2half_rn(o2);
    }
}

// ---------------------------------------------------------------------------
// FA2-style HMMA flash attention, GQA head pairing + DOUBLE-BUFFERED K/V.
// CTA: 64 q rows x 2 query heads x 64 kv tile; 512 thr = 16 warps.
// ONE syncthreads per tile: loads for tile c+1 go to buffer (c+1)&1 right
// after the sync, overlapping the whole tile-c compute; the next sync also
// guards buffer reuse.
// ---------------------------------------------------------------------------
#define FS_Q   0                 // 128 rows x 512 B = 64 KB
#define FS_KV0 65536             // K at +0 (32 KB), V at +32768 (32 KB)
#define FS_KV1 131072
#define FLASH_SMEM 196608        // 192 KB

__device__ __forceinline__ void flash_load_q(
    uint32_t dst, const __half* __restrict__ Qs, int q0, int kvh, int tid)
{
    #pragma unroll
    for (int it = 0; it < 8; it++) {
        int id  = tid + it * 512;
        int row = id >> 5;          // 0..127
        int c16 = id & 31;
        uint32_t sw = (uint32_t)(row * 512) + ((uint32_t)(c16 ^ (row & 7)) << 4);
        int head = row >> 6;
        int r    = row & 63;
        cp_async16(dst + sw, Qs + (size_t)(q0 + r) * CQD +
                                 (kvh * 2 + head) * CD + c16 * 8);
    }
    CP_COMMIT();
}

// loads K tile and V tile for one kv block into one buffer (single commit)
__device__ __forceinline__ void flash_load_kv(
    uint32_t buf, const __half* __restrict__ Ks, const __half* __restrict__ Vs,
    int t0, int colbase, int tid)
{
    #pragma unroll
    for (int it = 0; it < 4; it++) {
        int id  = tid + it * 512;
        int row = id >> 5;          // 0..63
        int c16 = id & 31;
        uint32_t sw = (uint32_t)(row * 512) + ((uint32_t)(c16 ^ (row & 7)) << 4);
        size_t go = (size_t)(t0 + row) * CKD + colbase + c16 * 8;
        cp_async16(buf + sw,         Ks + go);
        cp_async16(buf + 32768 + sw, Vs + go);
    }
    CP_COMMIT();
}

__global__ __launch_bounds__(512, 1) void flash_hmma_kernel(
    const __half* __restrict__ Qs, const __half* __restrict__ Ks,
    const __half* __restrict__ Vs, __half* __restrict__ AO)
{
    const uint32_t smb = smem_u32(dyn_smem);
    const int tid  = threadIdx.x;
    const int wid  = tid >> 5;
    const int lane = tid & 31;
    const int hh   = wid >> 3;          // head within pair
    const int wq   = (wid >> 1) & 3;    // q-row group
    const int wd   = wid & 1;           // d half
    const int q0   = blockIdx.x * 64;
    const int kvh  = blockIdx.y;
    const int h    = kvh * 2 + hh;

    const int row_in = lane & 15;
    const int hi     = lane >> 4;
    const uint32_t swkey = (uint32_t)(row_in & 7);
    const int qr = lane >> 2;
    const int qc = (lane & 3) * 2;

    float oacc[16][4];
    #pragma unroll
    for (int nt = 0; nt < 16; nt++)
        #pragma unroll
        for (int r = 0; r < 4; r++) oacc[nt][r] = 0.0f;
    float mrun0 = -1e30f, mrun1 = -1e30f, lrun0 = 0.0f, lrun1 = 0.0f;

    int kb_lo = q0 - CWIN;
    if (kb_lo < 0) kb_lo = 0;

    flash_load_q(smb + FS_Q, Qs, q0, kvh, tid);
    flash_load_kv(smb + FS_KV0, Ks, Vs, kb_lo, kvh * CD, tid);

    const uint32_t qbase = smb + FS_Q +
        (uint32_t)(hh * 64 + wq * 16 + row_in) * 512;

    int bufsel = 0;
    for (int k0 = kb_lo; k0 <= q0; k0 += 64, bufsel ^= 1) {
        CP_WAIT(0);           // Q + K/V(cur) resident
        __syncthreads();      // all warps past previous tile's reads

        // kick off next tile's K/V into the other buffer — overlaps ALL of
        // this tile's compute
        if (k0 + 64 <= q0)
            flash_load_kv(smb + (bufsel ? FS_KV0 : FS_KV1), Ks, Vs,
                          k0 + 64, kvh * CD, tid);

        const uint32_t kvb = smb + (bufsel ? FS_KV1 : FS_KV0);

        // ---- S = Q K^T over all 64 kv (8 n8 tiles per warp) ----
        float sacc[8][4];
        #pragma unroll
        for (int nt = 0; nt < 8; nt++)
            #pragma unroll
            for (int r = 0; r < 4; r++) sacc[nt][r] = 0.0f;

        #pragma unroll
        for (int ks = 0; ks < 16; ks++) {
            const uint32_t csw = ((uint32_t)(ks * 2 + hi) ^ swkey) << 4;
            uint32_t aQ[4];
            LDSM_X4(aQ[0], aQ[1], aQ[2], aQ[3], qbase + csw);
            #pragma unroll
            for (int p = 0; p < 4; p++) {
                uint32_t r0, r1, r2, r3;
                LDSM_X4(r0, r1, r2, r3,
                        kvb + (uint32_t)(p * 16 + row_in) * 512 + csw);
                uint32_t b0[2] = {r0, r2}, b1[2] = {r1, r3};
                mma16816(sacc[2 * p],     aQ, b0);
                mma16816(sacc[2 * p + 1], aQ, b1);
            }
        }

        // ---- mask (edge tiles only) ----
        const bool needmask = (k0 + 64 > q0) || (k0 + (CWIN - 64) < q0);
        const int rbase = q0 + wq * 16 + qr;
        if (needmask) {
            #pragma unroll
            for (int nt = 0; nt < 8; nt++) {
                int kg = k0 + nt * 8 + qc;
                #pragma unroll
                for (int e = 0; e < 4; e++) {
                    int qg = rbase + (e >> 1) * 8;
                    int kk = kg + (e & 1);
                    unsigned dd = (unsigned)(qg - kk);
                    if (dd >= (unsigned)CWIN) sacc[nt][e] = -1e30f;
                }
            }
        }

        // ---- warp-local online softmax ----
        float mx0 = -1e30f, mx1 = -1e30f;
        #pragma unroll
        for (int nt = 0; nt < 8; nt++) {
            mx0 = fmaxf(mx0, fmaxf(sacc[nt][0], sacc[nt][1]));
            mx1 = fmaxf(mx1, fmaxf(sacc[nt][2], sacc[nt][3]));
        }
        mx0 = fmaxf(mx0, __shfl_xor_sync(0xffffffffu, mx0, 1));
        mx0 = fmaxf(mx0, __shfl_xor_sync(0xffffffffu, mx0, 2));
        mx1 = fmaxf(mx1, __shfl_xor_sync(0xffffffffu, mx1, 1));
        mx1 = fmaxf(mx1, __shfl_xor_sync(0xffffffffu, mx1, 2));

        float newm0 = fmaxf(fmaxf(mrun0, mx0), -1e29f);
        float newm1 = fmaxf(fmaxf(mrun1, mx1), -1e29f);
        float alpha0 = fast_exp2(mrun0 - newm0);
        float alpha1 = fast_exp2(mrun1 - newm1);
        mrun0 = newm0; mrun1 = newm1;

        float rs0 = 0.0f, rs1 = 0.0f;
        #pragma unroll
        for (int nt = 0; nt < 8; nt++) {
            sacc[nt][0] = fast_exp2(sacc[nt][0] - newm0);
            sacc[nt][1] = fast_exp2(sacc[nt][1] - newm0);
            sacc[nt][2] = fast_exp2(sacc[nt][2] - newm1);
            sacc[nt][3] = fast_exp2(sacc[nt][3] - newm1);
            rs0 += sacc[nt][0] + sacc[nt][1];
            rs1 += sacc[nt][2] + sacc[nt][3];
        }
        rs0 += __shfl_xor_sync(0xffffffffu, rs0, 1);
        rs0 += __shfl_xor_sync(0xffffffffu, rs0, 2);
        rs1 += __shfl_xor_sync(0xffffffffu, rs1, 1);
        rs1 += __shfl_xor_sync(0xffffffffu, rs1, 2);
        lrun0 = lrun0 * alpha0 + rs0;
        lrun1 = lrun1 * alpha1 + rs1;

        // ---- P acc fragments -> A fragments, in registers ----
        uint32_t pa[4][4];
        #pragma unroll
        for (int c = 0; c < 4; c++) {
            pa[c][0] = packh2(sacc[2 * c][0],     sacc[2 * c][1]);
            pa[c][1] = packh2(sacc[2 * c][2],     sacc[2 * c][3]);
            pa[c][2] = packh2(sacc[2 * c + 1][0], sacc[2 * c + 1][1]);
            pa[c][3] = packh2(sacc[2 * c + 1][2], sacc[2 * c + 1][3]);
        }

        // ---- rescale O, O += P V (reads same buffer; no barrier needed) ----
        #pragma unroll
        for (int nt = 0; nt < 16; nt++) {
            oacc[nt][0] *= alpha0; oacc[nt][1] *= alpha0;
            oacc[nt][2] *= alpha1; oacc[nt][3] *= alpha1;
        }
        const uint32_t vbase = kvb + 32768;
        #pragma unroll
        for (int c = 0; c < 4; c++) {
            #pragma unroll
            for (int j = 0; j < 8; j++) {
                uint32_t c16v = (uint32_t)(wd * 16 + j * 2 + hi);
                uint32_t offV = (uint32_t)(c * 16 + row_in) * 512 +
                                ((c16v ^ swkey) << 4);
                uint32_t h0, h1, h2, h3;
                LDSM_X4_T(h0, h1, h2, h3, vbase + offV);
                uint32_t b0[2] = {h0, h1}, b1[2] = {h2, h3};
                mma16816(oacc[2 * j],     pa[c], b0);
                mma16816(oacc[2 * j + 1], pa[c], b1);
            }
        }
    }

    // ---- epilogue: fp16 AO ----
    float inv0 = 1.0f / lrun0, inv1 = 1.0f / lrun1;
    int row0 = q0 + wq * 16 + qr;
    #pragma unroll
    for (int nt = 0; nt < 16; nt++) {
        int col = h * CD + wd * 128 + nt * 8 + qc;
        *(__half2*)&AO[(size_t)row0 * CQD + col] =
            __floats2half2_rn(oacc[nt][0] * inv0, oacc[nt][1] * inv0);
        *(__half2*)&AO[(size_t)(row0 + 8) * CQD + col] =
            __floats2half2_rn(oacc[nt][2] * inv1, oacc[nt][3] * inv1);
    }
}

// ---------------------------------------------------------------------------
extern "C" void kernel_launch(void* const* d_in, const int* in_sizes, int n_in,
                              void* d_out, int out_size) {
    const float* x  = (const float*)d_in[0];
    const int*   ps = (const int*)  d_in[1];
    const float* Wq = (const float*)d_in[2];
    const float* Wk = (const float*)d_in[3];
    const float* Wv = (const float*)d_in[4];
    const float* Wo = (const float*)d_in[5];
    const float* qw = (const float*)d_in[6];
    const float* kw = (const float*)d_in[7];
    float* out = (float*)d_out;
    (void)in_sizes; (void)n_in; (void)out_size;

    float *Qp, *Kp;
    cudaGetSymbolAddress((void**)&Qp, g_Q);
    cudaGetSymbolAddress((void**)&Kp, g_K);
    __half *xs, *Wqkv, *Wot, *Qss, *Kss, *Vss, *AOs;
    cudaGetSymbolAddress((void**)&xs,   g_xs);
    cudaGetSymbolAddress((void**)&Wqkv, g_Wqkv);
    cudaGetSymbolAddress((void**)&Wot,  g_Wot);
    cudaGetSymbolAddress((void**)&Qss,  g_Qs);
    cudaGetSymbolAddress((void**)&Kss,  g_Ks);
    cudaGetSymbolAddress((void**)&Vss,  g_Vs);
    cudaGetSymbolAddress((void**)&AOs,  g_AOs);

    cudaFuncSetAttribute(gemm_qkv_kernel,
                         cudaFuncAttributeMaxDynamicSharedMemorySize, GEMM_SMEM);
    cudaFuncSetAttribute(gemm_o_kernel,
                         cudaFuncAttributeMaxDynamicSharedMemorySize, GEMM_SMEM);
    cudaFuncSetAttribute(flash_hmma_kernel,
                         cudaFuncAttributeMaxDynamicSharedMemorySize, FLASH_SMEM);

    // launch order: ncu (-s 5 -c 1) captures launch #6 = flash
    init_invf_kernel<<<1, 128>>>();                                      // 1
    convert_f16_kernel<<<512, 256>>>(x, xs, CT * CHID);                  // 2
    transpose_all_kernel<<<dim3(80, 80, 4), 256>>>(                      // 3
        Wq, Wk, Wv, Wo, Wqkv, Wot);

    gemm_qkv_kernel<<<dim3((CQD + 2 * CKD) / 128, CT / 128), 256,        // 4
                      GEMM_SMEM>>>(xs, Wqkv, Qp, Kp, Vss);

    norm_rope_kernel<<<dim3(CT, CH + CKH), 128>>>(Qp, Kp, ps, qw, kw,    // 5
                                                  Qss, Kss);

    flash_hmma_kernel<<<dim3(CT / 64, CKH), 512, FLASH_SMEM>>>(          // 6 <- ncu
        Qss, Kss, Vss, AOs);

    gemm_o_kernel<<<dim3(CHID / 128, CT / 128), 256, GEMM_SMEM>>>(       // 7
        AOs, Wot, out);
}